// round 5
// baseline (speedup 1.0000x reference)
#include <cuda_runtime.h>

#define NN 10000
#define EE 320000

__device__ float g_b1[(size_t)NN*256*64];   // conv1 out (also conv3 out)
__device__ float g_b0[(size_t)NN*64*64];    // conv2 out (also conv4 out)
__device__ float g_cf[NN*64];
__device__ float g_nA[NN*64];
__device__ float g_nB[NN*64];
__device__ float g_agg[NN*64];
__device__ float g_edge[(size_t)EE*64];

// ================= fused conv0(3->64) + conv1(64->64) per node-quadrant ======
__global__ void __launch_bounds__(256, 1) k_conv01(const float* __restrict__ crop,
    const float* __restrict__ w0, const float* __restrict__ b0_,
    const float* __restrict__ w1, const float* __restrict__ b1_,
    float* __restrict__ out) {
    extern __shared__ float sm[];
    float* w0s = sm;             // 768  [(c*4+p)*64 + oc]
    float* b0s = w0s + 768;      // 64
    float* w1s = b0s + 64;       // 16384 [(p*64+ic)*64 + oc]
    float* b1s = w1s + 16384;    // 64
    float* sIn = b1s + 64;       // 3*32*33 = 3168
    float* sA  = sIn + 3168;     // 256*65 = 16640 (conv0 out, [sp][ic] stride 65)

    const int t = threadIdx.x;
    const int n = blockIdx.x >> 2;
    const int q = blockIdx.x & 3;
    const int qy = q >> 1, qx = q & 1;

    for (int i = t; i < 768; i += 256) {
        int oc = i / 12, r = i - oc * 12;
        w0s[r * 64 + oc] = w0[i];
    }
    for (int i = t; i < 16384; i += 256) {
        int oc = i >> 8, r = i & 255, ic = r >> 2, p = r & 3;
        w1s[(p * 64 + ic) * 64 + oc] = w1[i];
    }
    if (t < 64) { b0s[t] = b0_[t]; b1s[t] = b1_[t]; }
    // input quadrant 32x32x3
    for (int e = t * 4; e < 3072; e += 1024) {
        int c = e >> 10, r = e & 1023, y = r >> 5, x = r & 31;
        float4 v = *(const float4*)&crop[(((size_t)n * 3 + c) * 64 + qy * 32 + y) * 64 + qx * 32 + x];
        float* d = &sIn[c * 1056 + y * 33 + x];
        d[0] = v.x; d[1] = v.y; d[2] = v.z; d[3] = v.w;
    }
    __syncthreads();

    // conv0: 256 sp x 64 oc, each thread: one sp, 4 oc, 16 iters
    #pragma unroll
    for (int it = 0; it < 16; it++) {
        int i = it * 256 + t;
        int sp = i >> 4, ocg = i & 15;
        int oy = sp >> 4, ox = sp & 15;
        float4 acc = *(const float4*)&b0s[ocg * 4];
        #pragma unroll
        for (int c = 0; c < 3; c++) {
            const float* ip = &sIn[c * 1056 + (2 * oy) * 33 + 2 * ox];
            #pragma unroll
            for (int p = 0; p < 4; p++) {
                float a = ip[(p >> 1) * 33 + (p & 1)];
                float4 w = *(const float4*)&w0s[(c * 4 + p) * 64 + ocg * 4];
                acc.x += a * w.x; acc.y += a * w.y; acc.z += a * w.z; acc.w += a * w.w;
            }
        }
        float* d = &sA[sp * 65 + ocg * 4];
        d[0] = fmaxf(acc.x, 0.f); d[1] = fmaxf(acc.y, 0.f);
        d[2] = fmaxf(acc.z, 0.f); d[3] = fmaxf(acc.w, 0.f);
    }
    __syncthreads();

    // conv1 GEMM: M=64 (8x8), N=64, K=256. 2 rows x 8 cols per thread.
    const int tr = t >> 3, tc = t & 7;
    const int r0 = 2 * tr, r1 = r0 + 1;
    const int oy0 = r0 >> 3, ox0 = r0 & 7;
    const int oy1 = r1 >> 3, ox1 = r1 & 7;
    float acc0[8], acc1[8];
    {
        float4 ba = *(const float4*)&b1s[tc * 8];
        float4 bb = *(const float4*)&b1s[tc * 8 + 4];
        acc0[0]=ba.x;acc0[1]=ba.y;acc0[2]=ba.z;acc0[3]=ba.w;
        acc0[4]=bb.x;acc0[5]=bb.y;acc0[6]=bb.z;acc0[7]=bb.w;
        #pragma unroll
        for (int j = 0; j < 8; j++) acc1[j] = acc0[j];
    }
    #pragma unroll
    for (int p = 0; p < 4; p++) {
        const int ky = p >> 1, kx = p & 1;
        const float* a0 = &sA[((2 * oy0 + ky) * 16 + 2 * ox0 + kx) * 65];
        const float* a1 = &sA[((2 * oy1 + ky) * 16 + 2 * ox1 + kx) * 65];
        const float* wp = &w1s[p * 4096 + tc * 8];
        #pragma unroll 8
        for (int k = 0; k < 64; k++) {
            float v0 = a0[k], v1 = a1[k];
            float4 wa = *(const float4*)&wp[k * 64];
            float4 wb = *(const float4*)&wp[k * 64 + 4];
            acc0[0]+=v0*wa.x; acc0[1]+=v0*wa.y; acc0[2]+=v0*wa.z; acc0[3]+=v0*wa.w;
            acc0[4]+=v0*wb.x; acc0[5]+=v0*wb.y; acc0[6]+=v0*wb.z; acc0[7]+=v0*wb.w;
            acc1[0]+=v1*wa.x; acc1[1]+=v1*wa.y; acc1[2]+=v1*wa.z; acc1[3]+=v1*wa.w;
            acc1[4]+=v1*wb.x; acc1[5]+=v1*wb.y; acc1[6]+=v1*wb.z; acc1[7]+=v1*wb.w;
        }
    }
    const int gsp0 = (qy * 8 + oy0) * 16 + qx * 8 + ox0;
    const int gsp1 = (qy * 8 + oy1) * 16 + qx * 8 + ox1;
    float* o0 = &out[((size_t)n * 256 + gsp0) * 64 + tc * 8];
    float* o1 = &out[((size_t)n * 256 + gsp1) * 64 + tc * 8];
    float4 v;
    v.x=fmaxf(acc0[0],0.f); v.y=fmaxf(acc0[1],0.f); v.z=fmaxf(acc0[2],0.f); v.w=fmaxf(acc0[3],0.f);
    *(float4*)o0 = v;
    v.x=fmaxf(acc0[4],0.f); v.y=fmaxf(acc0[5],0.f); v.z=fmaxf(acc0[6],0.f); v.w=fmaxf(acc0[7],0.f);
    *(float4*)(o0+4) = v;
    v.x=fmaxf(acc1[0],0.f); v.y=fmaxf(acc1[1],0.f); v.z=fmaxf(acc1[2],0.f); v.w=fmaxf(acc1[3],0.f);
    *(float4*)o1 = v;
    v.x=fmaxf(acc1[4],0.f); v.y=fmaxf(acc1[5],0.f); v.z=fmaxf(acc1[6],0.f); v.w=fmaxf(acc1[7],0.f);
    *(float4*)(o1+4) = v;
}

// ================== generic conv 64->64 k2s2, 128-row tiles, 4x8 per thread ==
__global__ void __launch_bounds__(256, 2) k_conv(const float* __restrict__ in,
    float* __restrict__ out, const float* __restrict__ w, const float* __restrict__ b,
    int so_bits, int M) {
    extern __shared__ float sm[];
    float* Ws = sm;            // 16384 [(p*64+ic)*64+oc]
    float* Bs = Ws + 16384;    // 64
    float* As = Bs + 64;       // 128*65
    const int t = threadIdx.x;
    const int Rbase = blockIdx.x * 128;
    for (int i = t; i < 16384; i += 256) {
        int oc = i >> 8, r = i & 255, ic = r >> 2, p = r & 3;
        Ws[(p * 64 + ic) * 64 + oc] = w[i];
    }
    if (t < 64) Bs[t] = b[t];
    const int S_out = 1 << so_bits, S_in = S_out * 2, so2 = 2 * so_bits;
    const int tr = t >> 3, tc = t & 7;
    const float* ar[4];
    #pragma unroll
    for (int i = 0; i < 4; i++) ar[i] = &As[(tr * 4 + i) * 65];
    float acc[4][8];
    for (int p = 0; p < 4; p++) {
        __syncthreads();
        const int ky = p >> 1, kx = p & 1;
        for (int e = t * 4; e < 8192; e += 1024) {
            int row = e >> 6, c4 = e & 63;
            int R = Rbase + row;
            float4 vv = make_float4(0.f, 0.f, 0.f, 0.f);
            if (R < M) {
                int n = R >> so2, sp = R & (S_out * S_out - 1);
                int oy = sp >> so_bits, ox = sp & (S_out - 1);
                vv = *(const float4*)&in[(((size_t)n * S_in + 2 * oy + ky) * S_in + 2 * ox + kx) * 64 + c4];
            }
            float* d = &As[row * 65 + c4];
            d[0] = vv.x; d[1] = vv.y; d[2] = vv.z; d[3] = vv.w;
        }
        __syncthreads();
        if (p == 0) {
            float4 ba = *(const float4*)&Bs[tc * 8];
            float4 bb = *(const float4*)&Bs[tc * 8 + 4];
            #pragma unroll
            for (int i = 0; i < 4; i++) {
                acc[i][0]=ba.x;acc[i][1]=ba.y;acc[i][2]=ba.z;acc[i][3]=ba.w;
                acc[i][4]=bb.x;acc[i][5]=bb.y;acc[i][6]=bb.z;acc[i][7]=bb.w;
            }
        }
        const float* wp = &Ws[p * 4096 + tc * 8];
        #pragma unroll 8
        for (int k = 0; k < 64; k++) {
            float4 wa = *(const float4*)&wp[k * 64];
            float4 wb = *(const float4*)&wp[k * 64 + 4];
            #pragma unroll
            for (int i = 0; i < 4; i++) {
                float a = ar[i][k];
                acc[i][0]+=a*wa.x; acc[i][1]+=a*wa.y; acc[i][2]+=a*wa.z; acc[i][3]+=a*wa.w;
                acc[i][4]+=a*wb.x; acc[i][5]+=a*wb.y; acc[i][6]+=a*wb.z; acc[i][7]+=a*wb.w;
            }
        }
    }
    #pragma unroll
    for (int i = 0; i < 4; i++) {
        int R = Rbase + tr * 4 + i;
        if (R < M) {
            float4 v;
            v.x=fmaxf(acc[i][0],0.f); v.y=fmaxf(acc[i][1],0.f);
            v.z=fmaxf(acc[i][2],0.f); v.w=fmaxf(acc[i][3],0.f);
            *(float4*)&out[(size_t)R * 64 + tc * 8] = v;
            v.x=fmaxf(acc[i][4],0.f); v.y=fmaxf(acc[i][5],0.f);
            v.z=fmaxf(acc[i][6],0.f); v.w=fmaxf(acc[i][7],0.f);
            *(float4*)&out[(size_t)R * 64 + tc * 8 + 4] = v;
        }
    }
}

// --------------------------------------------- node_update: [x|cf]@W + LN
__global__ void __launch_bounds__(256) k_nodeup(const float* __restrict__ x,
    const float* __restrict__ cf, const float* __restrict__ w, const float* __restrict__ b,
    const float* __restrict__ g, const float* __restrict__ be, float* __restrict__ out) {
    extern __shared__ float sm[];
    float* Ws = sm;
    float* Bs = Ws + 6144; float* Gs = Bs + 64; float* BEs = Gs + 64;
    float* mu = BEs + 64; float* rs = mu + 64;
    float* As = rs + 64;      // 64*100
    float* Hs = As + 6400;    // 64*68
    int t = threadIdx.x;
    int Rbase = blockIdx.x * 64;
    for (int i = t; i < 6144; i += 256) Ws[i] = w[i];
    if (t < 64) { Bs[t]=b[t]; Gs[t]=g[t]; BEs[t]=be[t]; }
    for (int e = t; e < 2048; e += 256) {
        int row = e >> 5, c = e & 31, nd = Rbase + row;
        As[row * 100 + c] = (nd < NN) ? x[nd * 32 + c] : 0.f;
    }
    for (int e = t; e < 4096; e += 256) {
        int row = e >> 6, c = e & 63, nd = Rbase + row;
        As[row * 100 + 32 + c] = (nd < NN) ? cf[nd * 64 + c] : 0.f;
    }
    __syncthreads();
    int tr = t >> 4, tc = t & 15;
    float acc[4][4];
    float4 b4 = *(const float4*)&Bs[tc * 4];
    #pragma unroll
    for (int i = 0; i < 4; i++) { acc[i][0]=b4.x; acc[i][1]=b4.y; acc[i][2]=b4.z; acc[i][3]=b4.w; }
    for (int k = 0; k < 96; k++) {
        float4 w4 = *(const float4*)&Ws[k * 64 + tc * 4];
        #pragma unroll
        for (int i = 0; i < 4; i++) {
            float a = As[(tr * 4 + i) * 100 + k];
            acc[i][0] += a*w4.x; acc[i][1] += a*w4.y; acc[i][2] += a*w4.z; acc[i][3] += a*w4.w;
        }
    }
    #pragma unroll
    for (int i = 0; i < 4; i++) {
        float4 r; r.x=fmaxf(acc[i][0],0.f); r.y=fmaxf(acc[i][1],0.f);
        r.z=fmaxf(acc[i][2],0.f); r.w=fmaxf(acc[i][3],0.f);
        *(float4*)&Hs[(tr * 4 + i) * 68 + tc * 4] = r;
    }
    __syncthreads();
    if (t < 64) {
        float s = 0.f, sq = 0.f;
        for (int c = 0; c < 64; c++) { float v = Hs[t * 68 + c]; s += v; sq += v * v; }
        float m = s * (1.f / 64.f);
        mu[t] = m; rs[t] = rsqrtf(sq * (1.f / 64.f) - m * m + 1e-5f);
    }
    __syncthreads();
    for (int i = t; i < 4096; i += 256) {
        int r = i >> 6, c = i & 63, nd = Rbase + r;
        if (nd < NN) out[nd * 64 + c] = (Hs[r * 68 + c] - mu[r]) * rs[r] * Gs[c] + BEs[c];
    }
}

// --------------------------------------------- edge_update: ea@W + LN
__global__ void __launch_bounds__(256) k_edgeup(const float* __restrict__ ea,
    const float* __restrict__ w, const float* __restrict__ b,
    const float* __restrict__ g, const float* __restrict__ be, float* __restrict__ out) {
    __shared__ float Ws[384], Bs[64], Gs[64], BEs[64], Aa[64][8], Hs[64][68], mu[64], rs[64];
    int t = threadIdx.x;
    int ebase = blockIdx.x * 64;
    for (int i = t; i < 384; i += 256) Ws[i] = w[i];
    if (t < 64) { Bs[t]=b[t]; Gs[t]=g[t]; BEs[t]=be[t]; }
    for (int e = t; e < 384; e += 256) {
        int row = e / 6, k = e - row * 6;
        Aa[row][k] = ea[(size_t)(ebase + row) * 6 + k];
    }
    __syncthreads();
    int r = t >> 2, cg = (t & 3) * 16;
    float a0=Aa[r][0],a1=Aa[r][1],a2=Aa[r][2],a3=Aa[r][3],a4=Aa[r][4],a5=Aa[r][5];
    #pragma unroll
    for (int j = 0; j < 16; j++) {
        int c = cg + j;
        float h = Bs[c] + a0*Ws[c] + a1*Ws[64+c] + a2*Ws[128+c] + a3*Ws[192+c] + a4*Ws[256+c] + a5*Ws[320+c];
        Hs[r][c] = fmaxf(h, 0.f);
    }
    __syncthreads();
    if (t < 64) {
        float s = 0.f, sq = 0.f;
        for (int c = 0; c < 64; c++) { float v = Hs[t][c]; s += v; sq += v * v; }
        float m = s * (1.f / 64.f);
        mu[t] = m; rs[t] = rsqrtf(sq * (1.f / 64.f) - m * m + 1e-5f);
    }
    __syncthreads();
    for (int i = t; i < 4096; i += 256) {
        int rr = i >> 6, c = i & 63;
        out[(size_t)ebase * 64 + i] = (Hs[rr][c] - mu[rr]) * rs[rr] * Gs[c] + BEs[c];
    }
}

// ======= msg MLP + fused scatter-add: 128 edges/block, 4x8 per thread ========
__global__ void __launch_bounds__(256, 2) k_msg(const float* __restrict__ node,
    const float* __restrict__ edge, const int* __restrict__ ei,
    const float* __restrict__ w1, const float* __restrict__ b1,
    const float* __restrict__ w2, const float* __restrict__ b2, float* __restrict__ agg) {
    extern __shared__ float sm[];
    float* W1s = sm;           // 12288
    float* W2s = W1s + 12288;  // 4096
    float* B1s = W2s + 4096; float* B2s = B1s + 64;
    float* As = B2s + 64;      // 128*65 (reused for H)
    int* srcs = (int*)(As + 8320);
    int* dsts = srcs + 128;
    const int t = threadIdx.x;
    const int ebase = blockIdx.x * 128;
    for (int i = t; i < 12288; i += 256) W1s[i] = w1[i];
    for (int i = t; i < 4096; i += 256) W2s[i] = w2[i];
    if (t < 64) { B1s[t]=b1[t]; B2s[t]=b2[t]; }
    if (t < 128) { srcs[t] = ei[ebase + t]; dsts[t] = ei[EE + ebase + t]; }
    const int tr = t >> 3, tc = t & 7;
    const float* ar[4];
    #pragma unroll
    for (int i = 0; i < 4; i++) ar[i] = &As[(tr * 4 + i) * 65];
    float acc[4][8];
    for (int ch = 0; ch < 3; ch++) {
        __syncthreads();
        for (int e = t * 4; e < 8192; e += 1024) {
            int row = e >> 6, c4 = e & 63;
            const float* base = (ch == 0) ? &node[(size_t)dsts[row] * 64]
                              : (ch == 1) ? &node[(size_t)srcs[row] * 64]
                                          : &edge[(size_t)(ebase + row) * 64];
            float4 vv = *(const float4*)&base[c4];
            float* d = &As[row * 65 + c4];
            d[0]=vv.x; d[1]=vv.y; d[2]=vv.z; d[3]=vv.w;
        }
        __syncthreads();
        if (ch == 0) {
            float4 ba = *(const float4*)&B1s[tc * 8];
            float4 bb = *(const float4*)&B1s[tc * 8 + 4];
            #pragma unroll
            for (int i = 0; i < 4; i++) {
                acc[i][0]=ba.x;acc[i][1]=ba.y;acc[i][2]=ba.z;acc[i][3]=ba.w;
                acc[i][4]=bb.x;acc[i][5]=bb.y;acc[i][6]=bb.z;acc[i][7]=bb.w;
            }
        }
        const float* wp = &W1s[ch * 4096 + tc * 8];
        #pragma unroll 8
        for (int k = 0; k < 64; k++) {
            float4 wa = *(const float4*)&wp[k * 64];
            float4 wb = *(const float4*)&wp[k * 64 + 4];
            #pragma unroll
            for (int i = 0; i < 4; i++) {
                float a = ar[i][k];
                acc[i][0]+=a*wa.x; acc[i][1]+=a*wa.y; acc[i][2]+=a*wa.z; acc[i][3]+=a*wa.w;
                acc[i][4]+=a*wb.x; acc[i][5]+=a*wb.y; acc[i][6]+=a*wb.z; acc[i][7]+=a*wb.w;
            }
        }
    }
    __syncthreads();
    #pragma unroll
    for (int i = 0; i < 4; i++)
        #pragma unroll
        for (int j = 0; j < 8; j++)
            As[(tr * 4 + i) * 65 + tc * 8 + j] = fmaxf(acc[i][j], 0.f);
    __syncthreads();
    float a2[4][8];
    {
        float4 ba = *(const float4*)&B2s[tc * 8];
        float4 bb = *(const float4*)&B2s[tc * 8 + 4];
        #pragma unroll
        for (int i = 0; i < 4; i++) {
            a2[i][0]=ba.x;a2[i][1]=ba.y;a2[i][2]=ba.z;a2[i][3]=ba.w;
            a2[i][4]=bb.x;a2[i][5]=bb.y;a2[i][6]=bb.z;a2[i][7]=bb.w;
        }
    }
    const float* wp2 = &W2s[tc * 8];
    #pragma unroll 8
    for (int k = 0; k < 64; k++) {
        float4 wa = *(const float4*)&wp2[k * 64];
        float4 wb = *(const float4*)&wp2[k * 64 + 4];
        #pragma unroll
        for (int i = 0; i < 4; i++) {
            float a = ar[i][k];
            a2[i][0]+=a*wa.x; a2[i][1]+=a*wa.y; a2[i][2]+=a*wa.z; a2[i][3]+=a*wa.w;
            a2[i][4]+=a*wb.x; a2[i][5]+=a*wb.y; a2[i][6]+=a*wb.z; a2[i][7]+=a*wb.w;
        }
    }
    #pragma unroll
    for (int i = 0; i < 4; i++) {
        int d = dsts[tr * 4 + i];
        float* ap = &agg[(size_t)d * 64 + tc * 8];
        #pragma unroll
        for (int j = 0; j < 8; j++) atomicAdd(ap + j, a2[i][j]);
    }
}

// ========= node MLP: [node|agg] 2-layer, 128 nodes/block, 4x8 per thread =====
__global__ void __launch_bounds__(256, 2) k_nodemlp(const float* __restrict__ node,
    const float* __restrict__ agg, const float* __restrict__ w1, const float* __restrict__ b1,
    const float* __restrict__ w2, const float* __restrict__ b2, float* __restrict__ out) {
    extern __shared__ float sm[];
    float* W1s = sm;           // 8192
    float* W2s = W1s + 8192;   // 4096
    float* B1s = W2s + 4096; float* B2s = B1s + 64;
    float* As = B2s + 64;      // 128*65 (reused for H)
    const int t = threadIdx.x;
    const int Rbase = blockIdx.x * 128;
    for (int i = t; i < 8192; i += 256) W1s[i] = w1[i];
    for (int i = t; i < 4096; i += 256) W2s[i] = w2[i];
    if (t < 64) { B1s[t]=b1[t]; B2s[t]=b2[t]; }
    const int tr = t >> 3, tc = t & 7;
    const float* ar[4];
    #pragma unroll
    for (int i = 0; i < 4; i++) ar[i] = &As[(tr * 4 + i) * 65];
    float acc[4][8];
    for (int ch = 0; ch < 2; ch++) {
        __syncthreads();
        for (int e = t * 4; e < 8192; e += 1024) {
            int row = e >> 6, c4 = e & 63, nd = Rbase + row;
            float4 vv = make_float4(0.f,0.f,0.f,0.f);
            if (nd < NN) {
                const float* base = (ch == 0) ? &node[(size_t)nd * 64] : &agg[(size_t)nd * 64];
                vv = *(const float4*)&base[c4];
            }
            float* d = &As[row * 65 + c4];
            d[0]=vv.x; d[1]=vv.y; d[2]=vv.z; d[3]=vv.w;
        }
        __syncthreads();
        if (ch == 0) {
            float4 ba = *(const float4*)&B1s[tc * 8];
            float4 bb = *(const float4*)&B1s[tc * 8 + 4];
            #pragma unroll
            for (int i = 0; i < 4; i++) {
                acc[i][0]=ba.x;acc[i][1]=ba.y;acc[i][2]=ba.z;acc[i][3]=ba.w;
                acc[i][4]=bb.x;acc[i][5]=bb.y;acc[i][6]=bb.z;acc[i][7]=bb.w;
            }
        }
        const float* wp = &W1s[ch * 4096 + tc * 8];
        #pragma unroll 8
        for (int k = 0; k < 64; k++) {
            float4 wa = *(const float4*)&wp[k * 64];
            float4 wb = *(const float4*)&wp[k * 64 + 4];
            #pragma unroll
            for (int i = 0; i < 4; i++) {
                float a = ar[i][k];
                acc[i][0]+=a*wa.x; acc[i][1]+=a*wa.y; acc[i][2]+=a*wa.z; acc[i][3]+=a*wa.w;
                acc[i][4]+=a*wb.x; acc[i][5]+=a*wb.y; acc[i][6]+=a*wb.z; acc[i][7]+=a*wb.w;
            }
        }
    }
    __syncthreads();
    #pragma unroll
    for (int i = 0; i < 4; i++)
        #pragma unroll
        for (int j = 0; j < 8; j++)
            As[(tr * 4 + i) * 65 + tc * 8 + j] = fmaxf(acc[i][j], 0.f);
    __syncthreads();
    float a2[4][8];
    {
        float4 ba = *(const float4*)&B2s[tc * 8];
        float4 bb = *(const float4*)&B2s[tc * 8 + 4];
        #pragma unroll
        for (int i = 0; i < 4; i++) {
            a2[i][0]=ba.x;a2[i][1]=ba.y;a2[i][2]=ba.z;a2[i][3]=ba.w;
            a2[i][4]=bb.x;a2[i][5]=bb.y;a2[i][6]=bb.z;a2[i][7]=bb.w;
        }
    }
    const float* wp2 = &W2s[tc * 8];
    #pragma unroll 8
    for (int k = 0; k < 64; k++) {
        float4 wa = *(const float4*)&wp2[k * 64];
        float4 wb = *(const float4*)&wp2[k * 64 + 4];
        #pragma unroll
        for (int i = 0; i < 4; i++) {
            float a = ar[i][k];
            a2[i][0]+=a*wa.x; a2[i][1]+=a*wa.y; a2[i][2]+=a*wa.z; a2[i][3]+=a*wa.w;
            a2[i][4]+=a*wb.x; a2[i][5]+=a*wb.y; a2[i][6]+=a*wb.z; a2[i][7]+=a*wb.w;
        }
    }
    #pragma unroll
    for (int i = 0; i < 4; i++) {
        int nd = Rbase + tr * 4 + i;
        if (nd < NN) {
            float4 v;
            v.x=a2[i][0]; v.y=a2[i][1]; v.z=a2[i][2]; v.w=a2[i][3];
            *(float4*)&out[(size_t)nd * 64 + tc * 8] = v;
            v.x=a2[i][4]; v.y=a2[i][5]; v.z=a2[i][6]; v.w=a2[i][7];
            *(float4*)&out[(size_t)nd * 64 + tc * 8 + 4] = v;
        }
    }
}

// --------------------------------------------- final edge MLP: 134->128->64->1
__global__ void __launch_bounds__(256) k_final(const float* __restrict__ node,
    const float* __restrict__ ea, const int* __restrict__ ei,
    const float* __restrict__ w1, const float* __restrict__ b1,
    const float* __restrict__ w2, const float* __restrict__ b2,
    const float* __restrict__ w3, const float* __restrict__ b3, float* __restrict__ out) {
    extern __shared__ float sm[];
    float* W1s = sm;              // 17152
    float* B1s = W1s + 17152;     // 128
    float* W2s = B1s + 128;       // 8192
    float* B2s = W2s + 8192;      // 64
    float* w3s = B2s + 64;        // 64
    float* b3s = w3s + 64;        // 4
    float* As  = b3s + 4;         // 64*68
    float* Hs  = As + 4352;       // 64*132
    float* H2s = Hs + 8448;       // 64*68
    int* srcs = (int*)(H2s + 4352);
    int* dsts = srcs + 64;
    int t = threadIdx.x;
    int ebase = blockIdx.x * 64;
    for (int i = t; i < 17152; i += 256) W1s[i] = w1[i];
    for (int i = t; i < 8192; i += 256) W2s[i] = w2[i];
    if (t < 128) B1s[t] = b1[t];
    if (t < 64) { B2s[t]=b2[t]; w3s[t]=w3[t]; srcs[t]=ei[ebase+t]; dsts[t]=ei[EE+ebase+t]; }
    if (t == 0) b3s[0] = b3[0];
    int tr = t >> 4, tc = t & 15;
    float acc[4][8];
    for (int ch = 0; ch < 2; ch++) {
        __syncthreads();
        for (int e = t * 4; e < 4096; e += 1024) {
            int row = e >> 6, c4 = e & 63;
            const float* base = (ch == 0) ? &node[(size_t)srcs[row] * 64]
                                          : &node[(size_t)dsts[row] * 64];
            *(float4*)&As[row * 68 + c4] = *(const float4*)&base[c4];
        }
        __syncthreads();
        if (ch == 0) {
            #pragma unroll
            for (int i = 0; i < 4; i++)
                #pragma unroll
                for (int j = 0; j < 8; j++) acc[i][j] = B1s[tc * 8 + j];
        }
        for (int k = 0; k < 64; k++) {
            float4 wa = *(const float4*)&W1s[(ch * 64 + k) * 128 + tc * 8];
            float4 wb = *(const float4*)&W1s[(ch * 64 + k) * 128 + tc * 8 + 4];
            #pragma unroll
            for (int i = 0; i < 4; i++) {
                float a = As[(tr * 4 + i) * 68 + k];
                acc[i][0]+=a*wa.x; acc[i][1]+=a*wa.y; acc[i][2]+=a*wa.z; acc[i][3]+=a*wa.w;
                acc[i][4]+=a*wb.x; acc[i][5]+=a*wb.y; acc[i][6]+=a*wb.z; acc[i][7]+=a*wb.w;
            }
        }
    }
    __syncthreads();
    for (int e = t; e < 384; e += 256) {
        int row = e / 6, k = e - row * 6;
        As[row * 8 + k] = ea[(size_t)(ebase + row) * 6 + k];
    }
    __syncthreads();
    for (int k = 0; k < 6; k++) {
        float4 wa = *(const float4*)&W1s[(128 + k) * 128 + tc * 8];
        float4 wb = *(const float4*)&W1s[(128 + k) * 128 + tc * 8 + 4];
        #pragma unroll
        for (int i = 0; i < 4; i++) {
            float a = As[(tr * 4 + i) * 8 + k];
            acc[i][0]+=a*wa.x; acc[i][1]+=a*wa.y; acc[i][2]+=a*wa.z; acc[i][3]+=a*wa.w;
            acc[i][4]+=a*wb.x; acc[i][5]+=a*wb.y; acc[i][6]+=a*wb.z; acc[i][7]+=a*wb.w;
        }
    }
    #pragma unroll
    for (int i = 0; i < 4; i++)
        #pragma unroll
        for (int j = 0; j < 8; j++)
            Hs[(tr * 4 + i) * 132 + tc * 8 + j] = fmaxf(acc[i][j], 0.f);
    __syncthreads();
    float a2[4][4];
    #pragma unroll
    for (int i = 0; i < 4; i++)
        #pragma unroll
        for (int j = 0; j < 4; j++) a2[i][j] = B2s[tc * 4 + j];
    for (int k = 0; k < 128; k++) {
        float4 w4 = *(const float4*)&W2s[k * 64 + tc * 4];
        #pragma unroll
        for (int i = 0; i < 4; i++) {
            float a = Hs[(tr * 4 + i) * 132 + k];
            a2[i][0] += a*w4.x; a2[i][1] += a*w4.y; a2[i][2] += a*w4.z; a2[i][3] += a*w4.w;
        }
    }
    #pragma unroll
    for (int i = 0; i < 4; i++)
        #pragma unroll
        for (int j = 0; j < 4; j++)
            H2s[(tr * 4 + i) * 68 + tc * 4 + j] = fmaxf(a2[i][j], 0.f);
    __syncthreads();
    if (t < 64) {
        float s = b3s[0];
        for (int c = 0; c < 64; c++) s += H2s[t * 68 + c] * w3s[c];
        out[ebase + t] = s;
    }
}

// ============================================================================
extern "C" void kernel_launch(void* const* d_in, const int* in_sizes, int n_in,
                              void* d_out, int out_size) {
    const float *x=0,*ea=0,*crop=0,*cw0=0,*cb0=0,*cw=0,*cb=0,*nu_w=0,*nu_b=0,*nu_g=0,*nu_be=0,
        *eu_w=0,*eu_b=0,*eu_g=0,*eu_be=0,*ie_w1=0,*ie_b1=0,*ie_w2=0,*ie_b2=0,
        *in_w1=0,*in_b1=0,*in_w2=0,*in_b2=0,*em_w1=0,*em_b1=0,*em_w2=0,*em_b2=0,*em_w3=0,*em_b3=0;
    const int* ei = 0;
    int c64 = 0, c256 = 0, c16k = 0;
    for (int i = 0; i < n_in; i++) {
        const float* p = (const float*)d_in[i];
        switch (in_sizes[i]) {
            case 320000: x = p; break;
            case 640000: ei = (const int*)p; break;
            case 1920000: ea = p; break;
            case 122880000: crop = p; break;
            case 768: cw0 = p; break;
            case 81920: cw = p; break;
            case 320: cb = p; break;
            case 6144: nu_w = p; break;
            case 384: eu_w = p; break;
            case 49152: ie_w1 = p; break;
            case 32768: in_w1 = p; break;
            case 17152: em_w1 = p; break;
            case 128: em_b1 = p; break;
            case 8192: em_w2 = p; break;
            case 1: em_b3 = p; break;
            case 16384: if (c16k++ == 0) ie_w2 = p; else in_w2 = p; break;
            case 256:
                if (c256 == 0) ie_b1 = p; else if (c256 == 1) ie_b2 = p;
                else if (c256 == 2) in_b1 = p; else in_b2 = p;
                c256++; break;
            case 64: {
                const float** slots[9] = {&cb0,&nu_b,&nu_g,&nu_be,&eu_b,&eu_g,&eu_be,&em_b2,&em_w3};
                if (c64 < 9) *slots[c64] = p;
                c64++; break;
            }
            default: break;
        }
    }
    float *b0, *b1, *cf, *nA, *nB, *agg, *edg;
    cudaGetSymbolAddress((void**)&b0, g_b0);
    cudaGetSymbolAddress((void**)&b1, g_b1);
    cudaGetSymbolAddress((void**)&cf, g_cf);
    cudaGetSymbolAddress((void**)&nA, g_nA);
    cudaGetSymbolAddress((void**)&nB, g_nB);
    cudaGetSymbolAddress((void**)&agg, g_agg);
    cudaGetSymbolAddress((void**)&edg, g_edge);

    const int SM01   = (768 + 64 + 16384 + 64 + 3168 + 16640) * 4;
    const int SM_CONV = (16384 + 64 + 128 * 65) * 4;
    const int SM_NU   = (6144 + 64 * 5 + 6400 + 4352 + 64) * 4;
    const int SM_MSG  = (12288 + 4096 + 128 + 8320) * 4 + 256 * 4;
    const int SM_NM   = (8192 + 4096 + 128 + 8320) * 4;
    const int SM_FIN  = (17152 + 128 + 8192 + 64 + 64 + 4 + 4352 + 8448 + 4352) * 4 + 512;
    cudaFuncSetAttribute(k_conv01,  cudaFuncAttributeMaxDynamicSharedMemorySize, SM01);
    cudaFuncSetAttribute(k_conv,    cudaFuncAttributeMaxDynamicSharedMemorySize, SM_CONV);
    cudaFuncSetAttribute(k_nodeup,  cudaFuncAttributeMaxDynamicSharedMemorySize, SM_NU);
    cudaFuncSetAttribute(k_msg,     cudaFuncAttributeMaxDynamicSharedMemorySize, SM_MSG);
    cudaFuncSetAttribute(k_nodemlp, cudaFuncAttributeMaxDynamicSharedMemorySize, SM_NM);
    cudaFuncSetAttribute(k_final,   cudaFuncAttributeMaxDynamicSharedMemorySize, SM_FIN);

    // CNN stack
    k_conv01<<<40000, 256, SM01>>>(crop, cw0, cb0, cw, cb, b1);
    k_conv<<<5000, 256, SM_CONV>>>(b1, b0, cw + 16384, cb + 64,  3, NN * 64);
    k_conv<<<1250, 256, SM_CONV>>>(b0, b1, cw + 32768, cb + 128, 2, NN * 16);
    k_conv<<<313,  256, SM_CONV>>>(b1, b0, cw + 49152, cb + 192, 1, NN * 4);
    k_conv<<<79,   256, SM_CONV>>>(b0, cf, cw + 65536, cb + 256, 0, NN);
    // encoders
    k_nodeup<<<157, 256, SM_NU>>>(x, cf, nu_w, nu_b, nu_g, nu_be, nA);
    k_edgeup<<<5000, 256>>>(ea, eu_w, eu_b, eu_g, eu_be, edg);
    // 4 interaction layers
    float* cur = nA; float* nxt = nB;
    for (int l = 0; l < 4; l++) {
        cudaMemsetAsync(agg, 0, (size_t)NN * 64 * sizeof(float), 0);
        k_msg<<<2500, 256, SM_MSG>>>(cur, edg, ei, ie_w1 + l * 12288, ie_b1 + l * 64,
                                     ie_w2 + l * 4096, ie_b2 + l * 64, agg);
        k_nodemlp<<<79, 256, SM_NM>>>(cur, agg, in_w1 + l * 8192, in_b1 + l * 64,
                                      in_w2 + l * 4096, in_b2 + l * 64, nxt);
        float* tmp = cur; cur = nxt; nxt = tmp;
    }
    // final edge MLP
    k_final<<<5000, 256, SM_FIN>>>(cur, ea, ei, em_w1, em_b1, em_w2, em_b2,
                                   em_w3, em_b3, (float*)d_out);
}

// round 6
// speedup vs baseline: 1.9232x; 1.9232x over previous
#include <cuda_runtime.h>
#include <cstdint>

#define NN 10000
#define EE 320000

__device__ float g_b1[(size_t)NN*256*64];
__device__ float g_b0[(size_t)NN*64*64];
__device__ float g_cf[NN*64];
__device__ float g_nA[NN*64];
__device__ float g_nB[NN*64];
__device__ float g_agg[NN*64];
__device__ float g_edge[(size_t)EE*64];

__device__ __forceinline__ unsigned f2tf(float x){unsigned r;asm("cvt.rna.tf32.f32 %0,%1;":"=r"(r):"f"(x));return r;}
__device__ __forceinline__ void mma8(float* c,unsigned a0,unsigned a1,unsigned a2,unsigned a3,unsigned b0,unsigned b1){
  asm("mma.sync.aligned.m16n8k8.row.col.f32.tf32.tf32.f32 {%0,%1,%2,%3},{%4,%5,%6,%7},{%8,%9},{%0,%1,%2,%3};"
      :"+f"(c[0]),"+f"(c[1]),"+f"(c[2]),"+f"(c[3]):"r"(a0),"r"(a1),"r"(a2),"r"(a3),"r"(b0),"r"(b1));}

// A tiles in smem stride 68 (hi/lo), W fragments staged in smem. 8 n-tiles, KT k-tiles.
__device__ __forceinline__ void mma_sweep(const float* Ah,const float* Al,const unsigned* Wh,const unsigned* Wl,
    int KT,float C[][4],int ab){
  const int lane=threadIdx.x&31;
  for(int kt=0;kt<KT;kt++){
    const float* ah=Ah+ab+kt*8;
    unsigned a0=__float_as_uint(ah[0]),a1=__float_as_uint(ah[8*68]),a2=__float_as_uint(ah[4]),a3=__float_as_uint(ah[8*68+4]);
    const float* al=Al+ab+kt*8;
    unsigned l0=__float_as_uint(al[0]),l1=__float_as_uint(al[8*68]),l2=__float_as_uint(al[4]),l3=__float_as_uint(al[8*68+4]);
    #pragma unroll
    for(int nt=0;nt<8;nt++){
      int s=(kt*8+nt)*32+lane;
      uint2 bh=*(const uint2*)(Wh+2*(size_t)s);
      unsigned ul=Wl[s];
      mma8(C[nt],a0,a1,a2,a3,bh.x,bh.y);
      mma8(C[nt],a0,a1,a2,a3,ul<<16,ul&0xFFFF0000u);
      mma8(C[nt],l0,l1,l2,l3,bh.x,bh.y);
    }
  }
}

#define STAGE_W(Wh,Wl,KT,GET) do{ for(int s_=threadIdx.x;s_<(KT)*256;s_+=256){ \
  int lane_=s_&31,nt_=(s_>>5)&7,kt_=s_>>8; int nn=nt_*8+(lane_>>2),kk=kt_*8+(lane_&3); \
  float w0v=GET(kk,nn),w1v=GET((kk+4),nn); unsigned h0=f2tf(w0v),h1=f2tf(w1v); \
  float q0=w0v-__uint_as_float(h0),q1=w1v-__uint_as_float(h1); \
  (Wh)[2*s_]=h0;(Wh)[2*s_+1]=h1; (Wl)[s_]=(__float_as_uint(q0)>>16)|(__float_as_uint(q1)&0xFFFF0000u);} }while(0)

#define SPLIT_ST(ah,al,v) {float h_=__uint_as_float(f2tf(v));(ah)=h_;(al)=(v)-h_;}

// =========== unified CNN layer (mma): layer0 fuses conv0 inline =============
__global__ void __launch_bounds__(256,2) k_cnn(const float* __restrict__ crop,
    const float* __restrict__ in,float* __restrict__ out,
    const float* __restrict__ w0,const float* __restrict__ b0c,
    const float* __restrict__ w,const float* __restrict__ b,int so_bits,int M,int L0){
  extern __shared__ float sm[];
  unsigned* Wh=(unsigned*)sm; unsigned* Wl=Wh+4096;
  float* w0s=(float*)(Wl+2048); float* b0s=w0s+768; float* bs=b0s+64;
  float* Ah=bs+64; float* Al=Ah+8704;
  const int t=threadIdx.x,lane=t&31,wid=t>>5;
  const int Rbase=blockIdx.x*128;
  if(L0){for(int i=t;i<768;i+=256){int oc=i/12,r=i-oc*12;w0s[r*64+oc]=w0[i];} if(t<64)b0s[t]=b0c[t];}
  if(t<64)bs[t]=b[t];
  const int S_out=1<<so_bits,S_in=S_out<<1,so2=so_bits*2;
  const int g=lane>>2,tq=lane&3,mrow=wid*16+g,ab=mrow*68+tq;
  float C[8][4];
  #pragma unroll
  for(int i=0;i<8;i++){C[i][0]=0;C[i][1]=0;C[i][2]=0;C[i][3]=0;}
  for(int p=0;p<4;p++){
    const int ky=p>>1,kx=p&1;
    __syncthreads();
    if(L0){
      int row=t>>1,half=t&1,R=Rbase+row;
      int n=R>>8,sp=R&255,oy=sp>>4,ox=sp&15;
      int y0=2*oy+ky,x0=2*ox+kx;
      float in12[12];
      #pragma unroll
      for(int ci=0;ci<3;ci++)
        #pragma unroll
        for(int q=0;q<4;q++)
          in12[ci*4+q]=crop[(((size_t)n*3+ci)*64+2*y0+(q>>1))*64+2*x0+(q&1)];
      for(int c=half*32;c<half*32+32;c++){
        float acc=b0s[c];
        #pragma unroll
        for(int j=0;j<12;j++)acc+=in12[j]*w0s[j*64+c];
        acc=fmaxf(acc,0.f);
        SPLIT_ST(Ah[row*68+c],Al[row*68+c],acc);
      }
    } else {
      for(int e=t*4;e<8192;e+=1024){
        int row=e>>6,c4=e&63,R=Rbase+row;
        float4 v=make_float4(0,0,0,0);
        if(R<M){int n=R>>so2,sp=R&(S_out*S_out-1),oy=sp>>so_bits,ox=sp&(S_out-1);
          v=*(const float4*)&in[(((size_t)n*S_in+2*oy+ky)*S_in+2*ox+kx)*64+c4];}
        float* dh=&Ah[row*68+c4]; float* dl=&Al[row*68+c4];
        SPLIT_ST(dh[0],dl[0],v.x);SPLIT_ST(dh[1],dl[1],v.y);
        SPLIT_ST(dh[2],dl[2],v.z);SPLIT_ST(dh[3],dl[3],v.w);
      }
    }
    #define GETC(kk,nn) (w[(nn)*256+(kk)*4+p])
    STAGE_W(Wh,Wl,8,GETC);
    #undef GETC
    __syncthreads();
    mma_sweep(Ah,Al,Wh,Wl,8,C,ab);
  }
  #pragma unroll
  for(int nt=0;nt<8;nt++){
    int col=nt*8+tq*2,r0=Rbase+mrow,r1=r0+8;
    if(r0<M){float2 v;v.x=fmaxf(C[nt][0]+bs[col],0.f);v.y=fmaxf(C[nt][1]+bs[col+1],0.f);
      *(float2*)&out[(size_t)r0*64+col]=v;}
    if(r1<M){float2 v;v.x=fmaxf(C[nt][2]+bs[col],0.f);v.y=fmaxf(C[nt][3]+bs[col+1],0.f);
      *(float2*)&out[(size_t)r1*64+col]=v;}
  }
}

// =========== msg MLP (192->64->64) + scatter-add (mma), 128 edges/block =====
__global__ void __launch_bounds__(256,2) k_msg(const float* __restrict__ node,
    const float* __restrict__ edge,const int* __restrict__ ei,
    const float* __restrict__ w1,const float* __restrict__ b1,
    const float* __restrict__ w2,const float* __restrict__ b2,float* __restrict__ agg){
  extern __shared__ float sm[];
  unsigned* Wh=(unsigned*)sm; unsigned* Wl=Wh+4096;
  float* b1s=(float*)(Wl+2048); float* b2s=b1s+64;
  float* Ah=b2s+64; float* Al=Ah+8704;
  int* srcs=(int*)(Al+8704); int* dsts=srcs+128;
  const int t=threadIdx.x,lane=t&31,wid=t>>5;
  const int ebase=blockIdx.x*128;
  if(t<64){b1s[t]=b1[t];b2s[t]=b2[t];}
  if(t<128){srcs[t]=ei[ebase+t];dsts[t]=ei[EE+ebase+t];}
  const int g=lane>>2,tq=lane&3,mrow=wid*16+g,ab=mrow*68+tq;
  float C1[8][4];
  #pragma unroll
  for(int i=0;i<8;i++){C1[i][0]=0;C1[i][1]=0;C1[i][2]=0;C1[i][3]=0;}
  for(int ch=0;ch<3;ch++){
    __syncthreads();
    for(int e=t*4;e<8192;e+=1024){
      int row=e>>6,c4=e&63;
      const float* bp=(ch==0)?&node[(size_t)dsts[row]*64]:(ch==1)?&node[(size_t)srcs[row]*64]
                     :&edge[(size_t)(ebase+row)*64];
      float4 v=*(const float4*)&bp[c4];
      float* dh=&Ah[row*68+c4]; float* dl=&Al[row*68+c4];
      SPLIT_ST(dh[0],dl[0],v.x);SPLIT_ST(dh[1],dl[1],v.y);
      SPLIT_ST(dh[2],dl[2],v.z);SPLIT_ST(dh[3],dl[3],v.w);
    }
    #define GETM(kk,nn) (w1[((ch)*64+(kk))*64+(nn)])
    STAGE_W(Wh,Wl,8,GETM);
    #undef GETM
    __syncthreads();
    mma_sweep(Ah,Al,Wh,Wl,8,C1,ab);
  }
  __syncthreads();
  #pragma unroll
  for(int nt=0;nt<8;nt++){
    int col=nt*8+tq*2;
    float v00=fmaxf(C1[nt][0]+b1s[col],0.f),v01=fmaxf(C1[nt][1]+b1s[col+1],0.f);
    float v10=fmaxf(C1[nt][2]+b1s[col],0.f),v11=fmaxf(C1[nt][3]+b1s[col+1],0.f);
    SPLIT_ST(Ah[mrow*68+col],Al[mrow*68+col],v00);
    SPLIT_ST(Ah[mrow*68+col+1],Al[mrow*68+col+1],v01);
    SPLIT_ST(Ah[(mrow+8)*68+col],Al[(mrow+8)*68+col],v10);
    SPLIT_ST(Ah[(mrow+8)*68+col+1],Al[(mrow+8)*68+col+1],v11);
  }
  #define GETM2(kk,nn) (w2[(kk)*64+(nn)])
  STAGE_W(Wh,Wl,8,GETM2);
  #undef GETM2
  __syncthreads();
  float C2[8][4];
  #pragma unroll
  for(int i=0;i<8;i++){C2[i][0]=0;C2[i][1]=0;C2[i][2]=0;C2[i][3]=0;}
  mma_sweep(Ah,Al,Wh,Wl,8,C2,ab);
  const int d0=dsts[mrow],d1=dsts[mrow+8];
  #pragma unroll
  for(int nt=0;nt<8;nt++){
    int col=nt*8+tq*2;
    atomicAdd(&agg[(size_t)d0*64+col],C2[nt][0]+b2s[col]);
    atomicAdd(&agg[(size_t)d0*64+col+1],C2[nt][1]+b2s[col+1]);
    atomicAdd(&agg[(size_t)d1*64+col],C2[nt][2]+b2s[col]);
    atomicAdd(&agg[(size_t)d1*64+col+1],C2[nt][3]+b2s[col+1]);
  }
}

// --------------------------------------------- node_update: [x|cf]@W + LN
__global__ void __launch_bounds__(256) k_nodeup(const float* __restrict__ x,
    const float* __restrict__ cf, const float* __restrict__ w, const float* __restrict__ b,
    const float* __restrict__ g, const float* __restrict__ be, float* __restrict__ out) {
    extern __shared__ float sm[];
    float* Ws = sm;
    float* Bs = Ws + 6144; float* Gs = Bs + 64; float* BEs = Gs + 64;
    float* mu = BEs + 64; float* rs = mu + 64;
    float* As = rs + 64; float* Hs = As + 6400;
    int t = threadIdx.x;
    int Rbase = blockIdx.x * 64;
    for (int i = t; i < 6144; i += 256) Ws[i] = w[i];
    if (t < 64) { Bs[t]=b[t]; Gs[t]=g[t]; BEs[t]=be[t]; }
    for (int e = t; e < 2048; e += 256) {
        int row = e >> 5, c = e & 31, nd = Rbase + row;
        As[row * 100 + c] = (nd < NN) ? x[nd * 32 + c] : 0.f;
    }
    for (int e = t; e < 4096; e += 256) {
        int row = e >> 6, c = e & 63, nd = Rbase + row;
        As[row * 100 + 32 + c] = (nd < NN) ? cf[nd * 64 + c] : 0.f;
    }
    __syncthreads();
    int tr = t >> 4, tc = t & 15;
    float acc[4][4];
    float4 b4 = *(const float4*)&Bs[tc * 4];
    #pragma unroll
    for (int i = 0; i < 4; i++) { acc[i][0]=b4.x; acc[i][1]=b4.y; acc[i][2]=b4.z; acc[i][3]=b4.w; }
    for (int k = 0; k < 96; k++) {
        float4 w4 = *(const float4*)&Ws[k * 64 + tc * 4];
        #pragma unroll
        for (int i = 0; i < 4; i++) {
            float a = As[(tr * 4 + i) * 100 + k];
            acc[i][0] += a*w4.x; acc[i][1] += a*w4.y; acc[i][2] += a*w4.z; acc[i][3] += a*w4.w;
        }
    }
    #pragma unroll
    for (int i = 0; i < 4; i++) {
        float4 r; r.x=fmaxf(acc[i][0],0.f); r.y=fmaxf(acc[i][1],0.f);
        r.z=fmaxf(acc[i][2],0.f); r.w=fmaxf(acc[i][3],0.f);
        *(float4*)&Hs[(tr * 4 + i) * 68 + tc * 4] = r;
    }
    __syncthreads();
    if (t < 64) {
        float s = 0.f, sq = 0.f;
        for (int c = 0; c < 64; c++) { float v = Hs[t * 68 + c]; s += v; sq += v * v; }
        float m = s * (1.f / 64.f);
        mu[t] = m; rs[t] = rsqrtf(sq * (1.f / 64.f) - m * m + 1e-5f);
    }
    __syncthreads();
    for (int i = t; i < 4096; i += 256) {
        int r = i >> 6, c = i & 63, nd = Rbase + r;
        if (nd < NN) out[nd * 64 + c] = (Hs[r * 68 + c] - mu[r]) * rs[r] * Gs[c] + BEs[c];
    }
}

// --------------------------------------------- edge_update: ea@W + LN
__global__ void __launch_bounds__(256) k_edgeup(const float* __restrict__ ea,
    const float* __restrict__ w, const float* __restrict__ b,
    const float* __restrict__ g, const float* __restrict__ be, float* __restrict__ out) {
    __shared__ float Ws[384], Bs[64], Gs[64], BEs[64], Aa[64][8], Hs[64][68], mu[64], rs[64];
    int t = threadIdx.x;
    int ebase = blockIdx.x * 64;
    for (int i = t; i < 384; i += 256) Ws[i] = w[i];
    if (t < 64) { Bs[t]=b[t]; Gs[t]=g[t]; BEs[t]=be[t]; }
    for (int e = t; e < 384; e += 256) {
        int row = e / 6, k = e - row * 6;
        Aa[row][k] = ea[(size_t)(ebase + row) * 6 + k];
    }
    __syncthreads();
    int r = t >> 2, cg = (t & 3) * 16;
    float a0=Aa[r][0],a1=Aa[r][1],a2=Aa[r][2],a3=Aa[r][3],a4=Aa[r][4],a5=Aa[r][5];
    #pragma unroll
    for (int j = 0; j < 16; j++) {
        int c = cg + j;
        float h = Bs[c] + a0*Ws[c] + a1*Ws[64+c] + a2*Ws[128+c] + a3*Ws[192+c] + a4*Ws[256+c] + a5*Ws[320+c];
        Hs[r][c] = fmaxf(h, 0.f);
    }
    __syncthreads();
    if (t < 64) {
        float s = 0.f, sq = 0.f;
        for (int c = 0; c < 64; c++) { float v = Hs[t][c]; s += v; sq += v * v; }
        float m = s * (1.f / 64.f);
        mu[t] = m; rs[t] = rsqrtf(sq * (1.f / 64.f) - m * m + 1e-5f);
    }
    __syncthreads();
    for (int i = t; i < 4096; i += 256) {
        int rr = i >> 6, c = i & 63;
        out[(size_t)ebase * 64 + i] = (Hs[rr][c] - mu[rr]) * rs[rr] * Gs[c] + BEs[c];
    }
}

// ========= node MLP: [node|agg] 2-layer, 128 nodes/block, 4x8 per thread =====
__global__ void __launch_bounds__(256, 2) k_nodemlp(const float* __restrict__ node,
    const float* __restrict__ agg, const float* __restrict__ w1, const float* __restrict__ b1,
    const float* __restrict__ w2, const float* __restrict__ b2, float* __restrict__ out) {
    extern __shared__ float sm[];
    float* W1s = sm;
    float* W2s = W1s + 8192;
    float* B1s = W2s + 4096; float* B2s = B1s + 64;
    float* As = B2s + 64;
    const int t = threadIdx.x;
    const int Rbase = blockIdx.x * 128;
    for (int i = t; i < 8192; i += 256) W1s[i] = w1[i];
    for (int i = t; i < 4096; i += 256) W2s[i] = w2[i];
    if (t < 64) { B1s[t]=b1[t]; B2s[t]=b2[t]; }
    const int tr = t >> 3, tc = t & 7;
    const float* ar[4];
    #pragma unroll
    for (int i = 0; i < 4; i++) ar[i] = &As[(tr * 4 + i) * 65];
    float acc[4][8];
    for (int ch = 0; ch < 2; ch++) {
        __syncthreads();
        for (int e = t * 4; e < 8192; e += 1024) {
            int row = e >> 6, c4 = e & 63, nd = Rbase + row;
            float4 vv = make_float4(0.f,0.f,0.f,0.f);
            if (nd < NN) {
                const float* base = (ch == 0) ? &node[(size_t)nd * 64] : &agg[(size_t)nd * 64];
                vv = *(const float4*)&base[c4];
            }
            float* d = &As[row * 65 + c4];
            d[0]=vv.x; d[1]=vv.y; d[2]=vv.z; d[3]=vv.w;
        }
        __syncthreads();
        if (ch == 0) {
            float4 ba = *(const float4*)&B1s[tc * 8];
            float4 bb = *(const float4*)&B1s[tc * 8 + 4];
            #pragma unroll
            for (int i = 0; i < 4; i++) {
                acc[i][0]=ba.x;acc[i][1]=ba.y;acc[i][2]=ba.z;acc[i][3]=ba.w;
                acc[i][4]=bb.x;acc[i][5]=bb.y;acc[i][6]=bb.z;acc[i][7]=bb.w;
            }
        }
        const float* wp = &W1s[ch * 4096 + tc * 8];
        #pragma unroll 8
        for (int k = 0; k < 64; k++) {
            float4 wa = *(const float4*)&wp[k * 64];
            float4 wb = *(const float4*)&wp[k * 64 + 4];
            #pragma unroll
            for (int i = 0; i < 4; i++) {
                float a = ar[i][k];
                acc[i][0]+=a*wa.x; acc[i][1]+=a*wa.y; acc[i][2]+=a*wa.z; acc[i][3]+=a*wa.w;
                acc[i][4]+=a*wb.x; acc[i][5]+=a*wb.y; acc[i][6]+=a*wb.z; acc[i][7]+=a*wb.w;
            }
        }
    }
    __syncthreads();
    #pragma unroll
    for (int i = 0; i < 4; i++)
        #pragma unroll
        for (int j = 0; j < 8; j++)
            As[(tr * 4 + i) * 65 + tc * 8 + j] = fmaxf(acc[i][j], 0.f);
    __syncthreads();
    float a2[4][8];
    {
        float4 ba = *(const float4*)&B2s[tc * 8];
        float4 bb = *(const float4*)&B2s[tc * 8 + 4];
        #pragma unroll
        for (int i = 0; i < 4; i++) {
            a2[i][0]=ba.x;a2[i][1]=ba.y;a2[i][2]=ba.z;a2[i][3]=ba.w;
            a2[i][4]=bb.x;a2[i][5]=bb.y;a2[i][6]=bb.z;a2[i][7]=bb.w;
        }
    }
    const float* wp2 = &W2s[tc * 8];
    #pragma unroll 8
    for (int k = 0; k < 64; k++) {
        float4 wa = *(const float4*)&wp2[k * 64];
        float4 wb = *(const float4*)&wp2[k * 64 + 4];
        #pragma unroll
        for (int i = 0; i < 4; i++) {
            float a = ar[i][k];
            a2[i][0]+=a*wa.x; a2[i][1]+=a*wa.y; a2[i][2]+=a*wa.z; a2[i][3]+=a*wa.w;
            a2[i][4]+=a*wb.x; a2[i][5]+=a*wb.y; a2[i][6]+=a*wb.z; a2[i][7]+=a*wb.w;
        }
    }
    #pragma unroll
    for (int i = 0; i < 4; i++) {
        int nd = Rbase + tr * 4 + i;
        if (nd < NN) {
            float4 v;
            v.x=a2[i][0]; v.y=a2[i][1]; v.z=a2[i][2]; v.w=a2[i][3];
            *(float4*)&out[(size_t)nd * 64 + tc * 8] = v;
            v.x=a2[i][4]; v.y=a2[i][5]; v.z=a2[i][6]; v.w=a2[i][7];
            *(float4*)&out[(size_t)nd * 64 + tc * 8 + 4] = v;
        }
    }
}

// --------------------------------------------- final edge MLP: 134->128->64->1
__global__ void __launch_bounds__(256) k_final(const float* __restrict__ node,
    const float* __restrict__ ea, const int* __restrict__ ei,
    const float* __restrict__ w1, const float* __restrict__ b1,
    const float* __restrict__ w2, const float* __restrict__ b2,
    const float* __restrict__ w3, const float* __restrict__ b3, float* __restrict__ out) {
    extern __shared__ float sm[];
    float* W1s = sm;
    float* B1s = W1s + 17152;
    float* W2s = B1s + 128;
    float* B2s = W2s + 8192;
    float* w3s = B2s + 64;
    float* b3s = w3s + 64;
    float* As  = b3s + 4;
    float* Hs  = As + 4352;
    float* H2s = Hs + 8448;
    int* srcs = (int*)(H2s + 4352);
    int* dsts = srcs + 64;
    int t = threadIdx.x;
    int ebase = blockIdx.x * 64;
    for (int i = t; i < 17152; i += 256) W1s[i] = w1[i];
    for (int i = t; i < 8192; i += 256) W2s[i] = w2[i];
    if (t < 128) B1s[t] = b1[t];
    if (t < 64) { B2s[t]=b2[t]; w3s[t]=w3[t]; srcs[t]=ei[ebase+t]; dsts[t]=ei[EE+ebase+t]; }
    if (t == 0) b3s[0] = b3[0];
    int tr = t >> 4, tc = t & 15;
    float acc[4][8];
    for (int ch = 0; ch < 2; ch++) {
        __syncthreads();
        for (int e = t * 4; e < 4096; e += 1024) {
            int row = e >> 6, c4 = e & 63;
            const float* base = (ch == 0) ? &node[(size_t)srcs[row] * 64]
                                          : &node[(size_t)dsts[row] * 64];
            *(float4*)&As[row * 68 + c4] = *(const float4*)&base[c4];
        }
        __syncthreads();
        if (ch == 0) {
            #pragma unroll
            for (int i = 0; i < 4; i++)
                #pragma unroll
                for (int j = 0; j < 8; j++) acc[i][j] = B1s[tc * 8 + j];
        }
        for (int k = 0; k < 64; k++) {
            float4 wa = *(const float4*)&W1s[(ch * 64 + k) * 128 + tc * 8];
            float4 wb = *(const float4*)&W1s[(ch * 64 + k) * 128 + tc * 8 + 4];
            #pragma unroll
            for (int i = 0; i < 4; i++) {
                float a = As[(tr * 4 + i) * 68 + k];
                acc[i][0]+=a*wa.x; acc[i][1]+=a*wa.y; acc[i][2]+=a*wa.z; acc[i][3]+=a*wa.w;
                acc[i][4]+=a*wb.x; acc[i][5]+=a*wb.y; acc[i][6]+=a*wb.z; acc[i][7]+=a*wb.w;
            }
        }
    }
    __syncthreads();
    for (int e = t; e < 384; e += 256) {
        int row = e / 6, k = e - row * 6;
        As[row * 8 + k] = ea[(size_t)(ebase + row) * 6 + k];
    }
    __syncthreads();
    for (int k = 0; k < 6; k++) {
        float4 wa = *(const float4*)&W1s[(128 + k) * 128 + tc * 8];
        float4 wb = *(const float4*)&W1s[(128 + k) * 128 + tc * 8 + 4];
        #pragma unroll
        for (int i = 0; i < 4; i++) {
            float a = As[(tr * 4 + i) * 8 + k];
            acc[i][0]+=a*wa.x; acc[i][1]+=a*wa.y; acc[i][2]+=a*wa.z; acc[i][3]+=a*wa.w;
            acc[i][4]+=a*wb.x; acc[i][5]+=a*wb.y; acc[i][6]+=a*wb.z; acc[i][7]+=a*wb.w;
        }
    }
    #pragma unroll
    for (int i = 0; i < 4; i++)
        #pragma unroll
        for (int j = 0; j < 8; j++)
            Hs[(tr * 4 + i) * 132 + tc * 8 + j] = fmaxf(acc[i][j], 0.f);
    __syncthreads();
    float a2[4][4];
    #pragma unroll
    for (int i = 0; i < 4; i++)
        #pragma unroll
        for (int j = 0; j < 4; j++) a2[i][j] = B2s[tc * 4 + j];
    for (int k = 0; k < 128; k++) {
        float4 w4 = *(const float4*)&W2s[k * 64 + tc * 4];
        #pragma unroll
        for (int i = 0; i < 4; i++) {
            float a = Hs[(tr * 4 + i) * 132 + k];
            a2[i][0] += a*w4.x; a2[i][1] += a*w4.y; a2[i][2] += a*w4.z; a2[i][3] += a*w4.w;
        }
    }
    #pragma unroll
    for (int i = 0; i < 4; i++)
        #pragma unroll
        for (int j = 0; j < 4; j++)
            H2s[(tr * 4 + i) * 68 + tc * 4 + j] = fmaxf(a2[i][j], 0.f);
    __syncthreads();
    if (t < 64) {
        float s = b3s[0];
        for (int c = 0; c < 64; c++) s += H2s[t * 68 + c] * w3s[c];
        out[ebase + t] = s;
    }
}

// ============================================================================
extern "C" void kernel_launch(void* const* d_in, const int* in_sizes, int n_in,
                              void* d_out, int out_size) {
    const float *x=0,*ea=0,*crop=0,*cw0=0,*cb0=0,*cw=0,*cb=0,*nu_w=0,*nu_b=0,*nu_g=0,*nu_be=0,
        *eu_w=0,*eu_b=0,*eu_g=0,*eu_be=0,*ie_w1=0,*ie_b1=0,*ie_w2=0,*ie_b2=0,
        *in_w1=0,*in_b1=0,*in_w2=0,*in_b2=0,*em_w1=0,*em_b1=0,*em_w2=0,*em_b2=0,*em_w3=0,*em_b3=0;
    const int* ei = 0;
    int c64 = 0, c256 = 0, c16k = 0;
    for (int i = 0; i < n_in; i++) {
        const float* p = (const float*)d_in[i];
        switch (in_sizes[i]) {
            case 320000: x = p; break;
            case 640000: ei = (const int*)p; break;
            case 1920000: ea = p; break;
            case 122880000: crop = p; break;
            case 768: cw0 = p; break;
            case 81920: cw = p; break;
            case 320: cb = p; break;
            case 6144: nu_w = p; break;
            case 384: eu_w = p; break;
            case 49152: ie_w1 = p; break;
            case 32768: in_w1 = p; break;
            case 17152: em_w1 = p; break;
            case 128: em_b1 = p; break;
            case 8192: em_w2 = p; break;
            case 1: em_b3 = p; break;
            case 16384: if (c16k++ == 0) ie_w2 = p; else in_w2 = p; break;
            case 256:
                if (c256 == 0) ie_b1 = p; else if (c256 == 1) ie_b2 = p;
                else if (c256 == 2) in_b1 = p; else in_b2 = p;
                c256++; break;
            case 64: {
                const float** slots[9] = {&cb0,&nu_b,&nu_g,&nu_be,&eu_b,&eu_g,&eu_be,&em_b2,&em_w3};
                if (c64 < 9) *slots[c64] = p;
                c64++; break;
            }
            default: break;
        }
    }
    float *b0, *b1, *cf, *nA, *nB, *agg, *edg;
    cudaGetSymbolAddress((void**)&b0, g_b0);
    cudaGetSymbolAddress((void**)&b1, g_b1);
    cudaGetSymbolAddress((void**)&cf, g_cf);
    cudaGetSymbolAddress((void**)&nA, g_nA);
    cudaGetSymbolAddress((void**)&nB, g_nB);
    cudaGetSymbolAddress((void**)&agg, g_agg);
    cudaGetSymbolAddress((void**)&edg, g_edge);

    const int SM_CNN = (4096 + 2048) * 4 + (768 + 64 + 64 + 8704 + 8704) * 4;
    const int SM_MSG = (4096 + 2048) * 4 + (64 + 64 + 8704 + 8704) * 4 + 256 * 4;
    const int SM_NU  = (6144 + 64 * 5 + 6400 + 4352 + 64) * 4;
    const int SM_NM  = (8192 + 4096 + 128 + 8320) * 4;
    const int SM_FIN = (17152 + 128 + 8192 + 64 + 64 + 4 + 4352 + 8448 + 4352) * 4 + 512;
    cudaFuncSetAttribute(k_cnn,     cudaFuncAttributeMaxDynamicSharedMemorySize, SM_CNN);
    cudaFuncSetAttribute(k_msg,     cudaFuncAttributeMaxDynamicSharedMemorySize, SM_MSG);
    cudaFuncSetAttribute(k_nodeup,  cudaFuncAttributeMaxDynamicSharedMemorySize, SM_NU);
    cudaFuncSetAttribute(k_nodemlp, cudaFuncAttributeMaxDynamicSharedMemorySize, SM_NM);
    cudaFuncSetAttribute(k_final,   cudaFuncAttributeMaxDynamicSharedMemorySize, SM_FIN);

    // CNN stack (layer 0 fuses conv0 inline)
    k_cnn<<<20000, 256, SM_CNN>>>(crop, crop, b1, cw0, cb0, cw,         cb,       4, NN*256, 1);
    k_cnn<<<5000,  256, SM_CNN>>>(crop, b1,   b0, cw0, cb0, cw + 16384, cb + 64,  3, NN*64,  0);
    k_cnn<<<1250,  256, SM_CNN>>>(crop, b0,   b1, cw0, cb0, cw + 32768, cb + 128, 2, NN*16,  0);
    k_cnn<<<313,   256, SM_CNN>>>(crop, b1,   b0, cw0, cb0, cw + 49152, cb + 192, 1, NN*4,   0);
    k_cnn<<<79,    256, SM_CNN>>>(crop, b0,   cf, cw0, cb0, cw + 65536, cb + 256, 0, NN,     0);
    // encoders
    k_nodeup<<<157, 256, SM_NU>>>(x, cf, nu_w, nu_b, nu_g, nu_be, nA);
    k_edgeup<<<5000, 256>>>(ea, eu_w, eu_b, eu_g, eu_be, edg);
    // 4 interaction layers
    float* cur = nA; float* nxt = nB;
    for (int l = 0; l < 4; l++) {
        cudaMemsetAsync(agg, 0, (size_t)NN * 64 * sizeof(float), 0);
        k_msg<<<2500, 256, SM_MSG>>>(cur, edg, ei, ie_w1 + l * 12288, ie_b1 + l * 64,
                                     ie_w2 + l * 4096, ie_b2 + l * 64, agg);
        k_nodemlp<<<79, 256, SM_NM>>>(cur, agg, in_w1 + l * 8192, in_b1 + l * 64,
                                      in_w2 + l * 4096, in_b2 + l * 64, nxt);
        float* tmp = cur; cur = nxt; nxt = tmp;
    }
    // final edge MLP
    k_final<<<5000, 256, SM_FIN>>>(cur, ea, ei, em_w1, em_b1, em_w2, em_b2,
                                   em_w3, em_b3, (float*)d_out);
}

// round 7
// speedup vs baseline: 2.1434x; 1.1145x over previous
#include <cuda_runtime.h>
#include <cstdint>

#define NN 10000
#define EE 320000

__device__ float g_b1[(size_t)NN*256*64];
__device__ float g_b0[(size_t)NN*64*64];
__device__ float g_cf[NN*64];
__device__ float g_nA[NN*64];
__device__ float g_nB[NN*64];
__device__ float g_agg[NN*64];
__device__ float g_edge[(size_t)EE*64];

__device__ __forceinline__ unsigned f2tf(float x){unsigned r;asm("cvt.rna.tf32.f32 %0,%1;":"=r"(r):"f"(x));return r;}
__device__ __forceinline__ void mma8(float* c,unsigned a0,unsigned a1,unsigned a2,unsigned a3,unsigned b0,unsigned b1){
  asm("mma.sync.aligned.m16n8k8.row.col.f32.tf32.tf32.f32 {%0,%1,%2,%3},{%4,%5,%6,%7},{%8,%9},{%0,%1,%2,%3};"
      :"+f"(c[0]),"+f"(c[1]),"+f"(c[2]),"+f"(c[3]):"r"(a0),"r"(a1),"r"(a2),"r"(a3),"r"(b0),"r"(b1));}
__device__ __forceinline__ void cpa16(uint32_t d,const void* s,int sz){
  asm volatile("cp.async.cg.shared.global [%0],[%1],16,%2;"::"r"(d),"l"(s),"r"(sz));}
__device__ __forceinline__ void cpacommit(){asm volatile("cp.async.commit_group;");}
template<int N> __device__ __forceinline__ void cpawait(){asm volatile("cp.async.wait_group %0;"::"n"(N));}

// raw-A sweep: split hi/lo in registers. A stride 68. 8 n-tiles, KT k-tiles, 3-term.
__device__ __forceinline__ void mma_sweep(const float* A,const unsigned* Wh,const unsigned* Wl,
    int KT,float C[][4],int ab){
  const int lane=threadIdx.x&31;
  for(int kt=0;kt<KT;kt++){
    const float* ap=A+ab+kt*8;
    float v0=ap[0],v1=ap[8*68],v2=ap[4],v3=ap[8*68+4];
    unsigned a0=f2tf(v0),a1=f2tf(v1),a2=f2tf(v2),a3=f2tf(v3);
    unsigned l0=__float_as_uint(v0-__uint_as_float(a0)),l1=__float_as_uint(v1-__uint_as_float(a1));
    unsigned l2=__float_as_uint(v2-__uint_as_float(a2)),l3=__float_as_uint(v3-__uint_as_float(a3));
    #pragma unroll
    for(int nt=0;nt<8;nt++){
      int s=(kt*8+nt)*32+lane;
      uint2 bh=*(const uint2*)(Wh+2*(size_t)s);
      unsigned ul=Wl[s];
      mma8(C[nt],a0,a1,a2,a3,bh.x,bh.y);
      mma8(C[nt],a0,a1,a2,a3,ul<<16,ul&0xFFFF0000u);
      mma8(C[nt],l0,l1,l2,l3,bh.x,bh.y);
    }
  }
}

#define STAGE_W(Wh,Wl,KT,GET) do{ for(int s_=threadIdx.x;s_<(KT)*256;s_+=256){ \
  int lane_=s_&31,nt_=(s_>>5)&7,kt_=s_>>8; int nn=nt_*8+(lane_>>2),kk=kt_*8+(lane_&3); \
  float w0v=GET(kk,nn),w1v=GET((kk+4),nn); unsigned h0=f2tf(w0v),h1=f2tf(w1v); \
  float q0=w0v-__uint_as_float(h0),q1=w1v-__uint_as_float(h1); \
  (Wh)[2*s_]=h0;(Wh)[2*s_+1]=h1; (Wl)[s_]=(__float_as_uint(q0)>>16)|(__float_as_uint(q1)&0xFFFF0000u);} }while(0)

// =========== unified CNN layer (mma, cp.async pipelined); L0 fuses conv0 ====
__global__ void __launch_bounds__(256,2) k_cnn(const float* __restrict__ crop,
    const float* __restrict__ in,float* __restrict__ out,
    const float* __restrict__ w0,const float* __restrict__ b0c,
    const float* __restrict__ w,const float* __restrict__ b,int so_bits,int M,int L0){
  extern __shared__ float sm[];
  unsigned* Wh=(unsigned*)sm; unsigned* Wl=Wh+4096;
  float* w0s=(float*)(Wl+2048); float* b0s=w0s+768; float* bs=b0s+64;
  float* A0=bs+64; float* A1=A0+8704;   // !L0: double buffer; L0: A1 = crop window
  const int t=threadIdx.x,lane=t&31,wid=t>>5;
  const int Rbase=blockIdx.x*128;
  const int S_out=1<<so_bits,S_in=S_out<<1,so2=so_bits*2;
  if(L0){
    for(int i=t;i<768;i+=256){int oc=i/12,r=i-oc*12;w0s[r*64+oc]=w0[i];}
    if(t<64)b0s[t]=b0c[t];
    int n=Rbase>>8,half=(Rbase>>7)&1;
    for(int i=t*4;i<6144;i+=1024){
      int c=i>>11,r=i&2047,y=r>>6,xx=r&63;
      *(float4*)&A1[i]=*(const float4*)&crop[(((size_t)n*3+c)*64+half*32+y)*64+xx];
    }
  }
  if(t<64)bs[t]=b[t];
  const int g=lane>>2,tq=lane&3,mrow=wid*16+g,ab=mrow*68+tq;
  auto issueA=[&](int pp,float* buf){
    int ky_=pp>>1,kx_=pp&1;
    uint32_t db=(uint32_t)__cvta_generic_to_shared(buf);
    #pragma unroll
    for(int k_=0;k_<8;k_++){
      int idx=t+k_*256,row=idx>>4,c4=(idx&15)*4,R=Rbase+row;
      const float* s_=in; int sz_=0;
      if(R<M){int n_=R>>so2,sp_=R&(S_out*S_out-1),oy_=sp_>>so_bits,ox_=sp_&(S_out-1);
        s_=&in[(((size_t)n_*S_in+2*oy_+ky_)*S_in+2*ox_+kx_)*64+c4];sz_=16;}
      cpa16(db+(row*68+c4)*4,s_,sz_);
    }
  };
  float C[8][4];
  #pragma unroll
  for(int i=0;i<8;i++){C[i][0]=0;C[i][1]=0;C[i][2]=0;C[i][3]=0;}
  if(!L0){issueA(0,A0);cpacommit();}
  for(int p=0;p<4;p++){
    const int ky=p>>1,kx=p&1;
    if(!L0&&p<3){issueA(p+1,(p&1)?A0:A1);cpacommit();}
    #define GETC(kk,nn) (w[(nn)*256+(kk)*4+p])
    STAGE_W(Wh,Wl,8,GETC);
    #undef GETC
    if(!L0){if(p<3)cpawait<1>();else cpawait<0>();}
    __syncthreads();
    if(L0){
      int row=t>>1,hc=t&1;
      int sp=(Rbase+row)&255,oy=sp>>4,ox=sp&15;
      int oyl=oy-((Rbase>>7)&1)*8;
      int y0=2*oyl+ky,x0=2*ox+kx;
      float in12[12];
      #pragma unroll
      for(int ci=0;ci<3;ci++)
        #pragma unroll
        for(int q=0;q<4;q++)
          in12[ci*4+q]=A1[ci*2048+(2*y0+(q>>1))*64+2*x0+(q&1)];
      for(int c=hc*32;c<hc*32+32;c++){
        float acc=b0s[c];
        #pragma unroll
        for(int j=0;j<12;j++)acc+=in12[j]*w0s[j*64+c];
        A0[row*68+c]=fmaxf(acc,0.f);
      }
      __syncthreads();
    }
    mma_sweep(L0?A0:((p&1)?A1:A0),Wh,Wl,8,C,ab);
    __syncthreads();
  }
  #pragma unroll
  for(int nt=0;nt<8;nt++){
    int col=nt*8+tq*2,r0=Rbase+mrow,r1=r0+8;
    if(r0<M){float2 v;v.x=fmaxf(C[nt][0]+bs[col],0.f);v.y=fmaxf(C[nt][1]+bs[col+1],0.f);
      *(float2*)&out[(size_t)r0*64+col]=v;}
    if(r1<M){float2 v;v.x=fmaxf(C[nt][2]+bs[col],0.f);v.y=fmaxf(C[nt][3]+bs[col+1],0.f);
      *(float2*)&out[(size_t)r1*64+col]=v;}
  }
}

// ====== msg MLP (192->64->64) + scatter-add, cp.async pipelined =============
__global__ void __launch_bounds__(256,2) k_msg(const float* __restrict__ node,
    const float* __restrict__ edge,const int* __restrict__ ei,
    const float* __restrict__ w1,const float* __restrict__ b1,
    const float* __restrict__ w2,const float* __restrict__ b2,float* __restrict__ agg){
  extern __shared__ float sm[];
  unsigned* Wh=(unsigned*)sm; unsigned* Wl=Wh+4096;
  float* b1s=(float*)(Wl+2048); float* b2s=b1s+64;
  float* A0=b2s+64; float* A1=A0+8704;
  int* srcs=(int*)(A1+8704); int* dsts=srcs+128;
  const int t=threadIdx.x,lane=t&31,wid=t>>5;
  const int ebase=blockIdx.x*128;
  if(t<64){b1s[t]=b1[t];b2s[t]=b2[t];}
  if(t<128){srcs[t]=ei[ebase+t];dsts[t]=ei[EE+ebase+t];}
  const int g=lane>>2,tq=lane&3,mrow=wid*16+g,ab=mrow*68+tq;
  __syncthreads();
  auto issueM=[&](int ch,float* buf){
    uint32_t db=(uint32_t)__cvta_generic_to_shared(buf);
    #pragma unroll
    for(int k_=0;k_<8;k_++){
      int idx=t+k_*256,row=idx>>4,c4=(idx&15)*4;
      const float* s_=(ch==0)?&node[(size_t)dsts[row]*64+c4]:(ch==1)?&node[(size_t)srcs[row]*64+c4]
                     :&edge[(size_t)(ebase+row)*64+c4];
      cpa16(db+(row*68+c4)*4,s_,16);
    }
  };
  float C1[8][4];
  #pragma unroll
  for(int i=0;i<8;i++){C1[i][0]=0;C1[i][1]=0;C1[i][2]=0;C1[i][3]=0;}
  issueM(0,A0);cpacommit();
  for(int ch=0;ch<3;ch++){
    if(ch<2){issueM(ch+1,(ch&1)?A0:A1);cpacommit();}
    #define GETM(kk,nn) (w1[((ch)*64+(kk))*64+(nn)])
    STAGE_W(Wh,Wl,8,GETM);
    #undef GETM
    if(ch<2)cpawait<1>();else cpawait<0>();
    __syncthreads();
    mma_sweep((ch&1)?A1:A0,Wh,Wl,8,C1,ab);
    __syncthreads();
  }
  // H = relu(C1+b1) -> A0 raw
  #pragma unroll
  for(int nt=0;nt<8;nt++){
    int col=nt*8+tq*2;
    A0[mrow*68+col]=fmaxf(C1[nt][0]+b1s[col],0.f);
    A0[mrow*68+col+1]=fmaxf(C1[nt][1]+b1s[col+1],0.f);
    A0[(mrow+8)*68+col]=fmaxf(C1[nt][2]+b1s[col],0.f);
    A0[(mrow+8)*68+col+1]=fmaxf(C1[nt][3]+b1s[col+1],0.f);
  }
  #define GETM2(kk,nn) (w2[(kk)*64+(nn)])
  STAGE_W(Wh,Wl,8,GETM2);
  #undef GETM2
  __syncthreads();
  float C2[8][4];
  #pragma unroll
  for(int i=0;i<8;i++){C2[i][0]=0;C2[i][1]=0;C2[i][2]=0;C2[i][3]=0;}
  mma_sweep(A0,Wh,Wl,8,C2,ab);
  const int d0=dsts[mrow],d1=dsts[mrow+8];
  #pragma unroll
  for(int nt=0;nt<8;nt++){
    int col=nt*8+tq*2;
    atomicAdd(&agg[(size_t)d0*64+col],C2[nt][0]+b2s[col]);
    atomicAdd(&agg[(size_t)d0*64+col+1],C2[nt][1]+b2s[col+1]);
    atomicAdd(&agg[(size_t)d1*64+col],C2[nt][2]+b2s[col]);
    atomicAdd(&agg[(size_t)d1*64+col+1],C2[nt][3]+b2s[col+1]);
  }
}

// --------------------------------------------- node_update: [x|cf]@W + LN
__global__ void __launch_bounds__(256) k_nodeup(const float* __restrict__ x,
    const float* __restrict__ cf, const float* __restrict__ w, const float* __restrict__ b,
    const float* __restrict__ g, const float* __restrict__ be, float* __restrict__ out) {
    extern __shared__ float sm[];
    float* Ws = sm;
    float* Bs = Ws + 6144; float* Gs = Bs + 64; float* BEs = Gs + 64;
    float* mu = BEs + 64; float* rs = mu + 64;
    float* As = rs + 64; float* Hs = As + 6400;
    int t = threadIdx.x;
    int Rbase = blockIdx.x * 64;
    for (int i = t; i < 6144; i += 256) Ws[i] = w[i];
    if (t < 64) { Bs[t]=b[t]; Gs[t]=g[t]; BEs[t]=be[t]; }
    for (int e = t; e < 2048; e += 256) {
        int row = e >> 5, c = e & 31, nd = Rbase + row;
        As[row * 100 + c] = (nd < NN) ? x[nd * 32 + c] : 0.f;
    }
    for (int e = t; e < 4096; e += 256) {
        int row = e >> 6, c = e & 63, nd = Rbase + row;
        As[row * 100 + 32 + c] = (nd < NN) ? cf[nd * 64 + c] : 0.f;
    }
    __syncthreads();
    int tr = t >> 4, tc = t & 15;
    float acc[4][4];
    float4 b4 = *(const float4*)&Bs[tc * 4];
    #pragma unroll
    for (int i = 0; i < 4; i++) { acc[i][0]=b4.x; acc[i][1]=b4.y; acc[i][2]=b4.z; acc[i][3]=b4.w; }
    for (int k = 0; k < 96; k++) {
        float4 w4 = *(const float4*)&Ws[k * 64 + tc * 4];
        #pragma unroll
        for (int i = 0; i < 4; i++) {
            float a = As[(tr * 4 + i) * 100 + k];
            acc[i][0] += a*w4.x; acc[i][1] += a*w4.y; acc[i][2] += a*w4.z; acc[i][3] += a*w4.w;
        }
    }
    #pragma unroll
    for (int i = 0; i < 4; i++) {
        float4 r; r.x=fmaxf(acc[i][0],0.f); r.y=fmaxf(acc[i][1],0.f);
        r.z=fmaxf(acc[i][2],0.f); r.w=fmaxf(acc[i][3],0.f);
        *(float4*)&Hs[(tr * 4 + i) * 68 + tc * 4] = r;
    }
    __syncthreads();
    if (t < 64) {
        float s = 0.f, sq = 0.f;
        for (int c = 0; c < 64; c++) { float v = Hs[t * 68 + c]; s += v; sq += v * v; }
        float m = s * (1.f / 64.f);
        mu[t] = m; rs[t] = rsqrtf(sq * (1.f / 64.f) - m * m + 1e-5f);
    }
    __syncthreads();
    for (int i = t; i < 4096; i += 256) {
        int r = i >> 6, c = i & 63, nd = Rbase + r;
        if (nd < NN) out[nd * 64 + c] = (Hs[r * 68 + c] - mu[r]) * rs[r] * Gs[c] + BEs[c];
    }
}

// --------------------------------------------- edge_update: ea@W + LN
__global__ void __launch_bounds__(256) k_edgeup(const float* __restrict__ ea,
    const float* __restrict__ w, const float* __restrict__ b,
    const float* __restrict__ g, const float* __restrict__ be, float* __restrict__ out) {
    __shared__ float Ws[384], Bs[64], Gs[64], BEs[64], Aa[64][8], Hs[64][68], mu[64], rs[64];
    int t = threadIdx.x;
    int ebase = blockIdx.x * 64;
    for (int i = t; i < 384; i += 256) Ws[i] = w[i];
    if (t < 64) { Bs[t]=b[t]; Gs[t]=g[t]; BEs[t]=be[t]; }
    for (int e = t; e < 384; e += 256) {
        int row = e / 6, k = e - row * 6;
        Aa[row][k] = ea[(size_t)(ebase + row) * 6 + k];
    }
    __syncthreads();
    int r = t >> 2, cg = (t & 3) * 16;
    float a0=Aa[r][0],a1=Aa[r][1],a2=Aa[r][2],a3=Aa[r][3],a4=Aa[r][4],a5=Aa[r][5];
    #pragma unroll
    for (int j = 0; j < 16; j++) {
        int c = cg + j;
        float h = Bs[c] + a0*Ws[c] + a1*Ws[64+c] + a2*Ws[128+c] + a3*Ws[192+c] + a4*Ws[256+c] + a5*Ws[320+c];
        Hs[r][c] = fmaxf(h, 0.f);
    }
    __syncthreads();
    if (t < 64) {
        float s = 0.f, sq = 0.f;
        for (int c = 0; c < 64; c++) { float v = Hs[t][c]; s += v; sq += v * v; }
        float m = s * (1.f / 64.f);
        mu[t] = m; rs[t] = rsqrtf(sq * (1.f / 64.f) - m * m + 1e-5f);
    }
    __syncthreads();
    for (int i = t; i < 4096; i += 256) {
        int rr = i >> 6, c = i & 63;
        out[(size_t)ebase * 64 + i] = (Hs[rr][c] - mu[rr]) * rs[rr] * Gs[c] + BEs[c];
    }
}

// ========= node MLP: [node|agg] 2-layer, 128 nodes/block, 4x8 per thread =====
__global__ void __launch_bounds__(256, 2) k_nodemlp(const float* __restrict__ node,
    const float* __restrict__ agg, const float* __restrict__ w1, const float* __restrict__ b1,
    const float* __restrict__ w2, const float* __restrict__ b2, float* __restrict__ out) {
    extern __shared__ float sm[];
    float* W1s = sm;
    float* W2s = W1s + 8192;
    float* B1s = W2s + 4096; float* B2s = B1s + 64;
    float* As = B2s + 64;
    const int t = threadIdx.x;
    const int Rbase = blockIdx.x * 128;
    for (int i = t; i < 8192; i += 256) W1s[i] = w1[i];
    for (int i = t; i < 4096; i += 256) W2s[i] = w2[i];
    if (t < 64) { B1s[t]=b1[t]; B2s[t]=b2[t]; }
    const int tr = t >> 3, tc = t & 7;
    const float* ar[4];
    #pragma unroll
    for (int i = 0; i < 4; i++) ar[i] = &As[(tr * 4 + i) * 65];
    float acc[4][8];
    for (int ch = 0; ch < 2; ch++) {
        __syncthreads();
        for (int e = t * 4; e < 8192; e += 1024) {
            int row = e >> 6, c4 = e & 63, nd = Rbase + row;
            float4 vv = make_float4(0.f,0.f,0.f,0.f);
            if (nd < NN) {
                const float* base = (ch == 0) ? &node[(size_t)nd * 64] : &agg[(size_t)nd * 64];
                vv = *(const float4*)&base[c4];
            }
            float* d = &As[row * 65 + c4];
            d[0]=vv.x; d[1]=vv.y; d[2]=vv.z; d[3]=vv.w;
        }
        __syncthreads();
        if (ch == 0) {
            float4 ba = *(const float4*)&B1s[tc * 8];
            float4 bb = *(const float4*)&B1s[tc * 8 + 4];
            #pragma unroll
            for (int i = 0; i < 4; i++) {
                acc[i][0]=ba.x;acc[i][1]=ba.y;acc[i][2]=ba.z;acc[i][3]=ba.w;
                acc[i][4]=bb.x;acc[i][5]=bb.y;acc[i][6]=bb.z;acc[i][7]=bb.w;
            }
        }
        const float* wp = &W1s[ch * 4096 + tc * 8];
        #pragma unroll 8
        for (int k = 0; k < 64; k++) {
            float4 wa = *(const float4*)&wp[k * 64];
            float4 wb = *(const float4*)&wp[k * 64 + 4];
            #pragma unroll
            for (int i = 0; i < 4; i++) {
                float a = ar[i][k];
                acc[i][0]+=a*wa.x; acc[i][1]+=a*wa.y; acc[i][2]+=a*wa.z; acc[i][3]+=a*wa.w;
                acc[i][4]+=a*wb.x; acc[i][5]+=a*wb.y; acc[i][6]+=a*wb.z; acc[i][7]+=a*wb.w;
            }
        }
    }
    __syncthreads();
    #pragma unroll
    for (int i = 0; i < 4; i++)
        #pragma unroll
        for (int j = 0; j < 8; j++)
            As[(tr * 4 + i) * 65 + tc * 8 + j] = fmaxf(acc[i][j], 0.f);
    __syncthreads();
    float a2[4][8];
    {
        float4 ba = *(const float4*)&B2s[tc * 8];
        float4 bb = *(const float4*)&B2s[tc * 8 + 4];
        #pragma unroll
        for (int i = 0; i < 4; i++) {
            a2[i][0]=ba.x;a2[i][1]=ba.y;a2[i][2]=ba.z;a2[i][3]=ba.w;
            a2[i][4]=bb.x;a2[i][5]=bb.y;a2[i][6]=bb.z;a2[i][7]=bb.w;
        }
    }
    const float* wp2 = &W2s[tc * 8];
    #pragma unroll 8
    for (int k = 0; k < 64; k++) {
        float4 wa = *(const float4*)&wp2[k * 64];
        float4 wb = *(const float4*)&wp2[k * 64 + 4];
        #pragma unroll
        for (int i = 0; i < 4; i++) {
            float a = ar[i][k];
            a2[i][0]+=a*wa.x; a2[i][1]+=a*wa.y; a2[i][2]+=a*wa.z; a2[i][3]+=a*wa.w;
            a2[i][4]+=a*wb.x; a2[i][5]+=a*wb.y; a2[i][6]+=a*wb.z; a2[i][7]+=a*wb.w;
        }
    }
    #pragma unroll
    for (int i = 0; i < 4; i++) {
        int nd = Rbase + tr * 4 + i;
        if (nd < NN) {
            float4 v;
            v.x=a2[i][0]; v.y=a2[i][1]; v.z=a2[i][2]; v.w=a2[i][3];
            *(float4*)&out[(size_t)nd * 64 + tc * 8] = v;
            v.x=a2[i][4]; v.y=a2[i][5]; v.z=a2[i][6]; v.w=a2[i][7];
            *(float4*)&out[(size_t)nd * 64 + tc * 8 + 4] = v;
        }
    }
}

// --------------------------------------------- final edge MLP: 134->128->64->1
__global__ void __launch_bounds__(256) k_final(const float* __restrict__ node,
    const float* __restrict__ ea, const int* __restrict__ ei,
    const float* __restrict__ w1, const float* __restrict__ b1,
    const float* __restrict__ w2, const float* __restrict__ b2,
    const float* __restrict__ w3, const float* __restrict__ b3, float* __restrict__ out) {
    extern __shared__ float sm[];
    float* W1s = sm;
    float* B1s = W1s + 17152;
    float* W2s = B1s + 128;
    float* B2s = W2s + 8192;
    float* w3s = B2s + 64;
    float* b3s = w3s + 64;
    float* As  = b3s + 4;
    float* Hs  = As + 4352;
    float* H2s = Hs + 8448;
    int* srcs = (int*)(H2s + 4352);
    int* dsts = srcs + 64;
    int t = threadIdx.x;
    int ebase = blockIdx.x * 64;
    for (int i = t; i < 17152; i += 256) W1s[i] = w1[i];
    for (int i = t; i < 8192; i += 256) W2s[i] = w2[i];
    if (t < 128) B1s[t] = b1[t];
    if (t < 64) { B2s[t]=b2[t]; w3s[t]=w3[t]; srcs[t]=ei[ebase+t]; dsts[t]=ei[EE+ebase+t]; }
    if (t == 0) b3s[0] = b3[0];
    int tr = t >> 4, tc = t & 15;
    float acc[4][8];
    for (int ch = 0; ch < 2; ch++) {
        __syncthreads();
        for (int e = t * 4; e < 4096; e += 1024) {
            int row = e >> 6, c4 = e & 63;
            const float* base = (ch == 0) ? &node[(size_t)srcs[row] * 64]
                                          : &node[(size_t)dsts[row] * 64];
            *(float4*)&As[row * 68 + c4] = *(const float4*)&base[c4];
        }
        __syncthreads();
        if (ch == 0) {
            #pragma unroll
            for (int i = 0; i < 4; i++)
                #pragma unroll
                for (int j = 0; j < 8; j++) acc[i][j] = B1s[tc * 8 + j];
        }
        for (int k = 0; k < 64; k++) {
            float4 wa = *(const float4*)&W1s[(ch * 64 + k) * 128 + tc * 8];
            float4 wb = *(const float4*)&W1s[(ch * 64 + k) * 128 + tc * 8 + 4];
            #pragma unroll
            for (int i = 0; i < 4; i++) {
                float a = As[(tr * 4 + i) * 68 + k];
                acc[i][0]+=a*wa.x; acc[i][1]+=a*wa.y; acc[i][2]+=a*wa.z; acc[i][3]+=a*wa.w;
                acc[i][4]+=a*wb.x; acc[i][5]+=a*wb.y; acc[i][6]+=a*wb.z; acc[i][7]+=a*wb.w;
            }
        }
    }
    __syncthreads();
    for (int e = t; e < 384; e += 256) {
        int row = e / 6, k = e - row * 6;
        As[row * 8 + k] = ea[(size_t)(ebase + row) * 6 + k];
    }
    __syncthreads();
    for (int k = 0; k < 6; k++) {
        float4 wa = *(const float4*)&W1s[(128 + k) * 128 + tc * 8];
        float4 wb = *(const float4*)&W1s[(128 + k) * 128 + tc * 8 + 4];
        #pragma unroll
        for (int i = 0; i < 4; i++) {
            float a = As[(tr * 4 + i) * 8 + k];
            acc[i][0]+=a*wa.x; acc[i][1]+=a*wa.y; acc[i][2]+=a*wa.z; acc[i][3]+=a*wa.w;
            acc[i][4]+=a*wb.x; acc[i][5]+=a*wb.y; acc[i][6]+=a*wb.z; acc[i][7]+=a*wb.w;
        }
    }
    #pragma unroll
    for (int i = 0; i < 4; i++)
        #pragma unroll
        for (int j = 0; j < 8; j++)
            Hs[(tr * 4 + i) * 132 + tc * 8 + j] = fmaxf(acc[i][j], 0.f);
    __syncthreads();
    float a2[4][4];
    #pragma unroll
    for (int i = 0; i < 4; i++)
        #pragma unroll
        for (int j = 0; j < 4; j++) a2[i][j] = B2s[tc * 4 + j];
    for (int k = 0; k < 128; k++) {
        float4 w4 = *(const float4*)&W2s[k * 64 + tc * 4];
        #pragma unroll
        for (int i = 0; i < 4; i++) {
            float a = Hs[(tr * 4 + i) * 132 + k];
            a2[i][0] += a*w4.x; a2[i][1] += a*w4.y; a2[i][2] += a*w4.z; a2[i][3] += a*w4.w;
        }
    }
    #pragma unroll
    for (int i = 0; i < 4; i++)
        #pragma unroll
        for (int j = 0; j < 4; j++)
            H2s[(tr * 4 + i) * 68 + tc * 4 + j] = fmaxf(a2[i][j], 0.f);
    __syncthreads();
    if (t < 64) {
        float s = b3s[0];
        for (int c = 0; c < 64; c++) s += H2s[t * 68 + c] * w3s[c];
        out[ebase + t] = s;
    }
}

// ============================================================================
extern "C" void kernel_launch(void* const* d_in, const int* in_sizes, int n_in,
                              void* d_out, int out_size) {
    const float *x=0,*ea=0,*crop=0,*cw0=0,*cb0=0,*cw=0,*cb=0,*nu_w=0,*nu_b=0,*nu_g=0,*nu_be=0,
        *eu_w=0,*eu_b=0,*eu_g=0,*eu_be=0,*ie_w1=0,*ie_b1=0,*ie_w2=0,*ie_b2=0,
        *in_w1=0,*in_b1=0,*in_w2=0,*in_b2=0,*em_w1=0,*em_b1=0,*em_w2=0,*em_b2=0,*em_w3=0,*em_b3=0;
    const int* ei = 0;
    int c64 = 0, c256 = 0, c16k = 0;
    for (int i = 0; i < n_in; i++) {
        const float* p = (const float*)d_in[i];
        switch (in_sizes[i]) {
            case 320000: x = p; break;
            case 640000: ei = (const int*)p; break;
            case 1920000: ea = p; break;
            case 122880000: crop = p; break;
            case 768: cw0 = p; break;
            case 81920: cw = p; break;
            case 320: cb = p; break;
            case 6144: nu_w = p; break;
            case 384: eu_w = p; break;
            case 49152: ie_w1 = p; break;
            case 32768: in_w1 = p; break;
            case 17152: em_w1 = p; break;
            case 128: em_b1 = p; break;
            case 8192: em_w2 = p; break;
            case 1: em_b3 = p; break;
            case 16384: if (c16k++ == 0) ie_w2 = p; else in_w2 = p; break;
            case 256:
                if (c256 == 0) ie_b1 = p; else if (c256 == 1) ie_b2 = p;
                else if (c256 == 2) in_b1 = p; else in_b2 = p;
                c256++; break;
            case 64: {
                const float** slots[9] = {&cb0,&nu_b,&nu_g,&nu_be,&eu_b,&eu_g,&eu_be,&em_b2,&em_w3};
                if (c64 < 9) *slots[c64] = p;
                c64++; break;
            }
            default: break;
        }
    }
    float *b0, *b1, *cf, *nA, *nB, *agg, *edg;
    cudaGetSymbolAddress((void**)&b0, g_b0);
    cudaGetSymbolAddress((void**)&b1, g_b1);
    cudaGetSymbolAddress((void**)&cf, g_cf);
    cudaGetSymbolAddress((void**)&nA, g_nA);
    cudaGetSymbolAddress((void**)&nB, g_nB);
    cudaGetSymbolAddress((void**)&agg, g_agg);
    cudaGetSymbolAddress((void**)&edg, g_edge);

    const int SM_CNN = (6144 + 768 + 64 + 64 + 8704 * 2) * 4;
    const int SM_MSG = (6144 + 128 + 8704 * 2) * 4 + 256 * 4;
    const int SM_NU  = (6144 + 64 * 5 + 6400 + 4352 + 64) * 4;
    const int SM_NM  = (8192 + 4096 + 128 + 8320) * 4;
    const int SM_FIN = (17152 + 128 + 8192 + 64 + 64 + 4 + 4352 + 8448 + 4352) * 4 + 512;
    cudaFuncSetAttribute(k_cnn,     cudaFuncAttributeMaxDynamicSharedMemorySize, SM_CNN);
    cudaFuncSetAttribute(k_msg,     cudaFuncAttributeMaxDynamicSharedMemorySize, SM_MSG);
    cudaFuncSetAttribute(k_nodeup,  cudaFuncAttributeMaxDynamicSharedMemorySize, SM_NU);
    cudaFuncSetAttribute(k_nodemlp, cudaFuncAttributeMaxDynamicSharedMemorySize, SM_NM);
    cudaFuncSetAttribute(k_final,   cudaFuncAttributeMaxDynamicSharedMemorySize, SM_FIN);

    // CNN stack (layer 0 fuses conv0 inline)
    k_cnn<<<20000, 256, SM_CNN>>>(crop, crop, b1, cw0, cb0, cw,         cb,       4, NN*256, 1);
    k_cnn<<<5000,  256, SM_CNN>>>(crop, b1,   b0, cw0, cb0, cw + 16384, cb + 64,  3, NN*64,  0);
    k_cnn<<<1250,  256, SM_CNN>>>(crop, b0,   b1, cw0, cb0, cw + 32768, cb + 128, 2, NN*16,  0);
    k_cnn<<<313,   256, SM_CNN>>>(crop, b1,   b0, cw0, cb0, cw + 49152, cb + 192, 1, NN*4,   0);
    k_cnn<<<79,    256, SM_CNN>>>(crop, b0,   cf, cw0, cb0, cw + 65536, cb + 256, 0, NN,     0);
    // encoders
    k_nodeup<<<157, 256, SM_NU>>>(x, cf, nu_w, nu_b, nu_g, nu_be, nA);
    k_edgeup<<<5000, 256>>>(ea, eu_w, eu_b, eu_g, eu_be, edg);
    // 4 interaction layers
    float* cur = nA; float* nxt = nB;
    for (int l = 0; l < 4; l++) {
        cudaMemsetAsync(agg, 0, (size_t)NN * 64 * sizeof(float), 0);
        k_msg<<<2500, 256, SM_MSG>>>(cur, edg, ei, ie_w1 + l * 12288, ie_b1 + l * 64,
                                     ie_w2 + l * 4096, ie_b2 + l * 64, agg);
        k_nodemlp<<<79, 256, SM_NM>>>(cur, agg, in_w1 + l * 8192, in_b1 + l * 64,
                                      in_w2 + l * 4096, in_b2 + l * 64, nxt);
        float* tmp = cur; cur = nxt; nxt = tmp;
    }
    // final edge MLP
    k_final<<<5000, 256, SM_FIN>>>(cur, ea, ei, em_w1, em_b1, em_w2, em_b2,
                                   em_w3, em_b3, (float*)d_out);
}

// round 8
// speedup vs baseline: 2.7022x; 1.2607x over previous
#include <cuda_runtime.h>
#include <cstdint>

#define NN 10000
#define EE 320000

__device__ float g_b1[(size_t)NN*256*64];
__device__ float g_b0[(size_t)NN*64*64];
__device__ float g_cf[NN*64];
__device__ float g_nA[NN*64];
__device__ float g_nB[NN*64];
__device__ float g_agg[NN*64];
__device__ float g_edge[(size_t)EE*64];

__device__ __forceinline__ unsigned f2tf(float x){unsigned r;asm("cvt.rna.tf32.f32 %0,%1;":"=r"(r):"f"(x));return r;}
__device__ __forceinline__ void mma8(float* c,unsigned a0,unsigned a1,unsigned a2,unsigned a3,unsigned b0,unsigned b1){
  asm("mma.sync.aligned.m16n8k8.row.col.f32.tf32.tf32.f32 {%0,%1,%2,%3},{%4,%5,%6,%7},{%8,%9},{%0,%1,%2,%3};"
      :"+f"(c[0]),"+f"(c[1]),"+f"(c[2]),"+f"(c[3]):"r"(a0),"r"(a1),"r"(a2),"r"(a3),"r"(b0),"r"(b1));}
__device__ __forceinline__ void cpa16(uint32_t d,const void* s,int sz){
  asm volatile("cp.async.cg.shared.global [%0],[%1],16,%2;"::"r"(d),"l"(s),"r"(sz));}
__device__ __forceinline__ void cpacommit(){asm volatile("cp.async.commit_group;");}
template<int N> __device__ __forceinline__ void cpawait(){asm volatile("cp.async.wait_group %0;"::"n"(N));}

// raw-A sweep: split hi/lo in registers. Wl holds 2 tf32 words per slot (no decode).
__device__ __forceinline__ void mma_sweep(const float* A,const unsigned* Wh,const unsigned* Wl,
    int KT,float C[][4],int ab,int stride){
  const int lane=threadIdx.x&31;
  for(int kt=0;kt<KT;kt++){
    const float* ap=A+ab+kt*8;
    float v0=ap[0],v1=ap[8*stride],v2=ap[4],v3=ap[8*stride+4];
    unsigned a0=f2tf(v0),a1=f2tf(v1),a2=f2tf(v2),a3=f2tf(v3);
    unsigned l0=__float_as_uint(v0-__uint_as_float(a0)),l1=__float_as_uint(v1-__uint_as_float(a1));
    unsigned l2=__float_as_uint(v2-__uint_as_float(a2)),l3=__float_as_uint(v3-__uint_as_float(a3));
    #pragma unroll
    for(int nt=0;nt<8;nt++){
      int s=(kt*8+nt)*32+lane;
      uint2 bh=*(const uint2*)(Wh+2*(size_t)s);
      uint2 bl=*(const uint2*)(Wl+2*(size_t)s);
      mma8(C[nt],a0,a1,a2,a3,bh.x,bh.y);
      mma8(C[nt],a0,a1,a2,a3,bl.x,bl.y);
      mma8(C[nt],l0,l1,l2,l3,bh.x,bh.y);
    }
  }
}

#define STAGE_W(Wh,Wl,KT,GET) do{ for(int s_=threadIdx.x;s_<(KT)*256;s_+=256){ \
  int lane_=s_&31,nt_=(s_>>5)&7,kt_=s_>>8; int nn=nt_*8+(lane_>>2),kk=kt_*8+(lane_&3); \
  float w0v=GET(kk,nn),w1v=GET((kk+4),nn); unsigned h0=f2tf(w0v),h1=f2tf(w1v); \
  (Wh)[2*s_]=h0;(Wh)[2*s_+1]=h1; \
  (Wl)[2*s_]=f2tf(w0v-__uint_as_float(h0));(Wl)[2*s_+1]=f2tf(w1v-__uint_as_float(h1));} }while(0)

// ===== unified CNN layer (mma, cp.async pipelined); L0: conv0 ALSO via mma ===
__global__ void __launch_bounds__(256,2) k_cnn(const float* __restrict__ crop,
    const float* __restrict__ in,float* __restrict__ out,
    const float* __restrict__ w0,const float* __restrict__ b0c,
    const float* __restrict__ w,const float* __restrict__ b,int so_bits,int M,int L0){
  extern __shared__ float sm[];
  unsigned* Wh=(unsigned*)sm;           // 4096
  unsigned* Wl=Wh+4096;                 // 4096
  unsigned* W0h=Wl+4096;                // 1024
  unsigned* W0l=W0h+1024;               // 1024
  float* b0s=(float*)(W0l+1024);        // 64
  float* bs=b0s+64;                     // 64
  float* A0=bs+64;                      // 8704
  float* A1=A0+8704;                    // 8704 (!L0: double buffer; L0: crop window + Ap)
  float* Ap=A1+6144;                    // L0 only: 128*20 = 2560 (inside A1 tail)
  const int t=threadIdx.x,lane=t&31,wid=t>>5;
  const int Rbase=blockIdx.x*128;
  const int S_out=1<<so_bits,S_in=S_out<<1,so2=so_bits*2;
  const int half=(Rbase>>7)&1;
  if(L0){
    #define GETW0(kk,nn) (((kk)<12)?w0[(nn)*12+(kk)]:0.f)
    STAGE_W(W0h,W0l,2,GETW0);
    #undef GETW0
    if(t<64)b0s[t]=b0c[t];
    int n=Rbase>>8;
    for(int i=t*4;i<6144;i+=1024){
      int c=i>>11,r=i&2047,y=r>>6,xx=r&63;
      *(float4*)&A1[i]=*(const float4*)&crop[(((size_t)n*3+c)*64+half*32+y)*64+xx];
    }
  }
  if(t<64)bs[t]=b[t];
  const int g=lane>>2,tq=lane&3,mrow=wid*16+g;
  const int ab68=mrow*68+tq,ab20=mrow*20+tq;
  auto issueA=[&](int pp,float* buf){
    int ky_=pp>>1,kx_=pp&1;
    uint32_t db=(uint32_t)__cvta_generic_to_shared(buf);
    #pragma unroll
    for(int k_=0;k_<8;k_++){
      int idx=t+k_*256,row=idx>>4,c4=(idx&15)*4,R=Rbase+row;
      const float* s_=in; int sz_=0;
      if(R<M){int n_=R>>so2,sp_=R&(S_out*S_out-1),oy_=sp_>>so_bits,ox_=sp_&(S_out-1);
        s_=&in[(((size_t)n_*S_in+2*oy_+ky_)*S_in+2*ox_+kx_)*64+c4];sz_=16;}
      cpa16(db+(row*68+c4)*4,s_,sz_);
    }
  };
  float C[8][4];
  #pragma unroll
  for(int i=0;i<8;i++){C[i][0]=0;C[i][1]=0;C[i][2]=0;C[i][3]=0;}
  if(!L0){issueA(0,A0);cpacommit();}
  for(int p=0;p<4;p++){
    const int ky=p>>1,kx=p&1;
    if(!L0&&p<3){issueA(p+1,(p&1)?A0:A1);cpacommit();}
    #define GETC(kk,nn) (w[(nn)*256+(kk)*4+p])
    STAGE_W(Wh,Wl,8,GETC);
    #undef GETC
    if(L0){
      // build A-patch tile [128 x 16] (K=12 padded) from crop window
      for(int i=t;i<2048;i+=256){
        int row=i>>4,col=i&15; float v=0.f;
        if(col<12){
          int sp=(Rbase+row)&255,oy=sp>>4,ox=sp&15;
          int oyl=oy-half*8;
          int c=col>>2,q=col&3;
          v=A1[c*2048+(4*oyl+2*ky+(q>>1))*64+4*ox+2*kx+(q&1)];
        }
        Ap[row*20+col]=v;
      }
    } else {
      if(p<3)cpawait<1>();else cpawait<0>();
    }
    __syncthreads();
    if(L0){
      float C0[8][4];
      #pragma unroll
      for(int i=0;i<8;i++){C0[i][0]=0;C0[i][1]=0;C0[i][2]=0;C0[i][3]=0;}
      mma_sweep(Ap,W0h,W0l,2,C0,ab20,20);
      #pragma unroll
      for(int nt=0;nt<8;nt++){
        int col=nt*8+tq*2;
        A0[mrow*68+col]=fmaxf(C0[nt][0]+b0s[col],0.f);
        A0[mrow*68+col+1]=fmaxf(C0[nt][1]+b0s[col+1],0.f);
        A0[(mrow+8)*68+col]=fmaxf(C0[nt][2]+b0s[col],0.f);
        A0[(mrow+8)*68+col+1]=fmaxf(C0[nt][3]+b0s[col+1],0.f);
      }
      __syncthreads();
    }
    mma_sweep(L0?A0:((p&1)?A1:A0),Wh,Wl,8,C,ab68,68);
    __syncthreads();
  }
  #pragma unroll
  for(int nt=0;nt<8;nt++){
    int col=nt*8+tq*2,r0=Rbase+mrow,r1=r0+8;
    if(r0<M){float2 v;v.x=fmaxf(C[nt][0]+bs[col],0.f);v.y=fmaxf(C[nt][1]+bs[col+1],0.f);
      *(float2*)&out[(size_t)r0*64+col]=v;}
    if(r1<M){float2 v;v.x=fmaxf(C[nt][2]+bs[col],0.f);v.y=fmaxf(C[nt][3]+bs[col+1],0.f);
      *(float2*)&out[(size_t)r1*64+col]=v;}
  }
}

// ====== msg MLP (192->64->64) + scatter-add, cp.async pipelined =============
__global__ void __launch_bounds__(256,2) k_msg(const float* __restrict__ node,
    const float* __restrict__ edge,const int* __restrict__ ei,
    const float* __restrict__ w1,const float* __restrict__ b1,
    const float* __restrict__ w2,const float* __restrict__ b2,float* __restrict__ agg){
  extern __shared__ float sm[];
  unsigned* Wh=(unsigned*)sm; unsigned* Wl=Wh+4096;
  float* b1s=(float*)(Wl+4096); float* b2s=b1s+64;
  float* A0=b2s+64; float* A1=A0+8704;
  int* srcs=(int*)(A1+8704); int* dsts=srcs+128;
  const int t=threadIdx.x,lane=t&31,wid=t>>5;
  const int ebase=blockIdx.x*128;
  if(t<64){b1s[t]=b1[t];b2s[t]=b2[t];}
  if(t<128){srcs[t]=ei[ebase+t];dsts[t]=ei[EE+ebase+t];}
  const int g=lane>>2,tq=lane&3,mrow=wid*16+g,ab=mrow*68+tq;
  __syncthreads();
  auto issueM=[&](int ch,float* buf){
    uint32_t db=(uint32_t)__cvta_generic_to_shared(buf);
    #pragma unroll
    for(int k_=0;k_<8;k_++){
      int idx=t+k_*256,row=idx>>4,c4=(idx&15)*4;
      const float* s_=(ch==0)?&node[(size_t)dsts[row]*64+c4]:(ch==1)?&node[(size_t)srcs[row]*64+c4]
                     :&edge[(size_t)(ebase+row)*64+c4];
      cpa16(db+(row*68+c4)*4,s_,16);
    }
  };
  float C1[8][4];
  #pragma unroll
  for(int i=0;i<8;i++){C1[i][0]=0;C1[i][1]=0;C1[i][2]=0;C1[i][3]=0;}
  issueM(0,A0);cpacommit();
  for(int ch=0;ch<3;ch++){
    if(ch<2){issueM(ch+1,(ch&1)?A0:A1);cpacommit();}
    #define GETM(kk,nn) (w1[((ch)*64+(kk))*64+(nn)])
    STAGE_W(Wh,Wl,8,GETM);
    #undef GETM
    if(ch<2)cpawait<1>();else cpawait<0>();
    __syncthreads();
    mma_sweep((ch&1)?A1:A0,Wh,Wl,8,C1,ab,68);
    __syncthreads();
  }
  #pragma unroll
  for(int nt=0;nt<8;nt++){
    int col=nt*8+tq*2;
    A0[mrow*68+col]=fmaxf(C1[nt][0]+b1s[col],0.f);
    A0[mrow*68+col+1]=fmaxf(C1[nt][1]+b1s[col+1],0.f);
    A0[(mrow+8)*68+col]=fmaxf(C1[nt][2]+b1s[col],0.f);
    A0[(mrow+8)*68+col+1]=fmaxf(C1[nt][3]+b1s[col+1],0.f);
  }
  #define GETM2(kk,nn) (w2[(kk)*64+(nn)])
  STAGE_W(Wh,Wl,8,GETM2);
  #undef GETM2
  __syncthreads();
  float C2[8][4];
  #pragma unroll
  for(int i=0;i<8;i++){C2[i][0]=0;C2[i][1]=0;C2[i][2]=0;C2[i][3]=0;}
  mma_sweep(A0,Wh,Wl,8,C2,ab,68);
  const int d0=dsts[mrow],d1=dsts[mrow+8];
  #pragma unroll
  for(int nt=0;nt<8;nt++){
    int col=nt*8+tq*2;
    atomicAdd(&agg[(size_t)d0*64+col],C2[nt][0]+b2s[col]);
    atomicAdd(&agg[(size_t)d0*64+col+1],C2[nt][1]+b2s[col+1]);
    atomicAdd(&agg[(size_t)d1*64+col],C2[nt][2]+b2s[col]);
    atomicAdd(&agg[(size_t)d1*64+col+1],C2[nt][3]+b2s[col+1]);
  }
}

// --------------------------------------------- node_update: [x|cf]@W + LN
__global__ void __launch_bounds__(256) k_nodeup(const float* __restrict__ x,
    const float* __restrict__ cf, const float* __restrict__ w, const float* __restrict__ b,
    const float* __restrict__ g, const float* __restrict__ be, float* __restrict__ out) {
    extern __shared__ float sm[];
    float* Ws = sm;
    float* Bs = Ws + 6144; float* Gs = Bs + 64; float* BEs = Gs + 64;
    float* mu = BEs + 64; float* rs = mu + 64;
    float* As = rs + 64; float* Hs = As + 6400;
    int t = threadIdx.x;
    int Rbase = blockIdx.x * 64;
    for (int i = t; i < 6144; i += 256) Ws[i] = w[i];
    if (t < 64) { Bs[t]=b[t]; Gs[t]=g[t]; BEs[t]=be[t]; }
    for (int e = t; e < 2048; e += 256) {
        int row = e >> 5, c = e & 31, nd = Rbase + row;
        As[row * 100 + c] = (nd < NN) ? x[nd * 32 + c] : 0.f;
    }
    for (int e = t; e < 4096; e += 256) {
        int row = e >> 6, c = e & 63, nd = Rbase + row;
        As[row * 100 + 32 + c] = (nd < NN) ? cf[nd * 64 + c] : 0.f;
    }
    __syncthreads();
    int tr = t >> 4, tc = t & 15;
    float acc[4][4];
    float4 b4 = *(const float4*)&Bs[tc * 4];
    #pragma unroll
    for (int i = 0; i < 4; i++) { acc[i][0]=b4.x; acc[i][1]=b4.y; acc[i][2]=b4.z; acc[i][3]=b4.w; }
    for (int k = 0; k < 96; k++) {
        float4 w4 = *(const float4*)&Ws[k * 64 + tc * 4];
        #pragma unroll
        for (int i = 0; i < 4; i++) {
            float a = As[(tr * 4 + i) * 100 + k];
            acc[i][0] += a*w4.x; acc[i][1] += a*w4.y; acc[i][2] += a*w4.z; acc[i][3] += a*w4.w;
        }
    }
    #pragma unroll
    for (int i = 0; i < 4; i++) {
        float4 r; r.x=fmaxf(acc[i][0],0.f); r.y=fmaxf(acc[i][1],0.f);
        r.z=fmaxf(acc[i][2],0.f); r.w=fmaxf(acc[i][3],0.f);
        *(float4*)&Hs[(tr * 4 + i) * 68 + tc * 4] = r;
    }
    __syncthreads();
    if (t < 64) {
        float s = 0.f, sq = 0.f;
        for (int c = 0; c < 64; c++) { float v = Hs[t * 68 + c]; s += v; sq += v * v; }
        float m = s * (1.f / 64.f);
        mu[t] = m; rs[t] = rsqrtf(sq * (1.f / 64.f) - m * m + 1e-5f);
    }
    __syncthreads();
    for (int i = t; i < 4096; i += 256) {
        int r = i >> 6, c = i & 63, nd = Rbase + r;
        if (nd < NN) out[nd * 64 + c] = (Hs[r * 68 + c] - mu[r]) * rs[r] * Gs[c] + BEs[c];
    }
}

// --------------------------------------------- edge_update: ea@W + LN
__global__ void __launch_bounds__(256) k_edgeup(const float* __restrict__ ea,
    const float* __restrict__ w, const float* __restrict__ b,
    const float* __restrict__ g, const float* __restrict__ be, float* __restrict__ out) {
    __shared__ float Ws[384], Bs[64], Gs[64], BEs[64], Aa[64][8], Hs[64][68], mu[64], rs[64];
    int t = threadIdx.x;
    int ebase = blockIdx.x * 64;
    for (int i = t; i < 384; i += 256) Ws[i] = w[i];
    if (t < 64) { Bs[t]=b[t]; Gs[t]=g[t]; BEs[t]=be[t]; }
    for (int e = t; e < 384; e += 256) {
        int row = e / 6, k = e - row * 6;
        Aa[row][k] = ea[(size_t)(ebase + row) * 6 + k];
    }
    __syncthreads();
    int r = t >> 2, cg = (t & 3) * 16;
    float a0=Aa[r][0],a1=Aa[r][1],a2=Aa[r][2],a3=Aa[r][3],a4=Aa[r][4],a5=Aa[r][5];
    #pragma unroll
    for (int j = 0; j < 16; j++) {
        int c = cg + j;
        float h = Bs[c] + a0*Ws[c] + a1*Ws[64+c] + a2*Ws[128+c] + a3*Ws[192+c] + a4*Ws[256+c] + a5*Ws[320+c];
        Hs[r][c] = fmaxf(h, 0.f);
    }
    __syncthreads();
    if (t < 64) {
        float s = 0.f, sq = 0.f;
        for (int c = 0; c < 64; c++) { float v = Hs[t][c]; s += v; sq += v * v; }
        float m = s * (1.f / 64.f);
        mu[t] = m; rs[t] = rsqrtf(sq * (1.f / 64.f) - m * m + 1e-5f);
    }
    __syncthreads();
    for (int i = t; i < 4096; i += 256) {
        int rr = i >> 6, c = i & 63;
        out[(size_t)ebase * 64 + i] = (Hs[rr][c] - mu[rr]) * rs[rr] * Gs[c] + BEs[c];
    }
}

// ========= node MLP: [node|agg] 2-layer, 128 nodes/block, 4x8 per thread =====
__global__ void __launch_bounds__(256, 2) k_nodemlp(const float* __restrict__ node,
    const float* __restrict__ agg, const float* __restrict__ w1, const float* __restrict__ b1,
    const float* __restrict__ w2, const float* __restrict__ b2, float* __restrict__ out) {
    extern __shared__ float sm[];
    float* W1s = sm;
    float* W2s = W1s + 8192;
    float* B1s = W2s + 4096; float* B2s = B1s + 64;
    float* As = B2s + 64;
    const int t = threadIdx.x;
    const int Rbase = blockIdx.x * 128;
    for (int i = t; i < 8192; i += 256) W1s[i] = w1[i];
    for (int i = t; i < 4096; i += 256) W2s[i] = w2[i];
    if (t < 64) { B1s[t]=b1[t]; B2s[t]=b2[t]; }
    const int tr = t >> 3, tc = t & 7;
    const float* ar[4];
    #pragma unroll
    for (int i = 0; i < 4; i++) ar[i] = &As[(tr * 4 + i) * 65];
    float acc[4][8];
    for (int ch = 0; ch < 2; ch++) {
        __syncthreads();
        for (int e = t * 4; e < 8192; e += 1024) {
            int row = e >> 6, c4 = e & 63, nd = Rbase + row;
            float4 vv = make_float4(0.f,0.f,0.f,0.f);
            if (nd < NN) {
                const float* base = (ch == 0) ? &node[(size_t)nd * 64] : &agg[(size_t)nd * 64];
                vv = *(const float4*)&base[c4];
            }
            float* d = &As[row * 65 + c4];
            d[0]=vv.x; d[1]=vv.y; d[2]=vv.z; d[3]=vv.w;
        }
        __syncthreads();
        if (ch == 0) {
            float4 ba = *(const float4*)&B1s[tc * 8];
            float4 bb = *(const float4*)&B1s[tc * 8 + 4];
            #pragma unroll
            for (int i = 0; i < 4; i++) {
                acc[i][0]=ba.x;acc[i][1]=ba.y;acc[i][2]=ba.z;acc[i][3]=ba.w;
                acc[i][4]=bb.x;acc[i][5]=bb.y;acc[i][6]=bb.z;acc[i][7]=bb.w;
            }
        }
        const float* wp = &W1s[ch * 4096 + tc * 8];
        #pragma unroll 8
        for (int k = 0; k < 64; k++) {
            float4 wa = *(const float4*)&wp[k * 64];
            float4 wb = *(const float4*)&wp[k * 64 + 4];
            #pragma unroll
            for (int i = 0; i < 4; i++) {
                float a = ar[i][k];
                acc[i][0]+=a*wa.x; acc[i][1]+=a*wa.y; acc[i][2]+=a*wa.z; acc[i][3]+=a*wa.w;
                acc[i][4]+=a*wb.x; acc[i][5]+=a*wb.y; acc[i][6]+=a*wb.z; acc[i][7]+=a*wb.w;
            }
        }
    }
    __syncthreads();
    #pragma unroll
    for (int i = 0; i < 4; i++)
        #pragma unroll
        for (int j = 0; j < 8; j++)
            As[(tr * 4 + i) * 65 + tc * 8 + j] = fmaxf(acc[i][j], 0.f);
    __syncthreads();
    float a2[4][8];
    {
        float4 ba = *(const float4*)&B2s[tc * 8];
        float4 bb = *(const float4*)&B2s[tc * 8 + 4];
        #pragma unroll
        for (int i = 0; i < 4; i++) {
            a2[i][0]=ba.x;a2[i][1]=ba.y;a2[i][2]=ba.z;a2[i][3]=ba.w;
            a2[i][4]=bb.x;a2[i][5]=bb.y;a2[i][6]=bb.z;a2[i][7]=bb.w;
        }
    }
    const float* wp2 = &W2s[tc * 8];
    #pragma unroll 8
    for (int k = 0; k < 64; k++) {
        float4 wa = *(const float4*)&wp2[k * 64];
        float4 wb = *(const float4*)&wp2[k * 64 + 4];
        #pragma unroll
        for (int i = 0; i < 4; i++) {
            float a = ar[i][k];
            a2[i][0]+=a*wa.x; a2[i][1]+=a*wa.y; a2[i][2]+=a*wa.z; a2[i][3]+=a*wa.w;
            a2[i][4]+=a*wb.x; a2[i][5]+=a*wb.y; a2[i][6]+=a*wb.z; a2[i][7]+=a*wb.w;
        }
    }
    #pragma unroll
    for (int i = 0; i < 4; i++) {
        int nd = Rbase + tr * 4 + i;
        if (nd < NN) {
            float4 v;
            v.x=a2[i][0]; v.y=a2[i][1]; v.z=a2[i][2]; v.w=a2[i][3];
            *(float4*)&out[(size_t)nd * 64 + tc * 8] = v;
            v.x=a2[i][4]; v.y=a2[i][5]; v.z=a2[i][6]; v.w=a2[i][7];
            *(float4*)&out[(size_t)nd * 64 + tc * 8 + 4] = v;
        }
    }
}

// --------------------------------------------- final edge MLP: 134->128->64->1
__global__ void __launch_bounds__(256) k_final(const float* __restrict__ node,
    const float* __restrict__ ea, const int* __restrict__ ei,
    const float* __restrict__ w1, const float* __restrict__ b1,
    const float* __restrict__ w2, const float* __restrict__ b2,
    const float* __restrict__ w3, const float* __restrict__ b3, float* __restrict__ out) {
    extern __shared__ float sm[];
    float* W1s = sm;
    float* B1s = W1s + 17152;
    float* W2s = B1s + 128;
    float* B2s = W2s + 8192;
    float* w3s = B2s + 64;
    float* b3s = w3s + 64;
    float* As  = b3s + 4;
    float* Hs  = As + 4352;
    float* H2s = Hs + 8448;
    int* srcs = (int*)(H2s + 4352);
    int* dsts = srcs + 64;
    int t = threadIdx.x;
    int ebase = blockIdx.x * 64;
    for (int i = t; i < 17152; i += 256) W1s[i] = w1[i];
    for (int i = t; i < 8192; i += 256) W2s[i] = w2[i];
    if (t < 128) B1s[t] = b1[t];
    if (t < 64) { B2s[t]=b2[t]; w3s[t]=w3[t]; srcs[t]=ei[ebase+t]; dsts[t]=ei[EE+ebase+t]; }
    if (t == 0) b3s[0] = b3[0];
    int tr = t >> 4, tc = t & 15;
    float acc[4][8];
    for (int ch = 0; ch < 2; ch++) {
        __syncthreads();
        for (int e = t * 4; e < 4096; e += 1024) {
            int row = e >> 6, c4 = e & 63;
            const float* base = (ch == 0) ? &node[(size_t)srcs[row] * 64]
                                          : &node[(size_t)dsts[row] * 64];
            *(float4*)&As[row * 68 + c4] = *(const float4*)&base[c4];
        }
        __syncthreads();
        if (ch == 0) {
            #pragma unroll
            for (int i = 0; i < 4; i++)
                #pragma unroll
                for (int j = 0; j < 8; j++) acc[i][j] = B1s[tc * 8 + j];
        }
        for (int k = 0; k < 64; k++) {
            float4 wa = *(const float4*)&W1s[(ch * 64 + k) * 128 + tc * 8];
            float4 wb = *(const float4*)&W1s[(ch * 64 + k) * 128 + tc * 8 + 4];
            #pragma unroll
            for (int i = 0; i < 4; i++) {
                float a = As[(tr * 4 + i) * 68 + k];
                acc[i][0]+=a*wa.x; acc[i][1]+=a*wa.y; acc[i][2]+=a*wa.z; acc[i][3]+=a*wa.w;
                acc[i][4]+=a*wb.x; acc[i][5]+=a*wb.y; acc[i][6]+=a*wb.z; acc[i][7]+=a*wb.w;
            }
        }
    }
    __syncthreads();
    for (int e = t; e < 384; e += 256) {
        int row = e / 6, k = e - row * 6;
        As[row * 8 + k] = ea[(size_t)(ebase + row) * 6 + k];
    }
    __syncthreads();
    for (int k = 0; k < 6; k++) {
        float4 wa = *(const float4*)&W1s[(128 + k) * 128 + tc * 8];
        float4 wb = *(const float4*)&W1s[(128 + k) * 128 + tc * 8 + 4];
        #pragma unroll
        for (int i = 0; i < 4; i++) {
            float a = As[(tr * 4 + i) * 8 + k];
            acc[i][0]+=a*wa.x; acc[i][1]+=a*wa.y; acc[i][2]+=a*wa.z; acc[i][3]+=a*wa.w;
            acc[i][4]+=a*wb.x; acc[i][5]+=a*wb.y; acc[i][6]+=a*wb.z; acc[i][7]+=a*wb.w;
        }
    }
    #pragma unroll
    for (int i = 0; i < 4; i++)
        #pragma unroll
        for (int j = 0; j < 8; j++)
            Hs[(tr * 4 + i) * 132 + tc * 8 + j] = fmaxf(acc[i][j], 0.f);
    __syncthreads();
    float a2[4][4];
    #pragma unroll
    for (int i = 0; i < 4; i++)
        #pragma unroll
        for (int j = 0; j < 4; j++) a2[i][j] = B2s[tc * 4 + j];
    for (int k = 0; k < 128; k++) {
        float4 w4 = *(const float4*)&W2s[k * 64 + tc * 4];
        #pragma unroll
        for (int i = 0; i < 4; i++) {
            float a = Hs[(tr * 4 + i) * 132 + k];
            a2[i][0] += a*w4.x; a2[i][1] += a*w4.y; a2[i][2] += a*w4.z; a2[i][3] += a*w4.w;
        }
    }
    #pragma unroll
    for (int i = 0; i < 4; i++)
        #pragma unroll
        for (int j = 0; j < 4; j++)
            H2s[(tr * 4 + i) * 68 + tc * 4 + j] = fmaxf(a2[i][j], 0.f);
    __syncthreads();
    if (t < 64) {
        float s = b3s[0];
        for (int c = 0; c < 64; c++) s += H2s[t * 68 + c] * w3s[c];
        out[ebase + t] = s;
    }
}

// ============================================================================
extern "C" void kernel_launch(void* const* d_in, const int* in_sizes, int n_in,
                              void* d_out, int out_size) {
    const float *x=0,*ea=0,*crop=0,*cw0=0,*cb0=0,*cw=0,*cb=0,*nu_w=0,*nu_b=0,*nu_g=0,*nu_be=0,
        *eu_w=0,*eu_b=0,*eu_g=0,*eu_be=0,*ie_w1=0,*ie_b1=0,*ie_w2=0,*ie_b2=0,
        *in_w1=0,*in_b1=0,*in_w2=0,*in_b2=0,*em_w1=0,*em_b1=0,*em_w2=0,*em_b2=0,*em_w3=0,*em_b3=0;
    const int* ei = 0;
    int c64 = 0, c256 = 0, c16k = 0;
    for (int i = 0; i < n_in; i++) {
        const float* p = (const float*)d_in[i];
        switch (in_sizes[i]) {
            case 320000: x = p; break;
            case 640000: ei = (const int*)p; break;
            case 1920000: ea = p; break;
            case 122880000: crop = p; break;
            case 768: cw0 = p; break;
            case 81920: cw = p; break;
            case 320: cb = p; break;
            case 6144: nu_w = p; break;
            case 384: eu_w = p; break;
            case 49152: ie_w1 = p; break;
            case 32768: in_w1 = p; break;
            case 17152: em_w1 = p; break;
            case 128: em_b1 = p; break;
            case 8192: em_w2 = p; break;
            case 1: em_b3 = p; break;
            case 16384: if (c16k++ == 0) ie_w2 = p; else in_w2 = p; break;
            case 256:
                if (c256 == 0) ie_b1 = p; else if (c256 == 1) ie_b2 = p;
                else if (c256 == 2) in_b1 = p; else in_b2 = p;
                c256++; break;
            case 64: {
                const float** slots[9] = {&cb0,&nu_b,&nu_g,&nu_be,&eu_b,&eu_g,&eu_be,&em_b2,&em_w3};
                if (c64 < 9) *slots[c64] = p;
                c64++; break;
            }
            default: break;
        }
    }
    float *b0, *b1, *cf, *nA, *nB, *agg, *edg;
    cudaGetSymbolAddress((void**)&b0, g_b0);
    cudaGetSymbolAddress((void**)&b1, g_b1);
    cudaGetSymbolAddress((void**)&cf, g_cf);
    cudaGetSymbolAddress((void**)&nA, g_nA);
    cudaGetSymbolAddress((void**)&nB, g_nB);
    cudaGetSymbolAddress((void**)&agg, g_agg);
    cudaGetSymbolAddress((void**)&edg, g_edge);

    const int SM_CNN = (4096 + 4096 + 1024 + 1024 + 64 + 64 + 8704 + 8704) * 4;
    const int SM_MSG = (4096 + 4096 + 64 + 64 + 8704 + 8704 + 256) * 4;
    const int SM_NU  = (6144 + 64 * 5 + 6400 + 4352 + 64) * 4;
    const int SM_NM  = (8192 + 4096 + 128 + 8320) * 4;
    const int SM_FIN = (17152 + 128 + 8192 + 64 + 64 + 4 + 4352 + 8448 + 4352) * 4 + 512;
    cudaFuncSetAttribute(k_cnn,     cudaFuncAttributeMaxDynamicSharedMemorySize, SM_CNN);
    cudaFuncSetAttribute(k_msg,     cudaFuncAttributeMaxDynamicSharedMemorySize, SM_MSG);
    cudaFuncSetAttribute(k_nodeup,  cudaFuncAttributeMaxDynamicSharedMemorySize, SM_NU);
    cudaFuncSetAttribute(k_nodemlp, cudaFuncAttributeMaxDynamicSharedMemorySize, SM_NM);
    cudaFuncSetAttribute(k_final,   cudaFuncAttributeMaxDynamicSharedMemorySize, SM_FIN);

    // CNN stack (layer 0: conv0 via mma inline)
    k_cnn<<<20000, 256, SM_CNN>>>(crop, crop, b1, cw0, cb0, cw,         cb,       4, NN*256, 1);
    k_cnn<<<5000,  256, SM_CNN>>>(crop, b1,   b0, cw0, cb0, cw + 16384, cb + 64,  3, NN*64,  0);
    k_cnn<<<1250,  256, SM_CNN>>>(crop, b0,   b1, cw0, cb0, cw + 32768, cb + 128, 2, NN*16,  0);
    k_cnn<<<313,   256, SM_CNN>>>(crop, b1,   b0, cw0, cb0, cw + 49152, cb + 192, 1, NN*4,   0);
    k_cnn<<<79,    256, SM_CNN>>>(crop, b0,   cf, cw0, cb0, cw + 65536, cb + 256, 0, NN,     0);
    // encoders
    k_nodeup<<<157, 256, SM_NU>>>(x, cf, nu_w, nu_b, nu_g, nu_be, nA);
    k_edgeup<<<5000, 256>>>(ea, eu_w, eu_b, eu_g, eu_be, edg);
    // 4 interaction layers
    float* cur = nA; float* nxt = nB;
    for (int l = 0; l < 4; l++) {
        cudaMemsetAsync(agg, 0, (size_t)NN * 64 * sizeof(float), 0);
        k_msg<<<2500, 256, SM_MSG>>>(cur, edg, ei, ie_w1 + l * 12288, ie_b1 + l * 64,
                                     ie_w2 + l * 4096, ie_b2 + l * 64, agg);
        k_nodemlp<<<79, 256, SM_NM>>>(cur, agg, in_w1 + l * 8192, in_b1 + l * 64,
                                      in_w2 + l * 4096, in_b2 + l * 64, nxt);
        float* tmp = cur; cur = nxt; nxt = tmp;
    }
    // final edge MLP
    k_final<<<5000, 256, SM_FIN>>>(cur, ea, ei, em_w1, em_b1, em_w2, em_b2,
                                   em_w3, em_b3, (float*)d_out);
}

// round 9
// speedup vs baseline: 3.3788x; 1.2504x over previous
#include <cuda_runtime.h>
#include <cstdint>

#define NN 10000
#define EE 320000

__device__ float g_b1[(size_t)NN*256*64];
__device__ float g_b0[(size_t)NN*64*64];
__device__ float g_cf[NN*64];
__device__ float g_nA[NN*64];
__device__ float g_nB[NN*64];
__device__ float g_agg[NN*64];
__device__ float g_edge[(size_t)EE*64];

__device__ __forceinline__ unsigned packbf(float lo,float hi){
  unsigned r;asm("cvt.rn.bf16x2.f32 %0,%1,%2;":"=r"(r):"f"(hi),"f"(lo));return r;}
__device__ __forceinline__ float bflo(unsigned p){return __uint_as_float(p<<16);}
__device__ __forceinline__ float bfhi(unsigned p){return __uint_as_float(p&0xFFFF0000u);}
__device__ __forceinline__ void mmabf(float* c,unsigned a0,unsigned a1,unsigned a2,unsigned a3,unsigned b0,unsigned b1){
  asm("mma.sync.aligned.m16n8k16.row.col.f32.bf16.bf16.f32 {%0,%1,%2,%3},{%4,%5,%6,%7},{%8,%9},{%0,%1,%2,%3};"
      :"+f"(c[0]),"+f"(c[1]),"+f"(c[2]),"+f"(c[3]):"r"(a0),"r"(a1),"r"(a2),"r"(a3),"r"(b0),"r"(b1));}
__device__ __forceinline__ void cpa16(uint32_t d,const void* s,int sz){
  asm volatile("cp.async.cg.shared.global [%0],[%1],16,%2;"::"r"(d),"l"(s),"r"(sz));}
__device__ __forceinline__ void cpacommit(){asm volatile("cp.async.commit_group;");}
template<int N> __device__ __forceinline__ void cpawait(){asm volatile("cp.async.wait_group %0;"::"n"(N));}

// bf16 3-term sweep: K=16 per mma. A raw fp32 in smem; split in registers.
__device__ __forceinline__ void mma_sweep(const float* A,const uint2* Wh,const uint2* Wl,
    int KT,float C[][4],int mrow,int tq,int stride){
  const int lane=threadIdx.x&31;
  for(int kt=0;kt<KT;kt++){
    const float* ap=A+mrow*stride+kt*16+2*tq;
    float2 x0=*(const float2*)ap;
    float2 x1=*(const float2*)(ap+8*stride);
    float2 x2=*(const float2*)(ap+8);
    float2 x3=*(const float2*)(ap+8*stride+8);
    unsigned a0=packbf(x0.x,x0.y),a1=packbf(x1.x,x1.y),a2=packbf(x2.x,x2.y),a3=packbf(x3.x,x3.y);
    unsigned l0=packbf(x0.x-bflo(a0),x0.y-bfhi(a0)),l1=packbf(x1.x-bflo(a1),x1.y-bfhi(a1));
    unsigned l2=packbf(x2.x-bflo(a2),x2.y-bfhi(a2)),l3=packbf(x3.x-bflo(a3),x3.y-bfhi(a3));
    #pragma unroll
    for(int nt=0;nt<8;nt++){
      int s=(kt*8+nt)*32+lane;
      uint2 bh=Wh[s],bl=Wl[s];
      mmabf(C[nt],a0,a1,a2,a3,bh.x,bh.y);
      mmabf(C[nt],a0,a1,a2,a3,bl.x,bl.y);
      mmabf(C[nt],l0,l1,l2,l3,bh.x,bh.y);
    }
  }
}

#define STAGE_WB(Wh,Wl,KT,GET) do{ for(int s_=threadIdx.x;s_<(KT)*256;s_+=256){ \
  int lane_=s_&31,nt_=(s_>>5)&7,kt_=s_>>8; int nn=nt_*8+(lane_>>2),k0=kt_*16+(lane_&3)*2; \
  float w00=GET(k0,nn),w01=GET((k0+1),nn),w10=GET((k0+8),nn),w11=GET((k0+9),nn); \
  unsigned h0=packbf(w00,w01),h1=packbf(w10,w11); \
  (Wh)[s_]=make_uint2(h0,h1); \
  (Wl)[s_]=make_uint2(packbf(w00-bflo(h0),w01-bfhi(h0)),packbf(w10-bflo(h1),w11-bfhi(h1)));} }while(0)

// ===== unified CNN layer (bf16 mma, cp.async pipelined); L0: conv0 via mma ===
__global__ void __launch_bounds__(256,2) k_cnn(const float* __restrict__ crop,
    const float* __restrict__ in,float* __restrict__ out,
    const float* __restrict__ w0,const float* __restrict__ b0c,
    const float* __restrict__ w,const float* __restrict__ b,int so_bits,int M,int L0){
  extern __shared__ float sm[];
  uint2* Wh=(uint2*)sm;                 // 1024 uint2 (2048 w)
  uint2* Wl=Wh+1024;                    // 2048 w
  uint2* W0h=Wl+1024;                   // 256 uint2 (512 w)
  uint2* W0l=W0h+256;                   // 512 w
  float* b0s=(float*)(W0l+256);         // 64
  float* bs=b0s+64;                     // 64
  float* A0=bs+64;                      // 8704
  float* A1=A0+8704;                    // 8704 (!L0: double buffer; L0: crop window + Ap)
  float* Ap=A1+6144;                    // L0 only: 128*20
  const int t=threadIdx.x,lane=t&31,wid=t>>5;
  const int Rbase=blockIdx.x*128;
  const int S_out=1<<so_bits,S_in=S_out<<1,so2=so_bits*2;
  const int half=(Rbase>>7)&1;
  if(L0){
    #define GETW0(kk,nn) (((kk)<12)?w0[(nn)*12+(kk)]:0.f)
    STAGE_WB(W0h,W0l,1,GETW0);
    #undef GETW0
    if(t<64)b0s[t]=b0c[t];
    int n=Rbase>>8;
    for(int i=t*4;i<6144;i+=1024){
      int c=i>>11,r=i&2047,y=r>>6,xx=r&63;
      *(float4*)&A1[i]=*(const float4*)&crop[(((size_t)n*3+c)*64+half*32+y)*64+xx];
    }
  }
  if(t<64)bs[t]=b[t];
  const int g=lane>>2,tq=lane&3,mrow=wid*16+g;
  auto issueA=[&](int pp,float* buf){
    int ky_=pp>>1,kx_=pp&1;
    uint32_t db=(uint32_t)__cvta_generic_to_shared(buf);
    #pragma unroll
    for(int k_=0;k_<8;k_++){
      int idx=t+k_*256,row=idx>>4,c4=(idx&15)*4,R=Rbase+row;
      const float* s_=in; int sz_=0;
      if(R<M){int n_=R>>so2,sp_=R&(S_out*S_out-1),oy_=sp_>>so_bits,ox_=sp_&(S_out-1);
        s_=&in[(((size_t)n_*S_in+2*oy_+ky_)*S_in+2*ox_+kx_)*64+c4];sz_=16;}
      cpa16(db+(row*68+c4)*4,s_,sz_);
    }
  };
  float C[8][4];
  #pragma unroll
  for(int i=0;i<8;i++){C[i][0]=0;C[i][1]=0;C[i][2]=0;C[i][3]=0;}
  if(!L0){issueA(0,A0);cpacommit();}
  for(int p=0;p<4;p++){
    const int ky=p>>1,kx=p&1;
    if(!L0&&p<3){issueA(p+1,(p&1)?A0:A1);cpacommit();}
    #define GETC(kk,nn) (w[(nn)*256+(kk)*4+p])
    STAGE_WB(Wh,Wl,4,GETC);
    #undef GETC
    if(L0){
      for(int i=t;i<2048;i+=256){
        int row=i>>4,col=i&15; float v=0.f;
        if(col<12){
          int sp=(Rbase+row)&255,oy=sp>>4,ox=sp&15;
          int oyl=oy-half*8;
          int c=col>>2,q=col&3;
          v=A1[c*2048+(4*oyl+2*ky+(q>>1))*64+4*ox+2*kx+(q&1)];
        }
        Ap[row*20+col]=v;
      }
    } else {
      if(p<3)cpawait<1>();else cpawait<0>();
    }
    __syncthreads();
    if(L0){
      float C0[8][4];
      #pragma unroll
      for(int i=0;i<8;i++){C0[i][0]=0;C0[i][1]=0;C0[i][2]=0;C0[i][3]=0;}
      mma_sweep(Ap,W0h,W0l,1,C0,mrow,tq,20);
      #pragma unroll
      for(int nt=0;nt<8;nt++){
        int col=nt*8+tq*2;
        A0[mrow*68+col]=fmaxf(C0[nt][0]+b0s[col],0.f);
        A0[mrow*68+col+1]=fmaxf(C0[nt][1]+b0s[col+1],0.f);
        A0[(mrow+8)*68+col]=fmaxf(C0[nt][2]+b0s[col],0.f);
        A0[(mrow+8)*68+col+1]=fmaxf(C0[nt][3]+b0s[col+1],0.f);
      }
      __syncthreads();
    }
    mma_sweep(L0?A0:((p&1)?A1:A0),Wh,Wl,4,C,mrow,tq,68);
    __syncthreads();
  }
  #pragma unroll
  for(int nt=0;nt<8;nt++){
    int col=nt*8+tq*2,r0=Rbase+mrow,r1=r0+8;
    if(r0<M){float2 v;v.x=fmaxf(C[nt][0]+bs[col],0.f);v.y=fmaxf(C[nt][1]+bs[col+1],0.f);
      *(float2*)&out[(size_t)r0*64+col]=v;}
    if(r1<M){float2 v;v.x=fmaxf(C[nt][2]+bs[col],0.f);v.y=fmaxf(C[nt][3]+bs[col+1],0.f);
      *(float2*)&out[(size_t)r1*64+col]=v;}
  }
}

// ====== msg MLP (192->64->64) + scatter-add, bf16 mma, cp.async =============
__global__ void __launch_bounds__(256,2) k_msg(const float* __restrict__ node,
    const float* __restrict__ edge,const int* __restrict__ ei,
    const float* __restrict__ w1,const float* __restrict__ b1,
    const float* __restrict__ w2,const float* __restrict__ b2,float* __restrict__ agg){
  extern __shared__ float sm[];
  uint2* Wh=(uint2*)sm; uint2* Wl=Wh+1024;
  float* b1s=(float*)(Wl+1024); float* b2s=b1s+64;
  float* A0=b2s+64; float* A1=A0+8704;
  int* srcs=(int*)(A1+8704); int* dsts=srcs+128;
  const int t=threadIdx.x,lane=t&31,wid=t>>5;
  const int ebase=blockIdx.x*128;
  if(t<64){b1s[t]=b1[t];b2s[t]=b2[t];}
  if(t<128){srcs[t]=ei[ebase+t];dsts[t]=ei[EE+ebase+t];}
  const int g=lane>>2,tq=lane&3,mrow=wid*16+g;
  __syncthreads();
  auto issueM=[&](int ch,float* buf){
    uint32_t db=(uint32_t)__cvta_generic_to_shared(buf);
    #pragma unroll
    for(int k_=0;k_<8;k_++){
      int idx=t+k_*256,row=idx>>4,c4=(idx&15)*4;
      const float* s_=(ch==0)?&node[(size_t)dsts[row]*64+c4]:(ch==1)?&node[(size_t)srcs[row]*64+c4]
                     :&edge[(size_t)(ebase+row)*64+c4];
      cpa16(db+(row*68+c4)*4,s_,16);
    }
  };
  float C1[8][4];
  #pragma unroll
  for(int i=0;i<8;i++){C1[i][0]=0;C1[i][1]=0;C1[i][2]=0;C1[i][3]=0;}
  issueM(0,A0);cpacommit();
  for(int ch=0;ch<3;ch++){
    if(ch<2){issueM(ch+1,(ch&1)?A0:A1);cpacommit();}
    #define GETM(kk,nn) (w1[((ch)*64+(kk))*64+(nn)])
    STAGE_WB(Wh,Wl,4,GETM);
    #undef GETM
    if(ch<2)cpawait<1>();else cpawait<0>();
    __syncthreads();
    mma_sweep((ch&1)?A1:A0,Wh,Wl,4,C1,mrow,tq,68);
    __syncthreads();
  }
  #pragma unroll
  for(int nt=0;nt<8;nt++){
    int col=nt*8+tq*2;
    A0[mrow*68+col]=fmaxf(C1[nt][0]+b1s[col],0.f);
    A0[mrow*68+col+1]=fmaxf(C1[nt][1]+b1s[col+1],0.f);
    A0[(mrow+8)*68+col]=fmaxf(C1[nt][2]+b1s[col],0.f);
    A0[(mrow+8)*68+col+1]=fmaxf(C1[nt][3]+b1s[col+1],0.f);
  }
  #define GETM2(kk,nn) (w2[(kk)*64+(nn)])
  STAGE_WB(Wh,Wl,4,GETM2);
  #undef GETM2
  __syncthreads();
  float C2[8][4];
  #pragma unroll
  for(int i=0;i<8;i++){C2[i][0]=0;C2[i][1]=0;C2[i][2]=0;C2[i][3]=0;}
  mma_sweep(A0,Wh,Wl,4,C2,mrow,tq,68);
  const int d0=dsts[mrow],d1=dsts[mrow+8];
  #pragma unroll
  for(int nt=0;nt<8;nt++){
    int col=nt*8+tq*2;
    atomicAdd(&agg[(size_t)d0*64+col],C2[nt][0]+b2s[col]);
    atomicAdd(&agg[(size_t)d0*64+col+1],C2[nt][1]+b2s[col+1]);
    atomicAdd(&agg[(size_t)d1*64+col],C2[nt][2]+b2s[col]);
    atomicAdd(&agg[(size_t)d1*64+col+1],C2[nt][3]+b2s[col+1]);
  }
}

// --------------------------------------------- node_update: [x|cf]@W + LN
__global__ void __launch_bounds__(256) k_nodeup(const float* __restrict__ x,
    const float* __restrict__ cf, const float* __restrict__ w, const float* __restrict__ b,
    const float* __restrict__ g, const float* __restrict__ be, float* __restrict__ out) {
    extern __shared__ float sm[];
    float* Ws = sm;
    float* Bs = Ws + 6144; float* Gs = Bs + 64; float* BEs = Gs + 64;
    float* mu = BEs + 64; float* rs = mu + 64;
    float* As = rs + 64; float* Hs = As + 6400;
    int t = threadIdx.x;
    int Rbase = blockIdx.x * 64;
    for (int i = t; i < 6144; i += 256) Ws[i] = w[i];
    if (t < 64) { Bs[t]=b[t]; Gs[t]=g[t]; BEs[t]=be[t]; }
    for (int e = t; e < 2048; e += 256) {
        int row = e >> 5, c = e & 31, nd = Rbase + row;
        As[row * 100 + c] = (nd < NN) ? x[nd * 32 + c] : 0.f;
    }
    for (int e = t; e < 4096; e += 256) {
        int row = e >> 6, c = e & 63, nd = Rbase + row;
        As[row * 100 + 32 + c] = (nd < NN) ? cf[nd * 64 + c] : 0.f;
    }
    __syncthreads();
    int tr = t >> 4, tc = t & 15;
    float acc[4][4];
    float4 b4 = *(const float4*)&Bs[tc * 4];
    #pragma unroll
    for (int i = 0; i < 4; i++) { acc[i][0]=b4.x; acc[i][1]=b4.y; acc[i][2]=b4.z; acc[i][3]=b4.w; }
    for (int k = 0; k < 96; k++) {
        float4 w4 = *(const float4*)&Ws[k * 64 + tc * 4];
        #pragma unroll
        for (int i = 0; i < 4; i++) {
            float a = As[(tr * 4 + i) * 100 + k];
            acc[i][0] += a*w4.x; acc[i][1] += a*w4.y; acc[i][2] += a*w4.z; acc[i][3] += a*w4.w;
        }
    }
    #pragma unroll
    for (int i = 0; i < 4; i++) {
        float4 r; r.x=fmaxf(acc[i][0],0.f); r.y=fmaxf(acc[i][1],0.f);
        r.z=fmaxf(acc[i][2],0.f); r.w=fmaxf(acc[i][3],0.f);
        *(float4*)&Hs[(tr * 4 + i) * 68 + tc * 4] = r;
    }
    __syncthreads();
    if (t < 64) {
        float s = 0.f, sq = 0.f;
        for (int c = 0; c < 64; c++) { float v = Hs[t * 68 + c]; s += v; sq += v * v; }
        float m = s * (1.f / 64.f);
        mu[t] = m; rs[t] = rsqrtf(sq * (1.f / 64.f) - m * m + 1e-5f);
    }
    __syncthreads();
    for (int i = t; i < 4096; i += 256) {
        int r = i >> 6, c = i & 63, nd = Rbase + r;
        if (nd < NN) out[nd * 64 + c] = (Hs[r * 68 + c] - mu[r]) * rs[r] * Gs[c] + BEs[c];
    }
}

// --------------------------------------------- edge_update: ea@W + LN
__global__ void __launch_bounds__(256) k_edgeup(const float* __restrict__ ea,
    const float* __restrict__ w, const float* __restrict__ b,
    const float* __restrict__ g, const float* __restrict__ be, float* __restrict__ out) {
    __shared__ float Ws[384], Bs[64], Gs[64], BEs[64], Aa[64][8], Hs[64][68], mu[64], rs[64];
    int t = threadIdx.x;
    int ebase = blockIdx.x * 64;
    for (int i = t; i < 384; i += 256) Ws[i] = w[i];
    if (t < 64) { Bs[t]=b[t]; Gs[t]=g[t]; BEs[t]=be[t]; }
    for (int e = t; e < 384; e += 256) {
        int row = e / 6, k = e - row * 6;
        Aa[row][k] = ea[(size_t)(ebase + row) * 6 + k];
    }
    __syncthreads();
    int r = t >> 2, cg = (t & 3) * 16;
    float a0=Aa[r][0],a1=Aa[r][1],a2=Aa[r][2],a3=Aa[r][3],a4=Aa[r][4],a5=Aa[r][5];
    #pragma unroll
    for (int j = 0; j < 16; j++) {
        int c = cg + j;
        float h = Bs[c] + a0*Ws[c] + a1*Ws[64+c] + a2*Ws[128+c] + a3*Ws[192+c] + a4*Ws[256+c] + a5*Ws[320+c];
        Hs[r][c] = fmaxf(h, 0.f);
    }
    __syncthreads();
    if (t < 64) {
        float s = 0.f, sq = 0.f;
        for (int c = 0; c < 64; c++) { float v = Hs[t][c]; s += v; sq += v * v; }
        float m = s * (1.f / 64.f);
        mu[t] = m; rs[t] = rsqrtf(sq * (1.f / 64.f) - m * m + 1e-5f);
    }
    __syncthreads();
    for (int i = t; i < 4096; i += 256) {
        int rr = i >> 6, c = i & 63;
        out[(size_t)ebase * 64 + i] = (Hs[rr][c] - mu[rr]) * rs[rr] * Gs[c] + BEs[c];
    }
}

// ========= node MLP: [node|agg] 2-layer, 128 nodes/block, 4x8 per thread =====
__global__ void __launch_bounds__(256, 2) k_nodemlp(const float* __restrict__ node,
    const float* __restrict__ agg, const float* __restrict__ w1, const float* __restrict__ b1,
    const float* __restrict__ w2, const float* __restrict__ b2, float* __restrict__ out) {
    extern __shared__ float sm[];
    float* W1s = sm;
    float* W2s = W1s + 8192;
    float* B1s = W2s + 4096; float* B2s = B1s + 64;
    float* As = B2s + 64;
    const int t = threadIdx.x;
    const int Rbase = blockIdx.x * 128;
    for (int i = t; i < 8192; i += 256) W1s[i] = w1[i];
    for (int i = t; i < 4096; i += 256) W2s[i] = w2[i];
    if (t < 64) { B1s[t]=b1[t]; B2s[t]=b2[t]; }
    const int tr = t >> 3, tc = t & 7;
    const float* ar[4];
    #pragma unroll
    for (int i = 0; i < 4; i++) ar[i] = &As[(tr * 4 + i) * 65];
    float acc[4][8];
    for (int ch = 0; ch < 2; ch++) {
        __syncthreads();
        for (int e = t * 4; e < 8192; e += 1024) {
            int row = e >> 6, c4 = e & 63, nd = Rbase + row;
            float4 vv = make_float4(0.f,0.f,0.f,0.f);
            if (nd < NN) {
                const float* base = (ch == 0) ? &node[(size_t)nd * 64] : &agg[(size_t)nd * 64];
                vv = *(const float4*)&base[c4];
            }
            float* d = &As[row * 65 + c4];
            d[0]=vv.x; d[1]=vv.y; d[2]=vv.z; d[3]=vv.w;
        }
        __syncthreads();
        if (ch == 0) {
            float4 ba = *(const float4*)&B1s[tc * 8];
            float4 bb = *(const float4*)&B1s[tc * 8 + 4];
            #pragma unroll
            for (int i = 0; i < 4; i++) {
                acc[i][0]=ba.x;acc[i][1]=ba.y;acc[i][2]=ba.z;acc[i][3]=ba.w;
                acc[i][4]=bb.x;acc[i][5]=bb.y;acc[i][6]=bb.z;acc[i][7]=bb.w;
            }
        }
        const float* wp = &W1s[ch * 4096 + tc * 8];
        #pragma unroll 8
        for (int k = 0; k < 64; k++) {
            float4 wa = *(const float4*)&wp[k * 64];
            float4 wb = *(const float4*)&wp[k * 64 + 4];
            #pragma unroll
            for (int i = 0; i < 4; i++) {
                float a = ar[i][k];
                acc[i][0]+=a*wa.x; acc[i][1]+=a*wa.y; acc[i][2]+=a*wa.z; acc[i][3]+=a*wa.w;
                acc[i][4]+=a*wb.x; acc[i][5]+=a*wb.y; acc[i][6]+=a*wb.z; acc[i][7]+=a*wb.w;
            }
        }
    }
    __syncthreads();
    #pragma unroll
    for (int i = 0; i < 4; i++)
        #pragma unroll
        for (int j = 0; j < 8; j++)
            As[(tr * 4 + i) * 65 + tc * 8 + j] = fmaxf(acc[i][j], 0.f);
    __syncthreads();
    float a2[4][8];
    {
        float4 ba = *(const float4*)&B2s[tc * 8];
        float4 bb = *(const float4*)&B2s[tc * 8 + 4];
        #pragma unroll
        for (int i = 0; i < 4; i++) {
            a2[i][0]=ba.x;a2[i][1]=ba.y;a2[i][2]=ba.z;a2[i][3]=ba.w;
            a2[i][4]=bb.x;a2[i][5]=bb.y;a2[i][6]=bb.z;a2[i][7]=bb.w;
        }
    }
    const float* wp2 = &W2s[tc * 8];
    #pragma unroll 8
    for (int k = 0; k < 64; k++) {
        float4 wa = *(const float4*)&wp2[k * 64];
        float4 wb = *(const float4*)&wp2[k * 64 + 4];
        #pragma unroll
        for (int i = 0; i < 4; i++) {
            float a = ar[i][k];
            a2[i][0]+=a*wa.x; a2[i][1]+=a*wa.y; a2[i][2]+=a*wa.z; a2[i][3]+=a*wa.w;
            a2[i][4]+=a*wb.x; a2[i][5]+=a*wb.y; a2[i][6]+=a*wb.z; a2[i][7]+=a*wb.w;
        }
    }
    #pragma unroll
    for (int i = 0; i < 4; i++) {
        int nd = Rbase + tr * 4 + i;
        if (nd < NN) {
            float4 v;
            v.x=a2[i][0]; v.y=a2[i][1]; v.z=a2[i][2]; v.w=a2[i][3];
            *(float4*)&out[(size_t)nd * 64 + tc * 8] = v;
            v.x=a2[i][4]; v.y=a2[i][5]; v.z=a2[i][6]; v.w=a2[i][7];
            *(float4*)&out[(size_t)nd * 64 + tc * 8 + 4] = v;
        }
    }
}

// --------------------------------------------- final edge MLP: 134->128->64->1
__global__ void __launch_bounds__(256) k_final(const float* __restrict__ node,
    const float* __restrict__ ea, const int* __restrict__ ei,
    const float* __restrict__ w1, const float* __restrict__ b1,
    const float* __restrict__ w2, const float* __restrict__ b2,
    const float* __restrict__ w3, const float* __restrict__ b3, float* __restrict__ out) {
    extern __shared__ float sm[];
    float* W1s = sm;
    float* B1s = W1s + 17152;
    float* W2s = B1s + 128;
    float* B2s = W2s + 8192;
    float* w3s = B2s + 64;
    float* b3s = w3s + 64;
    float* As  = b3s + 4;
    float* Hs  = As + 4352;
    float* H2s = Hs + 8448;
    int* srcs = (int*)(H2s + 4352);
    int* dsts = srcs + 64;
    int t = threadIdx.x;
    int ebase = blockIdx.x * 64;
    for (int i = t; i < 17152; i += 256) W1s[i] = w1[i];
    for (int i = t; i < 8192; i += 256) W2s[i] = w2[i];
    if (t < 128) B1s[t] = b1[t];
    if (t < 64) { B2s[t]=b2[t]; w3s[t]=w3[t]; srcs[t]=ei[ebase+t]; dsts[t]=ei[EE+ebase+t]; }
    if (t == 0) b3s[0] = b3[0];
    int tr = t >> 4, tc = t & 15;
    float acc[4][8];
    for (int ch = 0; ch < 2; ch++) {
        __syncthreads();
        for (int e = t * 4; e < 4096; e += 1024) {
            int row = e >> 6, c4 = e & 63;
            const float* base = (ch == 0) ? &node[(size_t)srcs[row] * 64]
                                          : &node[(size_t)dsts[row] * 64];
            *(float4*)&As[row * 68 + c4] = *(const float4*)&base[c4];
        }
        __syncthreads();
        if (ch == 0) {
            #pragma unroll
            for (int i = 0; i < 4; i++)
                #pragma unroll
                for (int j = 0; j < 8; j++) acc[i][j] = B1s[tc * 8 + j];
        }
        for (int k = 0; k < 64; k++) {
            float4 wa = *(const float4*)&W1s[(ch * 64 + k) * 128 + tc * 8];
            float4 wb = *(const float4*)&W1s[(ch * 64 + k) * 128 + tc * 8 + 4];
            #pragma unroll
            for (int i = 0; i < 4; i++) {
                float a = As[(tr * 4 + i) * 68 + k];
                acc[i][0]+=a*wa.x; acc[i][1]+=a*wa.y; acc[i][2]+=a*wa.z; acc[i][3]+=a*wa.w;
                acc[i][4]+=a*wb.x; acc[i][5]+=a*wb.y; acc[i][6]+=a*wb.z; acc[i][7]+=a*wb.w;
            }
        }
    }
    __syncthreads();
    for (int e = t; e < 384; e += 256) {
        int row = e / 6, k = e - row * 6;
        As[row * 8 + k] = ea[(size_t)(ebase + row) * 6 + k];
    }
    __syncthreads();
    for (int k = 0; k < 6; k++) {
        float4 wa = *(const float4*)&W1s[(128 + k) * 128 + tc * 8];
        float4 wb = *(const float4*)&W1s[(128 + k) * 128 + tc * 8 + 4];
        #pragma unroll
        for (int i = 0; i < 4; i++) {
            float a = As[(tr * 4 + i) * 8 + k];
            acc[i][0]+=a*wa.x; acc[i][1]+=a*wa.y; acc[i][2]+=a*wa.z; acc[i][3]+=a*wa.w;
            acc[i][4]+=a*wb.x; acc[i][5]+=a*wb.y; acc[i][6]+=a*wb.z; acc[i][7]+=a*wb.w;
        }
    }
    #pragma unroll
    for (int i = 0; i < 4; i++)
        #pragma unroll
        for (int j = 0; j < 8; j++)
            Hs[(tr * 4 + i) * 132 + tc * 8 + j] = fmaxf(acc[i][j], 0.f);
    __syncthreads();
    float a2[4][4];
    #pragma unroll
    for (int i = 0; i < 4; i++)
        #pragma unroll
        for (int j = 0; j < 4; j++) a2[i][j] = B2s[tc * 4 + j];
    for (int k = 0; k < 128; k++) {
        float4 w4 = *(const float4*)&W2s[k * 64 + tc * 4];
        #pragma unroll
        for (int i = 0; i < 4; i++) {
            float a = Hs[(tr * 4 + i) * 132 + k];
            a2[i][0] += a*w4.x; a2[i][1] += a*w4.y; a2[i][2] += a*w4.z; a2[i][3] += a*w4.w;
        }
    }
    #pragma unroll
    for (int i = 0; i < 4; i++)
        #pragma unroll
        for (int j = 0; j < 4; j++)
            H2s[(tr * 4 + i) * 68 + tc * 4 + j] = fmaxf(a2[i][j], 0.f);
    __syncthreads();
    if (t < 64) {
        float s = b3s[0];
        for (int c = 0; c < 64; c++) s += H2s[t * 68 + c] * w3s[c];
        out[ebase + t] = s;
    }
}

// ============================================================================
extern "C" void kernel_launch(void* const* d_in, const int* in_sizes, int n_in,
                              void* d_out, int out_size) {
    const float *x=0,*ea=0,*crop=0,*cw0=0,*cb0=0,*cw=0,*cb=0,*nu_w=0,*nu_b=0,*nu_g=0,*nu_be=0,
        *eu_w=0,*eu_b=0,*eu_g=0,*eu_be=0,*ie_w1=0,*ie_b1=0,*ie_w2=0,*ie_b2=0,
        *in_w1=0,*in_b1=0,*in_w2=0,*in_b2=0,*em_w1=0,*em_b1=0,*em_w2=0,*em_b2=0,*em_w3=0,*em_b3=0;
    const int* ei = 0;
    int c64 = 0, c256 = 0, c16k = 0;
    for (int i = 0; i < n_in; i++) {
        const float* p = (const float*)d_in[i];
        switch (in_sizes[i]) {
            case 320000: x = p; break;
            case 640000: ei = (const int*)p; break;
            case 1920000: ea = p; break;
            case 122880000: crop = p; break;
            case 768: cw0 = p; break;
            case 81920: cw = p; break;
            case 320: cb = p; break;
            case 6144: nu_w = p; break;
            case 384: eu_w = p; break;
            case 49152: ie_w1 = p; break;
            case 32768: in_w1 = p; break;
            case 17152: em_w1 = p; break;
            case 128: em_b1 = p; break;
            case 8192: em_w2 = p; break;
            case 1: em_b3 = p; break;
            case 16384: if (c16k++ == 0) ie_w2 = p; else in_w2 = p; break;
            case 256:
                if (c256 == 0) ie_b1 = p; else if (c256 == 1) ie_b2 = p;
                else if (c256 == 2) in_b1 = p; else in_b2 = p;
                c256++; break;
            case 64: {
                const float** slots[9] = {&cb0,&nu_b,&nu_g,&nu_be,&eu_b,&eu_g,&eu_be,&em_b2,&em_w3};
                if (c64 < 9) *slots[c64] = p;
                c64++; break;
            }
            default: break;
        }
    }
    float *b0, *b1, *cf, *nA, *nB, *agg, *edg;
    cudaGetSymbolAddress((void**)&b0, g_b0);
    cudaGetSymbolAddress((void**)&b1, g_b1);
    cudaGetSymbolAddress((void**)&cf, g_cf);
    cudaGetSymbolAddress((void**)&nA, g_nA);
    cudaGetSymbolAddress((void**)&nB, g_nB);
    cudaGetSymbolAddress((void**)&agg, g_agg);
    cudaGetSymbolAddress((void**)&edg, g_edge);

    const int SM_CNN = (2048 + 2048 + 512 + 512 + 64 + 64 + 8704 + 8704) * 4;
    const int SM_MSG = (2048 + 2048 + 64 + 64 + 8704 + 8704 + 256) * 4;
    const int SM_NU  = (6144 + 64 * 5 + 6400 + 4352 + 64) * 4;
    const int SM_NM  = (8192 + 4096 + 128 + 8320) * 4;
    const int SM_FIN = (17152 + 128 + 8192 + 64 + 64 + 4 + 4352 + 8448 + 4352) * 4 + 512;
    cudaFuncSetAttribute(k_cnn,     cudaFuncAttributeMaxDynamicSharedMemorySize, SM_CNN);
    cudaFuncSetAttribute(k_msg,     cudaFuncAttributeMaxDynamicSharedMemorySize, SM_MSG);
    cudaFuncSetAttribute(k_nodeup,  cudaFuncAttributeMaxDynamicSharedMemorySize, SM_NU);
    cudaFuncSetAttribute(k_nodemlp, cudaFuncAttributeMaxDynamicSharedMemorySize, SM_NM);
    cudaFuncSetAttribute(k_final,   cudaFuncAttributeMaxDynamicSharedMemorySize, SM_FIN);

    // CNN stack (layer 0: conv0 via mma inline)
    k_cnn<<<20000, 256, SM_CNN>>>(crop, crop, b1, cw0, cb0, cw,         cb,       4, NN*256, 1);
    k_cnn<<<5000,  256, SM_CNN>>>(crop, b1,   b0, cw0, cb0, cw + 16384, cb + 64,  3, NN*64,  0);
    k_cnn<<<1250,  256, SM_CNN>>>(crop, b0,   b1, cw0, cb0, cw + 32768, cb + 128, 2, NN*16,  0);
    k_cnn<<<313,   256, SM_CNN>>>(crop, b1,   b0, cw0, cb0, cw + 49152, cb + 192, 1, NN*4,   0);
    k_cnn<<<79,    256, SM_CNN>>>(crop, b0,   cf, cw0, cb0, cw + 65536, cb + 256, 0, NN,     0);
    // encoders
    k_nodeup<<<157, 256, SM_NU>>>(x, cf, nu_w, nu_b, nu_g, nu_be, nA);
    k_edgeup<<<5000, 256>>>(ea, eu_w, eu_b, eu_g, eu_be, edg);
    // 4 interaction layers
    float* cur = nA; float* nxt = nB;
    for (int l = 0; l < 4; l++) {
        cudaMemsetAsync(agg, 0, (size_t)NN * 64 * sizeof(float), 0);
        k_msg<<<2500, 256, SM_MSG>>>(cur, edg, ei, ie_w1 + l * 12288, ie_b1 + l * 64,
                                     ie_w2 + l * 4096, ie_b2 + l * 64, agg);
        k_nodemlp<<<79, 256, SM_NM>>>(cur, agg, in_w1 + l * 8192, in_b1 + l * 64,
                                      in_w2 + l * 4096, in_b2 + l * 64, nxt);
        float* tmp = cur; cur = nxt; nxt = tmp;
    }
    // final edge MLP
    k_final<<<5000, 256, SM_FIN>>>(cur, ea, ei, em_w1, em_b1, em_w2, em_b2,
                                   em_w3, em_b3, (float*)d_out);
}

// round 10
// speedup vs baseline: 4.0000x; 1.1839x over previous
#include <cuda_runtime.h>
#include <cstdint>

#define NN 10000
#define EE 320000

__device__ float g_b1[(size_t)NN*256*64];
__device__ float g_b0[(size_t)NN*64*64];
__device__ float g_cf[NN*64];
__device__ float g_nA[NN*64];
__device__ float g_nB[NN*64];
__device__ float g_agg[NN*64];
__device__ float g_edge[(size_t)EE*64];

__device__ __forceinline__ unsigned packbf(float lo,float hi){
  unsigned r;asm("cvt.rn.bf16x2.f32 %0,%1,%2;":"=r"(r):"f"(hi),"f"(lo));return r;}
__device__ __forceinline__ float bflo(unsigned p){return __uint_as_float(p<<16);}
__device__ __forceinline__ float bfhi(unsigned p){return __uint_as_float(p&0xFFFF0000u);}
__device__ __forceinline__ void mmabf(float* c,unsigned a0,unsigned a1,unsigned a2,unsigned a3,unsigned b0,unsigned b1){
  asm("mma.sync.aligned.m16n8k16.row.col.f32.bf16.bf16.f32 {%0,%1,%2,%3},{%4,%5,%6,%7},{%8,%9},{%0,%1,%2,%3};"
      :"+f"(c[0]),"+f"(c[1]),"+f"(c[2]),"+f"(c[3]):"r"(a0),"r"(a1),"r"(a2),"r"(a3),"r"(b0),"r"(b1));}
__device__ __forceinline__ void cpa16(uint32_t d,const void* s,int sz){
  asm volatile("cp.async.cg.shared.global [%0],[%1],16,%2;"::"r"(d),"l"(s),"r"(sz));}
__device__ __forceinline__ void cpacommit(){asm volatile("cp.async.commit_group;");}
template<int N> __device__ __forceinline__ void cpawait(){asm volatile("cp.async.wait_group %0;"::"n"(N));}

// bf16 3-term sweep: K=16 per mma. A raw fp32 in smem; split in registers.
template<int NT>
__device__ __forceinline__ void mma_sweepN(const float* A,const uint2* Wh,const uint2* Wl,
    int KT,float C[][4],int mrow,int tq,int stride){
  const int lane=threadIdx.x&31;
  for(int kt=0;kt<KT;kt++){
    const float* ap=A+mrow*stride+kt*16+2*tq;
    float2 x0=*(const float2*)ap;
    float2 x1=*(const float2*)(ap+8*stride);
    float2 x2=*(const float2*)(ap+8);
    float2 x3=*(const float2*)(ap+8*stride+8);
    unsigned a0=packbf(x0.x,x0.y),a1=packbf(x1.x,x1.y),a2=packbf(x2.x,x2.y),a3=packbf(x3.x,x3.y);
    unsigned l0=packbf(x0.x-bflo(a0),x0.y-bfhi(a0)),l1=packbf(x1.x-bflo(a1),x1.y-bfhi(a1));
    unsigned l2=packbf(x2.x-bflo(a2),x2.y-bfhi(a2)),l3=packbf(x3.x-bflo(a3),x3.y-bfhi(a3));
    #pragma unroll
    for(int nt=0;nt<NT;nt++){
      int s=(kt*NT+nt)*32+lane;
      uint2 bh=Wh[s],bl=Wl[s];
      mmabf(C[nt],a0,a1,a2,a3,bh.x,bh.y);
      mmabf(C[nt],a0,a1,a2,a3,bl.x,bl.y);
      mmabf(C[nt],l0,l1,l2,l3,bh.x,bh.y);
    }
  }
}

#define STAGE_WBN(Wh,Wl,KT,NT,GET) do{ for(int s_=threadIdx.x;s_<(KT)*(NT)*32;s_+=256){ \
  int lane_=s_&31,w_=s_>>5,nt_=w_%(NT),kt_=w_/(NT); \
  int nn=nt_*8+(lane_>>2),k0=kt_*16+(lane_&3)*2; \
  float w00=GET(k0,nn),w01=GET((k0+1),nn),w10=GET((k0+8),nn),w11=GET((k0+9),nn); \
  unsigned h0=packbf(w00,w01),h1=packbf(w10,w11); \
  (Wh)[s_]=make_uint2(h0,h1); \
  (Wl)[s_]=make_uint2(packbf(w00-bflo(h0),w01-bfhi(h0)),packbf(w10-bflo(h1),w11-bfhi(h1)));} }while(0)

// ===== unified CNN layer (bf16 mma, cp.async pipelined); L0: conv0 via mma ===
__global__ void __launch_bounds__(256,2) k_cnn(const float* __restrict__ crop,
    const float* __restrict__ in,float* __restrict__ out,
    const float* __restrict__ w0,const float* __restrict__ b0c,
    const float* __restrict__ w,const float* __restrict__ b,int so_bits,int M,int L0){
  extern __shared__ float sm[];
  uint2* Wh=(uint2*)sm;
  uint2* Wl=Wh+1024;
  uint2* W0h=Wl+1024;
  uint2* W0l=W0h+256;
  float* b0s=(float*)(W0l+256);
  float* bs=b0s+64;
  float* A0=bs+64;
  float* A1=A0+8704;
  float* Ap=A1+6144;
  const int t=threadIdx.x,lane=t&31,wid=t>>5;
  const int Rbase=blockIdx.x*128;
  const int S_out=1<<so_bits,S_in=S_out<<1,so2=so_bits*2;
  const int half=(Rbase>>7)&1;
  if(L0){
    #define GETW0(kk,nn) (((kk)<12)?w0[(nn)*12+(kk)]:0.f)
    STAGE_WBN(W0h,W0l,1,8,GETW0);
    #undef GETW0
    if(t<64)b0s[t]=b0c[t];
    int n=Rbase>>8;
    for(int i=t*4;i<6144;i+=1024){
      int c=i>>11,r=i&2047,y=r>>6,xx=r&63;
      *(float4*)&A1[i]=*(const float4*)&crop[(((size_t)n*3+c)*64+half*32+y)*64+xx];
    }
  }
  if(t<64)bs[t]=b[t];
  const int g=lane>>2,tq=lane&3,mrow=wid*16+g;
  auto issueA=[&](int pp,float* buf){
    int ky_=pp>>1,kx_=pp&1;
    uint32_t db=(uint32_t)__cvta_generic_to_shared(buf);
    #pragma unroll
    for(int k_=0;k_<8;k_++){
      int idx=t+k_*256,row=idx>>4,c4=(idx&15)*4,R=Rbase+row;
      const float* s_=in; int sz_=0;
      if(R<M){int n_=R>>so2,sp_=R&(S_out*S_out-1),oy_=sp_>>so_bits,ox_=sp_&(S_out-1);
        s_=&in[(((size_t)n_*S_in+2*oy_+ky_)*S_in+2*ox_+kx_)*64+c4];sz_=16;}
      cpa16(db+(row*68+c4)*4,s_,sz_);
    }
  };
  float C[8][4];
  #pragma unroll
  for(int i=0;i<8;i++){C[i][0]=0;C[i][1]=0;C[i][2]=0;C[i][3]=0;}
  if(!L0){issueA(0,A0);cpacommit();}
  for(int p=0;p<4;p++){
    const int ky=p>>1,kx=p&1;
    if(!L0&&p<3){issueA(p+1,(p&1)?A0:A1);cpacommit();}
    #define GETC(kk,nn) (w[(nn)*256+(kk)*4+p])
    STAGE_WBN(Wh,Wl,4,8,GETC);
    #undef GETC
    if(L0){
      for(int i=t;i<2048;i+=256){
        int row=i>>4,col=i&15; float v=0.f;
        if(col<12){
          int sp=(Rbase+row)&255,oy=sp>>4,ox=sp&15;
          int oyl=oy-half*8;
          int c=col>>2,q=col&3;
          v=A1[c*2048+(4*oyl+2*ky+(q>>1))*64+4*ox+2*kx+(q&1)];
        }
        Ap[row*20+col]=v;
      }
    } else {
      if(p<3)cpawait<1>();else cpawait<0>();
    }
    __syncthreads();
    if(L0){
      float C0[8][4];
      #pragma unroll
      for(int i=0;i<8;i++){C0[i][0]=0;C0[i][1]=0;C0[i][2]=0;C0[i][3]=0;}
      mma_sweepN<8>(Ap,W0h,W0l,1,C0,mrow,tq,20);
      #pragma unroll
      for(int nt=0;nt<8;nt++){
        int col=nt*8+tq*2;
        A0[mrow*68+col]=fmaxf(C0[nt][0]+b0s[col],0.f);
        A0[mrow*68+col+1]=fmaxf(C0[nt][1]+b0s[col+1],0.f);
        A0[(mrow+8)*68+col]=fmaxf(C0[nt][2]+b0s[col],0.f);
        A0[(mrow+8)*68+col+1]=fmaxf(C0[nt][3]+b0s[col+1],0.f);
      }
      __syncthreads();
    }
    mma_sweepN<8>(L0?A0:((p&1)?A1:A0),Wh,Wl,4,C,mrow,tq,68);
    __syncthreads();
  }
  #pragma unroll
  for(int nt=0;nt<8;nt++){
    int col=nt*8+tq*2,r0=Rbase+mrow,r1=r0+8;
    if(r0<M){float2 v;v.x=fmaxf(C[nt][0]+bs[col],0.f);v.y=fmaxf(C[nt][1]+bs[col+1],0.f);
      *(float2*)&out[(size_t)r0*64+col]=v;}
    if(r1<M){float2 v;v.x=fmaxf(C[nt][2]+bs[col],0.f);v.y=fmaxf(C[nt][3]+bs[col+1],0.f);
      *(float2*)&out[(size_t)r1*64+col]=v;}
  }
}

// ====== msg MLP (192->64->64) + scatter-add, bf16 mma, cp.async =============
__global__ void __launch_bounds__(256,2) k_msg(const float* __restrict__ node,
    const float* __restrict__ edge,const int* __restrict__ ei,
    const float* __restrict__ w1,const float* __restrict__ b1,
    const float* __restrict__ w2,const float* __restrict__ b2,float* __restrict__ agg){
  extern __shared__ float sm[];
  uint2* Wh=(uint2*)sm; uint2* Wl=Wh+1024;
  float* b1s=(float*)(Wl+1024); float* b2s=b1s+64;
  float* A0=b2s+64; float* A1=A0+8704;
  int* srcs=(int*)(A1+8704); int* dsts=srcs+128;
  const int t=threadIdx.x,lane=t&31,wid=t>>5;
  const int ebase=blockIdx.x*128;
  if(t<64){b1s[t]=b1[t];b2s[t]=b2[t];}
  if(t<128){srcs[t]=ei[ebase+t];dsts[t]=ei[EE+ebase+t];}
  const int g=lane>>2,tq=lane&3,mrow=wid*16+g;
  __syncthreads();
  auto issueM=[&](int ch,float* buf){
    uint32_t db=(uint32_t)__cvta_generic_to_shared(buf);
    #pragma unroll
    for(int k_=0;k_<8;k_++){
      int idx=t+k_*256,row=idx>>4,c4=(idx&15)*4;
      const float* s_=(ch==0)?&node[(size_t)dsts[row]*64+c4]:(ch==1)?&node[(size_t)srcs[row]*64+c4]
                     :&edge[(size_t)(ebase+row)*64+c4];
      cpa16(db+(row*68+c4)*4,s_,16);
    }
  };
  float C1[8][4];
  #pragma unroll
  for(int i=0;i<8;i++){C1[i][0]=0;C1[i][1]=0;C1[i][2]=0;C1[i][3]=0;}
  issueM(0,A0);cpacommit();
  for(int ch=0;ch<3;ch++){
    if(ch<2){issueM(ch+1,(ch&1)?A0:A1);cpacommit();}
    #define GETM(kk,nn) (w1[((ch)*64+(kk))*64+(nn)])
    STAGE_WBN(Wh,Wl,4,8,GETM);
    #undef GETM
    if(ch<2)cpawait<1>();else cpawait<0>();
    __syncthreads();
    mma_sweepN<8>((ch&1)?A1:A0,Wh,Wl,4,C1,mrow,tq,68);
    __syncthreads();
  }
  #pragma unroll
  for(int nt=0;nt<8;nt++){
    int col=nt*8+tq*2;
    A0[mrow*68+col]=fmaxf(C1[nt][0]+b1s[col],0.f);
    A0[mrow*68+col+1]=fmaxf(C1[nt][1]+b1s[col+1],0.f);
    A0[(mrow+8)*68+col]=fmaxf(C1[nt][2]+b1s[col],0.f);
    A0[(mrow+8)*68+col+1]=fmaxf(C1[nt][3]+b1s[col+1],0.f);
  }
  #define GETM2(kk,nn) (w2[(kk)*64+(nn)])
  STAGE_WBN(Wh,Wl,4,8,GETM2);
  #undef GETM2
  __syncthreads();
  float C2[8][4];
  #pragma unroll
  for(int i=0;i<8;i++){C2[i][0]=0;C2[i][1]=0;C2[i][2]=0;C2[i][3]=0;}
  mma_sweepN<8>(A0,Wh,Wl,4,C2,mrow,tq,68);
  const int d0=dsts[mrow],d1=dsts[mrow+8];
  #pragma unroll
  for(int nt=0;nt<8;nt++){
    int col=nt*8+tq*2;
    atomicAdd(&agg[(size_t)d0*64+col],C2[nt][0]+b2s[col]);
    atomicAdd(&agg[(size_t)d0*64+col+1],C2[nt][1]+b2s[col+1]);
    atomicAdd(&agg[(size_t)d1*64+col],C2[nt][2]+b2s[col]);
    atomicAdd(&agg[(size_t)d1*64+col+1],C2[nt][3]+b2s[col+1]);
  }
}

// --------------------------------------------- node_update: [x|cf]@W + LN
__global__ void __launch_bounds__(256) k_nodeup(const float* __restrict__ x,
    const float* __restrict__ cf, const float* __restrict__ w, const float* __restrict__ b,
    const float* __restrict__ g, const float* __restrict__ be, float* __restrict__ out) {
    extern __shared__ float sm[];
    float* Ws = sm;
    float* Bs = Ws + 6144; float* Gs = Bs + 64; float* BEs = Gs + 64;
    float* mu = BEs + 64; float* rs = mu + 64;
    float* As = rs + 64; float* Hs = As + 6400;
    int t = threadIdx.x;
    int Rbase = blockIdx.x * 64;
    for (int i = t; i < 6144; i += 256) Ws[i] = w[i];
    if (t < 64) { Bs[t]=b[t]; Gs[t]=g[t]; BEs[t]=be[t]; }
    for (int e = t; e < 2048; e += 256) {
        int row = e >> 5, c = e & 31, nd = Rbase + row;
        As[row * 100 + c] = (nd < NN) ? x[nd * 32 + c] : 0.f;
    }
    for (int e = t; e < 4096; e += 256) {
        int row = e >> 6, c = e & 63, nd = Rbase + row;
        As[row * 100 + 32 + c] = (nd < NN) ? cf[nd * 64 + c] : 0.f;
    }
    __syncthreads();
    int tr = t >> 4, tc = t & 15;
    float acc[4][4];
    float4 b4 = *(const float4*)&Bs[tc * 4];
    #pragma unroll
    for (int i = 0; i < 4; i++) { acc[i][0]=b4.x; acc[i][1]=b4.y; acc[i][2]=b4.z; acc[i][3]=b4.w; }
    for (int k = 0; k < 96; k++) {
        float4 w4 = *(const float4*)&Ws[k * 64 + tc * 4];
        #pragma unroll
        for (int i = 0; i < 4; i++) {
            float a = As[(tr * 4 + i) * 100 + k];
            acc[i][0] += a*w4.x; acc[i][1] += a*w4.y; acc[i][2] += a*w4.z; acc[i][3] += a*w4.w;
        }
    }
    #pragma unroll
    for (int i = 0; i < 4; i++) {
        float4 r; r.x=fmaxf(acc[i][0],0.f); r.y=fmaxf(acc[i][1],0.f);
        r.z=fmaxf(acc[i][2],0.f); r.w=fmaxf(acc[i][3],0.f);
        *(float4*)&Hs[(tr * 4 + i) * 68 + tc * 4] = r;
    }
    __syncthreads();
    if (t < 64) {
        float s = 0.f, sq = 0.f;
        for (int c = 0; c < 64; c++) { float v = Hs[t * 68 + c]; s += v; sq += v * v; }
        float m = s * (1.f / 64.f);
        mu[t] = m; rs[t] = rsqrtf(sq * (1.f / 64.f) - m * m + 1e-5f);
    }
    __syncthreads();
    for (int i = t; i < 4096; i += 256) {
        int r = i >> 6, c = i & 63, nd = Rbase + r;
        if (nd < NN) out[nd * 64 + c] = (Hs[r * 68 + c] - mu[r]) * rs[r] * Gs[c] + BEs[c];
    }
}

// --------------------------------------------- edge_update: ea@W + LN
__global__ void __launch_bounds__(256) k_edgeup(const float* __restrict__ ea,
    const float* __restrict__ w, const float* __restrict__ b,
    const float* __restrict__ g, const float* __restrict__ be, float* __restrict__ out) {
    __shared__ float Ws[384], Bs[64], Gs[64], BEs[64], Aa[64][8], Hs[64][68], mu[64], rs[64];
    int t = threadIdx.x;
    int ebase = blockIdx.x * 64;
    for (int i = t; i < 384; i += 256) Ws[i] = w[i];
    if (t < 64) { Bs[t]=b[t]; Gs[t]=g[t]; BEs[t]=be[t]; }
    for (int e = t; e < 384; e += 256) {
        int row = e / 6, k = e - row * 6;
        Aa[row][k] = ea[(size_t)(ebase + row) * 6 + k];
    }
    __syncthreads();
    int r = t >> 2, cg = (t & 3) * 16;
    float a0=Aa[r][0],a1=Aa[r][1],a2=Aa[r][2],a3=Aa[r][3],a4=Aa[r][4],a5=Aa[r][5];
    #pragma unroll
    for (int j = 0; j < 16; j++) {
        int c = cg + j;
        float h = Bs[c] + a0*Ws[c] + a1*Ws[64+c] + a2*Ws[128+c] + a3*Ws[192+c] + a4*Ws[256+c] + a5*Ws[320+c];
        Hs[r][c] = fmaxf(h, 0.f);
    }
    __syncthreads();
    if (t < 64) {
        float s = 0.f, sq = 0.f;
        for (int c = 0; c < 64; c++) { float v = Hs[t][c]; s += v; sq += v * v; }
        float m = s * (1.f / 64.f);
        mu[t] = m; rs[t] = rsqrtf(sq * (1.f / 64.f) - m * m + 1e-5f);
    }
    __syncthreads();
    for (int i = t; i < 4096; i += 256) {
        int rr = i >> 6, c = i & 63;
        out[(size_t)ebase * 64 + i] = (Hs[rr][c] - mu[rr]) * rs[rr] * Gs[c] + BEs[c];
    }
}

// ========= node MLP: [node|agg] 2-layer, 128 nodes/block, 4x8 per thread =====
__global__ void __launch_bounds__(256, 2) k_nodemlp(const float* __restrict__ node,
    const float* __restrict__ agg, const float* __restrict__ w1, const float* __restrict__ b1,
    const float* __restrict__ w2, const float* __restrict__ b2, float* __restrict__ out) {
    extern __shared__ float sm[];
    float* W1s = sm;
    float* W2s = W1s + 8192;
    float* B1s = W2s + 4096; float* B2s = B1s + 64;
    float* As = B2s + 64;
    const int t = threadIdx.x;
    const int Rbase = blockIdx.x * 128;
    for (int i = t; i < 8192; i += 256) W1s[i] = w1[i];
    for (int i = t; i < 4096; i += 256) W2s[i] = w2[i];
    if (t < 64) { B1s[t]=b1[t]; B2s[t]=b2[t]; }
    const int tr = t >> 3, tc = t & 7;
    const float* ar[4];
    #pragma unroll
    for (int i = 0; i < 4; i++) ar[i] = &As[(tr * 4 + i) * 65];
    float acc[4][8];
    for (int ch = 0; ch < 2; ch++) {
        __syncthreads();
        for (int e = t * 4; e < 8192; e += 1024) {
            int row = e >> 6, c4 = e & 63, nd = Rbase + row;
            float4 vv = make_float4(0.f,0.f,0.f,0.f);
            if (nd < NN) {
                const float* base = (ch == 0) ? &node[(size_t)nd * 64] : &agg[(size_t)nd * 64];
                vv = *(const float4*)&base[c4];
            }
            float* d = &As[row * 65 + c4];
            d[0]=vv.x; d[1]=vv.y; d[2]=vv.z; d[3]=vv.w;
        }
        __syncthreads();
        if (ch == 0) {
            float4 ba = *(const float4*)&B1s[tc * 8];
            float4 bb = *(const float4*)&B1s[tc * 8 + 4];
            #pragma unroll
            for (int i = 0; i < 4; i++) {
                acc[i][0]=ba.x;acc[i][1]=ba.y;acc[i][2]=ba.z;acc[i][3]=ba.w;
                acc[i][4]=bb.x;acc[i][5]=bb.y;acc[i][6]=bb.z;acc[i][7]=bb.w;
            }
        }
        const float* wp = &W1s[ch * 4096 + tc * 8];
        #pragma unroll 8
        for (int k = 0; k < 64; k++) {
            float4 wa = *(const float4*)&wp[k * 64];
            float4 wb = *(const float4*)&wp[k * 64 + 4];
            #pragma unroll
            for (int i = 0; i < 4; i++) {
                float a = ar[i][k];
                acc[i][0]+=a*wa.x; acc[i][1]+=a*wa.y; acc[i][2]+=a*wa.z; acc[i][3]+=a*wa.w;
                acc[i][4]+=a*wb.x; acc[i][5]+=a*wb.y; acc[i][6]+=a*wb.z; acc[i][7]+=a*wb.w;
            }
        }
    }
    __syncthreads();
    #pragma unroll
    for (int i = 0; i < 4; i++)
        #pragma unroll
        for (int j = 0; j < 8; j++)
            As[(tr * 4 + i) * 65 + tc * 8 + j] = fmaxf(acc[i][j], 0.f);
    __syncthreads();
    float a2[4][8];
    {
        float4 ba = *(const float4*)&B2s[tc * 8];
        float4 bb = *(const float4*)&B2s[tc * 8 + 4];
        #pragma unroll
        for (int i = 0; i < 4; i++) {
            a2[i][0]=ba.x;a2[i][1]=ba.y;a2[i][2]=ba.z;a2[i][3]=ba.w;
            a2[i][4]=bb.x;a2[i][5]=bb.y;a2[i][6]=bb.z;a2[i][7]=bb.w;
        }
    }
    const float* wp2 = &W2s[tc * 8];
    #pragma unroll 8
    for (int k = 0; k < 64; k++) {
        float4 wa = *(const float4*)&wp2[k * 64];
        float4 wb = *(const float4*)&wp2[k * 64 + 4];
        #pragma unroll
        for (int i = 0; i < 4; i++) {
            float a = ar[i][k];
            a2[i][0]+=a*wa.x; a2[i][1]+=a*wa.y; a2[i][2]+=a*wa.z; a2[i][3]+=a*wa.w;
            a2[i][4]+=a*wb.x; a2[i][5]+=a*wb.y; a2[i][6]+=a*wb.z; a2[i][7]+=a*wb.w;
        }
    }
    #pragma unroll
    for (int i = 0; i < 4; i++) {
        int nd = Rbase + tr * 4 + i;
        if (nd < NN) {
            float4 v;
            v.x=a2[i][0]; v.y=a2[i][1]; v.z=a2[i][2]; v.w=a2[i][3];
            *(float4*)&out[(size_t)nd * 64 + tc * 8] = v;
            v.x=a2[i][4]; v.y=a2[i][5]; v.z=a2[i][6]; v.w=a2[i][7];
            *(float4*)&out[(size_t)nd * 64 + tc * 8 + 4] = v;
        }
    }
}

// ===== final edge MLP (bf16 mma): 134->128->64->1, 128 edges/block ==========
__global__ void __launch_bounds__(256,2) k_final(const float* __restrict__ node,
    const float* __restrict__ ea,const int* __restrict__ ei,
    const float* __restrict__ w1,const float* __restrict__ b1,
    const float* __restrict__ w2,const float* __restrict__ b2,
    const float* __restrict__ w3,const float* __restrict__ b3,float* __restrict__ out){
  extern __shared__ float sm[];
  uint2* Wh=(uint2*)sm;            // 2048 uint2 (16 KB)
  uint2* Wl=Wh+2048;               // 16 KB
  float* B1s=(float*)(Wl+2048);    // 128
  float* B2s=B1s+128; float* w3s=B2s+64; float* b3s=w3s+64;  // 64+64+4
  float* HA=b3s+4;                 // 16896 floats (A tiles / H / H2, aliased)
  int* srcs=(int*)(HA+16896); int* dsts=srcs+128;
  const int t=threadIdx.x,lane=t&31,wid=t>>5;
  const int ebase=blockIdx.x*128;
  if(t<128){B1s[t]=b1[t];srcs[t]=ei[ebase+t];dsts[t]=ei[EE+ebase+t];}
  if(t<64){B2s[t]=b2[t];w3s[t]=w3[t];}
  if(t==0)b3s[0]=b3[0];
  const int g=lane>>2,tq=lane&3,mrow=wid*16+g;
  __syncthreads();
  float C1[16][4];
  #pragma unroll
  for(int i=0;i<16;i++){C1[i][0]=0;C1[i][1]=0;C1[i][2]=0;C1[i][3]=0;}
  for(int ch=0;ch<2;ch++){
    uint32_t db=(uint32_t)__cvta_generic_to_shared(HA);
    #pragma unroll
    for(int k_=0;k_<8;k_++){
      int idx=t+k_*256,row=idx>>4,c4=(idx&15)*4;
      const int nd=(ch==0)?srcs[row]:dsts[row];
      cpa16(db+(row*68+c4)*4,&node[(size_t)nd*64+c4],16);
    }
    cpacommit();
    #define GETF1(kk,nn) (w1[((ch)*64+(kk))*128+(nn)])
    STAGE_WBN(Wh,Wl,4,16,GETF1);
    #undef GETF1
    cpawait<0>();
    __syncthreads();
    mma_sweepN<16>(HA,Wh,Wl,4,C1,mrow,tq,68);
    __syncthreads();
  }
  // edge_attr chunk: K=6 padded to 16, stride 20
  for(int i=t;i<2560;i+=256)HA[i]=0.f;
  __syncthreads();
  for(int i=t;i<768;i+=256){int row=i/6,k=i-row*6;HA[row*20+k]=ea[(size_t)(ebase+row)*6+k];}
  #define GETFE(kk,nn) (((kk)<6)?w1[(128+(kk))*128+(nn)]:0.f)
  STAGE_WBN(Wh,Wl,1,16,GETFE);
  #undef GETFE
  __syncthreads();
  mma_sweepN<16>(HA,Wh,Wl,1,C1,mrow,tq,20);
  __syncthreads();
  // H = relu(C1+b1), stride 132
  #pragma unroll
  for(int nt=0;nt<16;nt++){
    int col=nt*8+tq*2;
    HA[mrow*132+col]      =fmaxf(C1[nt][0]+B1s[col],0.f);
    HA[mrow*132+col+1]    =fmaxf(C1[nt][1]+B1s[col+1],0.f);
    HA[(mrow+8)*132+col]  =fmaxf(C1[nt][2]+B1s[col],0.f);
    HA[(mrow+8)*132+col+1]=fmaxf(C1[nt][3]+B1s[col+1],0.f);
  }
  #define GETF2(kk,nn) (w2[(kk)*64+(nn)])
  STAGE_WBN(Wh,Wl,8,8,GETF2);
  #undef GETF2
  __syncthreads();
  float C2[8][4];
  #pragma unroll
  for(int i=0;i<8;i++){C2[i][0]=0;C2[i][1]=0;C2[i][2]=0;C2[i][3]=0;}
  mma_sweepN<8>(HA,Wh,Wl,8,C2,mrow,tq,132);
  __syncthreads();
  // H2 = relu(C2+b2), stride 68 (H dead)
  #pragma unroll
  for(int nt=0;nt<8;nt++){
    int col=nt*8+tq*2;
    HA[mrow*68+col]      =fmaxf(C2[nt][0]+B2s[col],0.f);
    HA[mrow*68+col+1]    =fmaxf(C2[nt][1]+B2s[col+1],0.f);
    HA[(mrow+8)*68+col]  =fmaxf(C2[nt][2]+B2s[col],0.f);
    HA[(mrow+8)*68+col+1]=fmaxf(C2[nt][3]+B2s[col+1],0.f);
  }
  __syncthreads();
  if(t<128){
    float s=b3s[0];
    #pragma unroll 8
    for(int c=0;c<64;c++)s+=HA[t*68+c]*w3s[c];
    out[ebase+t]=s;
  }
}

// ============================================================================
extern "C" void kernel_launch(void* const* d_in, const int* in_sizes, int n_in,
                              void* d_out, int out_size) {
    const float *x=0,*ea=0,*crop=0,*cw0=0,*cb0=0,*cw=0,*cb=0,*nu_w=0,*nu_b=0,*nu_g=0,*nu_be=0,
        *eu_w=0,*eu_b=0,*eu_g=0,*eu_be=0,*ie_w1=0,*ie_b1=0,*ie_w2=0,*ie_b2=0,
        *in_w1=0,*in_b1=0,*in_w2=0,*in_b2=0,*em_w1=0,*em_b1=0,*em_w2=0,*em_b2=0,*em_w3=0,*em_b3=0;
    const int* ei = 0;
    int c64 = 0, c256 = 0, c16k = 0;
    for (int i = 0; i < n_in; i++) {
        const float* p = (const float*)d_in[i];
        switch (in_sizes[i]) {
            case 320000: x = p; break;
            case 640000: ei = (const int*)p; break;
            case 1920000: ea = p; break;
            case 122880000: crop = p; break;
            case 768: cw0 = p; break;
            case 81920: cw = p; break;
            case 320: cb = p; break;
            case 6144: nu_w = p; break;
            case 384: eu_w = p; break;
            case 49152: ie_w1 = p; break;
            case 32768: in_w1 = p; break;
            case 17152: em_w1 = p; break;
            case 128: em_b1 = p; break;
            case 8192: em_w2 = p; break;
            case 1: em_b3 = p; break;
            case 16384: if (c16k++ == 0) ie_w2 = p; else in_w2 = p; break;
            case 256:
                if (c256 == 0) ie_b1 = p; else if (c256 == 1) ie_b2 = p;
                else if (c256 == 2) in_b1 = p; else in_b2 = p;
                c256++; break;
            case 64: {
                const float** slots[9] = {&cb0,&nu_b,&nu_g,&nu_be,&eu_b,&eu_g,&eu_be,&em_b2,&em_w3};
                if (c64 < 9) *slots[c64] = p;
                c64++; break;
            }
            default: break;
        }
    }
    float *b0, *b1, *cf, *nA, *nB, *agg, *edg;
    cudaGetSymbolAddress((void**)&b0, g_b0);
    cudaGetSymbolAddress((void**)&b1, g_b1);
    cudaGetSymbolAddress((void**)&cf, g_cf);
    cudaGetSymbolAddress((void**)&nA, g_nA);
    cudaGetSymbolAddress((void**)&nB, g_nB);
    cudaGetSymbolAddress((void**)&agg, g_agg);
    cudaGetSymbolAddress((void**)&edg, g_edge);

    const int SM_CNN = (2048 + 2048 + 512 + 512 + 64 + 64 + 8704 + 8704) * 4;
    const int SM_MSG = (2048 + 2048 + 64 + 64 + 8704 + 8704 + 256) * 4;
    const int SM_NU  = (6144 + 64 * 5 + 6400 + 4352 + 64) * 4;
    const int SM_NM  = (8192 + 4096 + 128 + 8320) * 4;
    const int SM_FIN = (4096 + 4096 + 128 + 64 + 64 + 4 + 16896 + 256) * 4;
    cudaFuncSetAttribute(k_cnn,     cudaFuncAttributeMaxDynamicSharedMemorySize, SM_CNN);
    cudaFuncSetAttribute(k_msg,     cudaFuncAttributeMaxDynamicSharedMemorySize, SM_MSG);
    cudaFuncSetAttribute(k_nodeup,  cudaFuncAttributeMaxDynamicSharedMemorySize, SM_NU);
    cudaFuncSetAttribute(k_nodemlp, cudaFuncAttributeMaxDynamicSharedMemorySize, SM_NM);
    cudaFuncSetAttribute(k_final,   cudaFuncAttributeMaxDynamicSharedMemorySize, SM_FIN);

    // CNN stack (layer 0: conv0 via mma inline)
    k_cnn<<<20000, 256, SM_CNN>>>(crop, crop, b1, cw0, cb0, cw,         cb,       4, NN*256, 1);
    k_cnn<<<5000,  256, SM_CNN>>>(crop, b1,   b0, cw0, cb0, cw + 16384, cb + 64,  3, NN*64,  0);
    k_cnn<<<1250,  256, SM_CNN>>>(crop, b0,   b1, cw0, cb0, cw + 32768, cb + 128, 2, NN*16,  0);
    k_cnn<<<313,   256, SM_CNN>>>(crop, b1,   b0, cw0, cb0, cw + 49152, cb + 192, 1, NN*4,   0);
    k_cnn<<<79,    256, SM_CNN>>>(crop, b0,   cf, cw0, cb0, cw + 65536, cb + 256, 0, NN,     0);
    // encoders
    k_nodeup<<<157, 256, SM_NU>>>(x, cf, nu_w, nu_b, nu_g, nu_be, nA);
    k_edgeup<<<5000, 256>>>(ea, eu_w, eu_b, eu_g, eu_be, edg);
    // 4 interaction layers
    float* cur = nA; float* nxt = nB;
    for (int l = 0; l < 4; l++) {
        cudaMemsetAsync(agg, 0, (size_t)NN * 64 * sizeof(float), 0);
        k_msg<<<2500, 256, SM_MSG>>>(cur, edg, ei, ie_w1 + l * 12288, ie_b1 + l * 64,
                                     ie_w2 + l * 4096, ie_b2 + l * 64, agg);
        k_nodemlp<<<79, 256, SM_NM>>>(cur, agg, in_w1 + l * 8192, in_b1 + l * 64,
                                      in_w2 + l * 4096, in_b2 + l * 64, nxt);
        float* tmp = cur; cur = nxt; nxt = tmp;
    }
    // final edge MLP (bf16 mma)
    k_final<<<2500, 256, SM_FIN>>>(cur, ea, ei, em_w1, em_b1, em_w2, em_b2,
                                   em_w3, em_b3, (float*)d_out);
}

// round 14
// speedup vs baseline: 5.2431x; 1.3108x over previous
#include <cuda_runtime.h>
#include <cstdint>

#define NN 10000
#define EE 320000

__device__ float g_b1[(size_t)NN*256*64];
__device__ float g_b0[(size_t)NN*64*64];
__device__ float g_cf[NN*64];
__device__ float g_nA[NN*64];
__device__ float g_nB[NN*64];
__device__ float g_agg[NN*64];
__device__ float g_edge[(size_t)EE*64];

// precomputed bf16 hi/lo weight fragments (slot-linear, sweep order)
// cnn: (l*4+p)*2048  [Wh 1024 | Wl 1024]         l=0..4
// w0 : 40960         [Wh 256  | Wl 256]
// msg: 41472+(l*4+u)*2048 (u=0..2 W1 ch, u=3 W2) [1024|1024]
// fin1: 74240+ch*4096 [2048|2048]; fine: 82432 [512|512]; fin2: 83456 [2048|2048]
__device__ __align__(16) uint2 g_wf[87552];

__device__ __forceinline__ unsigned packbf(float lo,float hi){
  unsigned r;asm("cvt.rn.bf16x2.f32 %0,%1,%2;":"=r"(r):"f"(hi),"f"(lo));return r;}
__device__ __forceinline__ float bflo(unsigned p){return __uint_as_float(p<<16);}
__device__ __forceinline__ float bfhi(unsigned p){return __uint_as_float(p&0xFFFF0000u);}
__device__ __forceinline__ void mmabf(float* c,unsigned a0,unsigned a1,unsigned a2,unsigned a3,unsigned b0,unsigned b1){
  asm("mma.sync.aligned.m16n8k16.row.col.f32.bf16.bf16.f32 {%0,%1,%2,%3},{%4,%5,%6,%7},{%8,%9},{%0,%1,%2,%3};"
      :"+f"(c[0]),"+f"(c[1]),"+f"(c[2]),"+f"(c[3]):"r"(a0),"r"(a1),"r"(a2),"r"(a3),"r"(b0),"r"(b1));}
__device__ __forceinline__ void cpa16(uint32_t d,const void* s,int sz){
  asm volatile("cp.async.cg.shared.global [%0],[%1],16,%2;"::"r"(d),"l"(s),"r"(sz));}
__device__ __forceinline__ void cpacommit(){asm volatile("cp.async.commit_group;");}
template<int N> __device__ __forceinline__ void cpawait(){asm volatile("cp.async.wait_group %0;"::"n"(N));}

// bf16 3-term sweep: K=16 per mma. A raw fp32 in smem; split in registers.
template<int NT>
__device__ __forceinline__ void mma_sweepN(const float* A,const uint2* Wh,const uint2* Wl,
    int KT,float C[][4],int mrow,int tq,int stride){
  const int lane=threadIdx.x&31;
  for(int kt=0;kt<KT;kt++){
    const float* ap=A+mrow*stride+kt*16+2*tq;
    float2 x0=*(const float2*)ap;
    float2 x1=*(const float2*)(ap+8*stride);
    float2 x2=*(const float2*)(ap+8);
    float2 x3=*(const float2*)(ap+8*stride+8);
    unsigned a0=packbf(x0.x,x0.y),a1=packbf(x1.x,x1.y),a2=packbf(x2.x,x2.y),a3=packbf(x3.x,x3.y);
    unsigned l0=packbf(x0.x-bflo(a0),x0.y-bfhi(a0)),l1=packbf(x1.x-bflo(a1),x1.y-bfhi(a1));
    unsigned l2=packbf(x2.x-bflo(a2),x2.y-bfhi(a2)),l3=packbf(x3.x-bflo(a3),x3.y-bfhi(a3));
    #pragma unroll
    for(int nt=0;nt<NT;nt++){
      int s=(kt*NT+nt)*32+lane;
      uint2 bh=Wh[s],bl=Wl[s];
      mmabf(C[nt],a0,a1,a2,a3,bh.x,bh.y);
      mmabf(C[nt],a0,a1,a2,a3,bl.x,bl.y);
      mmabf(C[nt],l0,l1,l2,l3,bh.x,bh.y);
    }
  }
}

// ----------------------- weight fragment prep kernels ------------------------
#define PREP_BODY(NSLOT,NT,BASE,GET) \
  for(int s=threadIdx.x;s<(NSLOT);s+=256){ \
    int lane=s&31,wd=s>>5,nt=wd%(NT),kt=wd/(NT); \
    int nn=nt*8+(lane>>2),k0=kt*16+(lane&3)*2; \
    float w00=GET(k0,nn),w01=GET((k0+1),nn),w10=GET((k0+8),nn),w11=GET((k0+9),nn); \
    unsigned h0=packbf(w00,w01),h1=packbf(w10,w11); \
    g_wf[(BASE)+s]=make_uint2(h0,h1); \
    g_wf[(BASE)+(NSLOT)+s]=make_uint2(packbf(w00-bflo(h0),w01-bfhi(h0)),packbf(w10-bflo(h1),w11-bfhi(h1))); \
  }

__global__ void k_prep_cnn(const float* __restrict__ cw){
  int l=blockIdx.x>>2,p=blockIdx.x&3;
  const float* w=cw+l*16384;
  #define G(kk,nn) (w[(nn)*256+(kk)*4+p])
  PREP_BODY(1024,8,(l*4+p)*2048,G)
  #undef G
}
__global__ void k_prep_w0(const float* __restrict__ w0){
  #define G(kk,nn) (((kk)<12)?w0[(nn)*12+(kk)]:0.f)
  PREP_BODY(256,8,40960,G)
  #undef G
}
__global__ void k_prep_msg(const float* __restrict__ w1,const float* __restrict__ w2){
  int l=blockIdx.x>>2,u=blockIdx.x&3;
  const float* wp=(u<3)?(w1+l*12288+u*4096):(w2+l*4096);
  #define G(kk,nn) (wp[(kk)*64+(nn)])
  PREP_BODY(1024,8,41472+(l*4+u)*2048,G)
  #undef G
}
__global__ void k_prep_fin(const float* __restrict__ w1,const float* __restrict__ w2){
  int b=blockIdx.x;
  if(b<2){
    #define G(kk,nn) (w1[((b)*64+(kk))*128+(nn)])
    PREP_BODY(2048,16,74240+b*4096,G)
    #undef G
  } else if(b==2){
    #define G(kk,nn) (((kk)<6)?w1[(128+(kk))*128+(nn)]:0.f)
    PREP_BODY(512,16,82432,G)
    #undef G
  } else {
    #define G(kk,nn) (w2[(kk)*64+(nn)])
    PREP_BODY(2048,8,83456,G)
    #undef G
  }
}

// copy n uint2 fragments g_wf[gbase..] -> smem buf (coalesced cp.async)
__device__ __forceinline__ void issueWF(uint2* buf,int gbase,int n){
  uint32_t db=(uint32_t)__cvta_generic_to_shared(buf);
  const uint2* src=g_wf+gbase;
  for(int j=threadIdx.x*2;j<n;j+=512) cpa16(db+j*8,src+j,16);
}

// ===== unified CNN layer (bf16 mma); L0: conv0 via mma; W frags precomputed ==
__global__ void __launch_bounds__(256,2) k_cnn(const float* __restrict__ crop,
    const float* __restrict__ in,float* __restrict__ out,
    const float* __restrict__ b0c,const float* __restrict__ b,
    int so_bits,int M,int L0,int lidx){
  extern __shared__ float sm[];
  uint2* Wb0=(uint2*)sm;               // 2048 uint2
  uint2* Wb1=Wb0+2048;                 // 2048
  uint2* W0f=Wb1+2048;                 // 512
  float* b0s=(float*)(W0f+512);        // 64
  float* bs=b0s+64;                    // 64
  float* A0=bs+64;                     // 8704
  float* A1=A0+8704;                   // 8704 (!L0 double buffer; L0: crop + Ap)
  float* Ap=A1+6144;                   // L0: 128*20
  const int t=threadIdx.x,lane=t&31,wid=t>>5;
  const int Rbase=blockIdx.x*128;
  const int S_out=1<<so_bits,S_in=S_out<<1,so2=so_bits*2;
  const int half=(Rbase>>7)&1;
  if(L0){
    issueWF(W0f,40960,512);
    if(t<64)b0s[t]=b0c[t];
    int n=Rbase>>8;
    for(int i=t*4;i<6144;i+=1024){
      int c=i>>11,r=i&2047,y=r>>6,xx=r&63;
      *(float4*)&A1[i]=*(const float4*)&crop[(((size_t)n*3+c)*64+half*32+y)*64+xx];
    }
  }
  if(t<64)bs[t]=b[t];
  const int g=lane>>2,tq=lane&3,mrow=wid*16+g;
  const int wfb=lidx*4;
  auto issueA=[&](int pp,float* buf){
    int ky_=pp>>1,kx_=pp&1;
    uint32_t db=(uint32_t)__cvta_generic_to_shared(buf);
    #pragma unroll
    for(int k_=0;k_<8;k_++){
      int idx=t+k_*256,row=idx>>4,c4=(idx&15)*4,R=Rbase+row;
      const float* s_=in; int sz_=0;
      if(R<M){int n_=R>>so2,sp_=R&(S_out*S_out-1),oy_=sp_>>so_bits,ox_=sp_&(S_out-1);
        s_=&in[(((size_t)n_*S_in+2*oy_+ky_)*S_in+2*ox_+kx_)*64+c4];sz_=16;}
      cpa16(db+(row*68+c4)*4,s_,sz_);
    }
  };
  float C[8][4];
  #pragma unroll
  for(int i=0;i<8;i++){C[i][0]=0;C[i][1]=0;C[i][2]=0;C[i][3]=0;}
  if(!L0)issueA(0,A0);
  issueWF(Wb0,(wfb+0)*2048,2048);
  cpacommit();
  __syncthreads();   // L0: crop window visible before Ap builds
  for(int p=0;p<4;p++){
    const int ky=p>>1,kx=p&1;
    if(p<3){
      if(!L0)issueA(p+1,(p&1)?A0:A1);
      issueWF((p&1)?Wb0:Wb1,(wfb+p+1)*2048,2048);
      cpacommit();
    }
    if(L0){
      for(int i=t;i<2048;i+=256){
        int row=i>>4,col=i&15; float v=0.f;
        if(col<12){
          int sp=(Rbase+row)&255,oy=sp>>4,ox=sp&15;
          int oyl=oy-half*8;
          int c=col>>2,q=col&3;
          v=A1[c*2048+(4*oyl+2*ky+(q>>1))*64+4*ox+2*kx+(q&1)];
        }
        Ap[row*20+col]=v;
      }
    }
    if(p<3)cpawait<1>();else cpawait<0>();
    __syncthreads();
    uint2* Wb=(p&1)?Wb1:Wb0;
    if(L0){
      float C0[8][4];
      #pragma unroll
      for(int i=0;i<8;i++){C0[i][0]=0;C0[i][1]=0;C0[i][2]=0;C0[i][3]=0;}
      mma_sweepN<8>(Ap,W0f,W0f+256,1,C0,mrow,tq,20);
      #pragma unroll
      for(int nt=0;nt<8;nt++){
        int col=nt*8+tq*2;
        A0[mrow*68+col]=fmaxf(C0[nt][0]+b0s[col],0.f);
        A0[mrow*68+col+1]=fmaxf(C0[nt][1]+b0s[col+1],0.f);
        A0[(mrow+8)*68+col]=fmaxf(C0[nt][2]+b0s[col],0.f);
        A0[(mrow+8)*68+col+1]=fmaxf(C0[nt][3]+b0s[col+1],0.f);
      }
      __syncthreads();
    }
    mma_sweepN<8>(L0?A0:((p&1)?A1:A0),Wb,Wb+1024,4,C,mrow,tq,68);
    __syncthreads();
  }
  #pragma unroll
  for(int nt=0;nt<8;nt++){
    int col=nt*8+tq*2,r0=Rbase+mrow,r1=r0+8;
    if(r0<M){float2 v;v.x=fmaxf(C[nt][0]+bs[col],0.f);v.y=fmaxf(C[nt][1]+bs[col+1],0.f);
      *(float2*)&out[(size_t)r0*64+col]=v;}
    if(r1<M){float2 v;v.x=fmaxf(C[nt][2]+bs[col],0.f);v.y=fmaxf(C[nt][3]+bs[col+1],0.f);
      *(float2*)&out[(size_t)r1*64+col]=v;}
  }
}

// ====== msg MLP (192->64->64) + scatter-add, bf16 mma, frag pipeline ========
__global__ void __launch_bounds__(256,2) k_msg(const float* __restrict__ node,
    const float* __restrict__ edge,const int* __restrict__ ei,
    const float* __restrict__ b1,const float* __restrict__ b2,
    int mbase,float* __restrict__ agg){
  extern __shared__ float sm[];
  uint2* Wb0=(uint2*)sm; uint2* Wb1=Wb0+2048;
  float* b1s=(float*)(Wb1+2048); float* b2s=b1s+64;
  float* A0=b2s+64; float* A1=A0+8704;
  int* srcs=(int*)(A1+8704); int* dsts=srcs+128;
  const int t=threadIdx.x,lane=t&31,wid=t>>5;
  const int ebase=blockIdx.x*128;
  if(t<64){b1s[t]=b1[t];b2s[t]=b2[t];}
  if(t<128){srcs[t]=ei[ebase+t];dsts[t]=ei[EE+ebase+t];}
  const int g=lane>>2,tq=lane&3,mrow=wid*16+g;
  __syncthreads();
  auto issueM=[&](int ch,float* buf){
    uint32_t db=(uint32_t)__cvta_generic_to_shared(buf);
    #pragma unroll
    for(int k_=0;k_<8;k_++){
      int idx=t+k_*256,row=idx>>4,c4=(idx&15)*4;
      const float* s_=(ch==0)?&node[(size_t)dsts[row]*64+c4]:(ch==1)?&node[(size_t)srcs[row]*64+c4]
                     :&edge[(size_t)(ebase+row)*64+c4];
      cpa16(db+(row*68+c4)*4,s_,16);
    }
  };
  float C1[8][4];
  #pragma unroll
  for(int i=0;i<8;i++){C1[i][0]=0;C1[i][1]=0;C1[i][2]=0;C1[i][3]=0;}
  issueM(0,A0);issueWF(Wb0,mbase,2048);cpacommit();
  for(int ch=0;ch<3;ch++){
    if(ch<2){
      issueM(ch+1,(ch&1)?A0:A1);
      issueWF((ch&1)?Wb0:Wb1,mbase+(ch+1)*2048,2048);
      cpacommit();
    } else {
      issueWF(Wb1,mbase+3*2048,2048);   // W2
      cpacommit();
    }
    cpawait<1>();
    __syncthreads();
    mma_sweepN<8>((ch&1)?A1:A0,(ch&1)?Wb1:Wb0,((ch&1)?Wb1:Wb0)+1024,4,C1,mrow,tq,68);
    __syncthreads();
  }
  #pragma unroll
  for(int nt=0;nt<8;nt++){
    int col=nt*8+tq*2;
    A0[mrow*68+col]=fmaxf(C1[nt][0]+b1s[col],0.f);
    A0[mrow*68+col+1]=fmaxf(C1[nt][1]+b1s[col+1],0.f);
    A0[(mrow+8)*68+col]=fmaxf(C1[nt][2]+b1s[col],0.f);
    A0[(mrow+8)*68+col+1]=fmaxf(C1[nt][3]+b1s[col+1],0.f);
  }
  cpawait<0>();
  __syncthreads();
  float C2[8][4];
  #pragma unroll
  for(int i=0;i<8;i++){C2[i][0]=0;C2[i][1]=0;C2[i][2]=0;C2[i][3]=0;}
  mma_sweepN<8>(A0,Wb1,Wb1+1024,4,C2,mrow,tq,68);
  const int d0=dsts[mrow],d1=dsts[mrow+8];
  #pragma unroll
  for(int nt=0;nt<8;nt++){
    int col=nt*8+tq*2;
    atomicAdd(&agg[(size_t)d0*64+col],C2[nt][0]+b2s[col]);
    atomicAdd(&agg[(size_t)d0*64+col+1],C2[nt][1]+b2s[col+1]);
    atomicAdd(&agg[(size_t)d1*64+col],C2[nt][2]+b2s[col]);
    atomicAdd(&agg[(size_t)d1*64+col+1],C2[nt][3]+b2s[col+1]);
  }
}

// --------------------------------------------- node_update: [x|cf]@W + LN
__global__ void __launch_bounds__(256) k_nodeup(const float* __restrict__ x,
    const float* __restrict__ cf, const float* __restrict__ w, const float* __restrict__ b,
    const float* __restrict__ g, const float* __restrict__ be, float* __restrict__ out) {
    extern __shared__ float sm[];
    float* Ws = sm;
    float* Bs = Ws + 6144; float* Gs = Bs + 64; float* BEs = Gs + 64;
    float* mu = BEs + 64; float* rs = mu + 64;
    float* As = rs + 64; float* Hs = As + 6400;
    int t = threadIdx.x;
    int Rbase = blockIdx.x * 64;
    for (int i = t; i < 6144; i += 256) Ws[i] = w[i];
    if (t < 64) { Bs[t]=b[t]; Gs[t]=g[t]; BEs[t]=be[t]; }
    for (int e = t; e < 2048; e += 256) {
        int row = e >> 5, c = e & 31, nd = Rbase + row;
        As[row * 100 + c] = (nd < NN) ? x[nd * 32 + c] : 0.f;
    }
    for (int e = t; e < 4096; e += 256) {
        int row = e >> 6, c = e & 63, nd = Rbase + row;
        As[row * 100 + 32 + c] = (nd < NN) ? cf[nd * 64 + c] : 0.f;
    }
    __syncthreads();
    int tr = t >> 4, tc = t & 15;
    float acc[4][4];
    float4 b4 = *(const float4*)&Bs[tc * 4];
    #pragma unroll
    for (int i = 0; i < 4; i++) { acc[i][0]=b4.x; acc[i][1]=b4.y; acc[i][2]=b4.z; acc[i][3]=b4.w; }
    for (int k = 0; k < 96; k++) {
        float4 w4 = *(const float4*)&Ws[k * 64 + tc * 4];
        #pragma unroll
        for (int i = 0; i < 4; i++) {
            float a = As[(tr * 4 + i) * 100 + k];
            acc[i][0] += a*w4.x; acc[i][1] += a*w4.y; acc[i][2] += a*w4.z; acc[i][3] += a*w4.w;
        }
    }
    #pragma unroll
    for (int i = 0; i < 4; i++) {
        float4 r; r.x=fmaxf(acc[i][0],0.f); r.y=fmaxf(acc[i][1],0.f);
        r.z=fmaxf(acc[i][2],0.f); r.w=fmaxf(acc[i][3],0.f);
        *(float4*)&Hs[(tr * 4 + i) * 68 + tc * 4] = r;
    }
    __syncthreads();
    if (t < 64) {
        float s = 0.f, sq = 0.f;
        for (int c = 0; c < 64; c++) { float v = Hs[t * 68 + c]; s += v; sq += v * v; }
        float m = s * (1.f / 64.f);
        mu[t] = m; rs[t] = rsqrtf(sq * (1.f / 64.f) - m * m + 1e-5f);
    }
    __syncthreads();
    for (int i = t; i < 4096; i += 256) {
        int r = i >> 6, c = i & 63, nd = Rbase + r;
        if (nd < NN) out[nd * 64 + c] = (Hs[r * 68 + c] - mu[r]) * rs[r] * Gs[c] + BEs[c];
    }
}

// --------------------------------------------- edge_update: ea@W + LN
__global__ void __launch_bounds__(256) k_edgeup(const float* __restrict__ ea,
    const float* __restrict__ w, const float* __restrict__ b,
    const float* __restrict__ g, const float* __restrict__ be, float* __restrict__ out) {
    __shared__ float Ws[384], Bs[64], Gs[64], BEs[64], Aa[64][8], Hs[64][68], mu[64], rs[64];
    int t = threadIdx.x;
    int ebase = blockIdx.x * 64;
    for (int i = t; i < 384; i += 256) Ws[i] = w[i];
    if (t < 64) { Bs[t]=b[t]; Gs[t]=g[t]; BEs[t]=be[t]; }
    for (int e = t; e < 384; e += 256) {
        int row = e / 6, k = e - row * 6;
        Aa[row][k] = ea[(size_t)(ebase + row) * 6 + k];
    }
    __syncthreads();
    int r = t >> 2, cg = (t & 3) * 16;
    float a0=Aa[r][0],a1=Aa[r][1],a2=Aa[r][2],a3=Aa[r][3],a4=Aa[r][4],a5=Aa[r][5];
    #pragma unroll
    for (int j = 0; j < 16; j++) {
        int c = cg + j;
        float h = Bs[c] + a0*Ws[c] + a1*Ws[64+c] + a2*Ws[128+c] + a3*Ws[192+c] + a4*Ws[256+c] + a5*Ws[320+c];
        Hs[r][c] = fmaxf(h, 0.f);
    }
    __syncthreads();
    if (t < 64) {
        float s = 0.f, sq = 0.f;
        for (int c = 0; c < 64; c++) { float v = Hs[t][c]; s += v; sq += v * v; }
        float m = s * (1.f / 64.f);
        mu[t] = m; rs[t] = rsqrtf(sq * (1.f / 64.f) - m * m + 1e-5f);
    }
    __syncthreads();
    for (int i = t; i < 4096; i += 256) {
        int rr = i >> 6, c = i & 63;
        out[(size_t)ebase * 64 + i] = (Hs[rr][c] - mu[rr]) * rs[rr] * Gs[c] + BEs[c];
    }
}

// ========= node MLP: [node|agg] 2-layer, 128 nodes/block, 4x8 per thread =====
__global__ void __launch_bounds__(256, 2) k_nodemlp(const float* __restrict__ node,
    const float* __restrict__ agg, const float* __restrict__ w1, const float* __restrict__ b1,
    const float* __restrict__ w2, const float* __restrict__ b2, float* __restrict__ out) {
    extern __shared__ float sm[];
    float* W1s = sm;
    float* W2s = W1s + 8192;
    float* B1s = W2s + 4096; float* B2s = B1s + 64;
    float* As = B2s + 64;
    const int t = threadIdx.x;
    const int Rbase = blockIdx.x * 128;
    for (int i = t; i < 8192; i += 256) W1s[i] = w1[i];
    for (int i = t; i < 4096; i += 256) W2s[i] = w2[i];
    if (t < 64) { B1s[t]=b1[t]; B2s[t]=b2[t]; }
    const int tr = t >> 3, tc = t & 7;
    const float* ar[4];
    #pragma unroll
    for (int i = 0; i < 4; i++) ar[i] = &As[(tr * 4 + i) * 65];
    float acc[4][8];
    for (int ch = 0; ch < 2; ch++) {
        __syncthreads();
        for (int e = t * 4; e < 8192; e += 1024) {
            int row = e >> 6, c4 = e & 63, nd = Rbase + row;
            float4 vv = make_float4(0.f,0.f,0.f,0.f);
            if (nd < NN) {
                const float* base = (ch == 0) ? &node[(size_t)nd * 64] : &agg[(size_t)nd * 64];
                vv = *(const float4*)&base[c4];
            }
            float* d = &As[row * 65 + c4];
            d[0]=vv.x; d[1]=vv.y; d[2]=vv.z; d[3]=vv.w;
        }
        __syncthreads();
        if (ch == 0) {
            float4 ba = *(const float4*)&B1s[tc * 8];
            float4 bb = *(const float4*)&B1s[tc * 8 + 4];
            #pragma unroll
            for (int i = 0; i < 4; i++) {
                acc[i][0]=ba.x;acc[i][1]=ba.y;acc[i][2]=ba.z;acc[i][3]=ba.w;
                acc[i][4]=bb.x;acc[i][5]=bb.y;acc[i][6]=bb.z;acc[i][7]=bb.w;
            }
        }
        const float* wp = &W1s[ch * 4096 + tc * 8];
        #pragma unroll 8
        for (int k = 0; k < 64; k++) {
            float4 wa = *(const float4*)&wp[k * 64];
            float4 wb = *(const float4*)&wp[k * 64 + 4];
            #pragma unroll
            for (int i = 0; i < 4; i++) {
                float a = ar[i][k];
                acc[i][0]+=a*wa.x; acc[i][1]+=a*wa.y; acc[i][2]+=a*wa.z; acc[i][3]+=a*wa.w;
                acc[i][4]+=a*wb.x; acc[i][5]+=a*wb.y; acc[i][6]+=a*wb.z; acc[i][7]+=a*wb.w;
            }
        }
    }
    __syncthreads();
    #pragma unroll
    for (int i = 0; i < 4; i++)
        #pragma unroll
        for (int j = 0; j < 8; j++)
            As[(tr * 4 + i) * 65 + tc * 8 + j] = fmaxf(acc[i][j], 0.f);
    __syncthreads();
    float a2[4][8];
    {
        float4 ba = *(const float4*)&B2s[tc * 8];
        float4 bb = *(const float4*)&B2s[tc * 8 + 4];
        #pragma unroll
        for (int i = 0; i < 4; i++) {
            a2[i][0]=ba.x;a2[i][1]=ba.y;a2[i][2]=ba.z;a2[i][3]=ba.w;
            a2[i][4]=bb.x;a2[i][5]=bb.y;a2[i][6]=bb.z;a2[i][7]=bb.w;
        }
    }
    const float* wp2 = &W2s[tc * 8];
    #pragma unroll 8
    for (int k = 0; k < 64; k++) {
        float4 wa = *(const float4*)&wp2[k * 64];
        float4 wb = *(const float4*)&wp2[k * 64 + 4];
        #pragma unroll
        for (int i = 0; i < 4; i++) {
            float a = ar[i][k];
            a2[i][0]+=a*wa.x; a2[i][1]+=a*wa.y; a2[i][2]+=a*wa.z; a2[i][3]+=a*wa.w;
            a2[i][4]+=a*wb.x; a2[i][5]+=a*wb.y; a2[i][6]+=a*wb.z; a2[i][7]+=a*wb.w;
        }
    }
    #pragma unroll
    for (int i = 0; i < 4; i++) {
        int nd = Rbase + tr * 4 + i;
        if (nd < NN) {
            float4 v;
            v.x=a2[i][0]; v.y=a2[i][1]; v.z=a2[i][2]; v.w=a2[i][3];
            *(float4*)&out[(size_t)nd * 64 + tc * 8] = v;
            v.x=a2[i][4]; v.y=a2[i][5]; v.z=a2[i][6]; v.w=a2[i][7];
            *(float4*)&out[(size_t)nd * 64 + tc * 8 + 4] = v;
        }
    }
}

// ===== final edge MLP (bf16 mma): 134->128->64->1, 128 edges/block ==========
__global__ void __launch_bounds__(256,2) k_final(const float* __restrict__ node,
    const float* __restrict__ ea,const int* __restrict__ ei,
    const float* __restrict__ b1,const float* __restrict__ b2,
    const float* __restrict__ w3,const float* __restrict__ b3,float* __restrict__ out){
  extern __shared__ float sm[];
  uint2* Wb=(uint2*)sm;            // 4096 uint2 (32 KB)
  float* B1s=(float*)(Wb+4096);    // 128
  float* B2s=B1s+128; float* w3s=B2s+64; float* b3s=w3s+64;
  float* HA=b3s+4;                 // 16896 floats (A / H / H2 aliased)
  int* srcs=(int*)(HA+16896); int* dsts=srcs+128;
  const int t=threadIdx.x,lane=t&31,wid=t>>5;
  const int ebase=blockIdx.x*128;
  if(t<128){B1s[t]=b1[t];srcs[t]=ei[ebase+t];dsts[t]=ei[EE+ebase+t];}
  if(t<64){B2s[t]=b2[t];w3s[t]=w3[t];}
  if(t==0)b3s[0]=b3[0];
  const int g=lane>>2,tq=lane&3,mrow=wid*16+g;
  __syncthreads();
  float C1[16][4];
  #pragma unroll
  for(int i=0;i<16;i++){C1[i][0]=0;C1[i][1]=0;C1[i][2]=0;C1[i][3]=0;}
  for(int ch=0;ch<2;ch++){
    uint32_t db=(uint32_t)__cvta_generic_to_shared(HA);
    #pragma unroll
    for(int k_=0;k_<8;k_++){
      int idx=t+k_*256,row=idx>>4,c4=(idx&15)*4;
      const int nd=(ch==0)?srcs[row]:dsts[row];
      cpa16(db+(row*68+c4)*4,&node[(size_t)nd*64+c4],16);
    }
    issueWF(Wb,74240+ch*4096,4096);
    cpacommit();
    cpawait<0>();
    __syncthreads();
    mma_sweepN<16>(HA,Wb,Wb+2048,4,C1,mrow,tq,68);
    __syncthreads();
  }
  // edge_attr chunk: K=6 padded to 16, stride 20
  for(int i=t;i<2560;i+=256)HA[i]=0.f;
  issueWF(Wb,82432,1024);
  cpacommit();
  __syncthreads();
  for(int i=t;i<768;i+=256){int row=i/6,k=i-row*6;HA[row*20+k]=ea[(size_t)(ebase+row)*6+k];}
  cpawait<0>();
  __syncthreads();
  mma_sweepN<16>(HA,Wb,Wb+512,1,C1,mrow,tq,20);
  __syncthreads();
  // H = relu(C1+b1), stride 132
  issueWF(Wb,83456,4096);
  cpacommit();
  #pragma unroll
  for(int nt=0;nt<16;nt++){
    int col=nt*8+tq*2;
    HA[mrow*132+col]      =fmaxf(C1[nt][0]+B1s[col],0.f);
    HA[mrow*132+col+1]    =fmaxf(C1[nt][1]+B1s[col+1],0.f);
    HA[(mrow+8)*132+col]  =fmaxf(C1[nt][2]+B1s[col],0.f);
    HA[(mrow+8)*132+col+1]=fmaxf(C1[nt][3]+B1s[col+1],0.f);
  }
  cpawait<0>();
  __syncthreads();
  float C2[8][4];
  #pragma unroll
  for(int i=0;i<8;i++){C2[i][0]=0;C2[i][1]=0;C2[i][2]=0;C2[i][3]=0;}
  mma_sweepN<8>(HA,Wb,Wb+2048,8,C2,mrow,tq,132);
  __syncthreads();
  #pragma unroll
  for(int nt=0;nt<8;nt++){
    int col=nt*8+tq*2;
    HA[mrow*68+col]      =fmaxf(C2[nt][0]+B2s[col],0.f);
    HA[mrow*68+col+1]    =fmaxf(C2[nt][1]+B2s[col+1],0.f);
    HA[(mrow+8)*68+col]  =fmaxf(C2[nt][2]+B2s[col],0.f);
    HA[(mrow+8)*68+col+1]=fmaxf(C2[nt][3]+B2s[col+1],0.f);
  }
  __syncthreads();
  if(t<128){
    float s=b3s[0];
    #pragma unroll 8
    for(int c=0;c<64;c++)s+=HA[t*68+c]*w3s[c];
    out[ebase+t]=s;
  }
}

// ============================================================================
extern "C" void kernel_launch(void* const* d_in, const int* in_sizes, int n_in,
                              void* d_out, int out_size) {
    const float *x=0,*ea=0,*crop=0,*cw0=0,*cb0=0,*cw=0,*cb=0,*nu_w=0,*nu_b=0,*nu_g=0,*nu_be=0,
        *eu_w=0,*eu_b=0,*eu_g=0,*eu_be=0,*ie_w1=0,*ie_b1=0,*ie_w2=0,*ie_b2=0,
        *in_w1=0,*in_b1=0,*in_w2=0,*in_b2=0,*em_w1=0,*em_b1=0,*em_w2=0,*em_b2=0,*em_w3=0,*em_b3=0;
    const int* ei = 0;
    int c64 = 0, c256 = 0, c16k = 0;
    for (int i = 0; i < n_in; i++) {
        const float* p = (const float*)d_in[i];
        switch (in_sizes[i]) {
            case 320000: x = p; break;
            case 640000: ei = (const int*)p; break;
            case 1920000: ea = p; break;
            case 122880000: crop = p; break;
            case 768: cw0 = p; break;
            case 81920: cw = p; break;
            case 320: cb = p; break;
            case 6144: nu_w = p; break;
            case 384: eu_w = p; break;
            case 49152: ie_w1 = p; break;
            case 32768: in_w1 = p; break;
            case 17152: em_w1 = p; break;
            case 128: em_b1 = p; break;
            case 8192: em_w2 = p; break;
            case 1: em_b3 = p; break;
            case 16384: if (c16k++ == 0) ie_w2 = p; else in_w2 = p; break;
            case 256:
                if (c256 == 0) ie_b1 = p; else if (c256 == 1) ie_b2 = p;
                else if (c256 == 2) in_b1 = p; else in_b2 = p;
                c256++; break;
            case 64: {
                const float** slots[9] = {&cb0,&nu_b,&nu_g,&nu_be,&eu_b,&eu_g,&eu_be,&em_b2,&em_w3};
                if (c64 < 9) *slots[c64] = p;
                c64++; break;
            }
            default: break;
        }
    }
    float *b0, *b1, *cf, *nA, *nB, *agg, *edg;
    cudaGetSymbolAddress((void**)&b0, g_b0);
    cudaGetSymbolAddress((void**)&b1, g_b1);
    cudaGetSymbolAddress((void**)&cf, g_cf);
    cudaGetSymbolAddress((void**)&nA, g_nA);
    cudaGetSymbolAddress((void**)&nB, g_nB);
    cudaGetSymbolAddress((void**)&agg, g_agg);
    cudaGetSymbolAddress((void**)&edg, g_edge);

    const int SM_CNN = (4608 * 2 + 64 + 64 + 8704 + 8704) * 4;
    const int SM_MSG = (4096 * 2 + 64 + 64 + 8704 + 8704 + 256) * 4;
    const int SM_NU  = (6144 + 64 * 5 + 6400 + 4352 + 64) * 4;
    const int SM_NM  = (8192 + 4096 + 128 + 8320) * 4;
    const int SM_FIN = (4096 * 2 + 128 + 64 + 64 + 4 + 16896 + 256) * 4;
    cudaFuncSetAttribute(k_cnn,     cudaFuncAttributeMaxDynamicSharedMemorySize, SM_CNN);
    cudaFuncSetAttribute(k_msg,     cudaFuncAttributeMaxDynamicSharedMemorySize, SM_MSG);
    cudaFuncSetAttribute(k_nodeup,  cudaFuncAttributeMaxDynamicSharedMemorySize, SM_NU);
    cudaFuncSetAttribute(k_nodemlp, cudaFuncAttributeMaxDynamicSharedMemorySize, SM_NM);
    cudaFuncSetAttribute(k_final,   cudaFuncAttributeMaxDynamicSharedMemorySize, SM_FIN);

    // weight fragment prep (once per launch; cheap)
    k_prep_cnn<<<20, 256>>>(cw);
    k_prep_w0<<<1, 256>>>(cw0);
    k_prep_msg<<<16, 256>>>(ie_w1, ie_w2);
    k_prep_fin<<<4, 256>>>(em_w1, em_w2);

    // CNN stack (layer 0: conv0 via mma inline)
    k_cnn<<<20000, 256, SM_CNN>>>(crop, crop, b1, cb0, cb,       4, NN*256, 1, 0);
    k_cnn<<<5000,  256, SM_CNN>>>(crop, b1,   b0, cb0, cb + 64,  3, NN*64,  0, 1);
    k_cnn<<<1250,  256, SM_CNN>>>(crop, b0,   b1, cb0, cb + 128, 2, NN*16,  0, 2);
    k_cnn<<<313,   256, SM_CNN>>>(crop, b1,   b0, cb0, cb + 192, 1, NN*4,   0, 3);
    k_cnn<<<79,    256, SM_CNN>>>(crop, b0,   cf, cb0, cb + 256, 0, NN,     0, 4);
    // encoders
    k_nodeup<<<157, 256, SM_NU>>>(x, cf, nu_w, nu_b, nu_g, nu_be, nA);
    k_edgeup<<<5000, 256>>>(ea, eu_w, eu_b, eu_g, eu_be, edg);
    // 4 interaction layers
    float* cur = nA; float* nxt = nB;
    for (int l = 0; l < 4; l++) {
        cudaMemsetAsync(agg, 0, (size_t)NN * 64 * sizeof(float), 0);
        k_msg<<<2500, 256, SM_MSG>>>(cur, edg, ei, ie_b1 + l * 64, ie_b2 + l * 64,
                                     41472 + l * 8192, agg);
        k_nodemlp<<<79, 256, SM_NM>>>(cur, agg, in_w1 + l * 8192, in_b1 + l * 64,
                                      in_w2 + l * 4096, in_b2 + l * 64, nxt);
        float* tmp = cur; cur = nxt; nxt = tmp;
    }
    // final edge MLP (bf16 mma)
    k_final<<<2500, 256, SM_FIN>>>(cur, ea, ei, em_b1, em_b2, em_w3, em_b3, (float*)d_out);
}

// round 16
// speedup vs baseline: 5.3549x; 1.0213x over previous
#include <cuda_runtime.h>
#include <cstdint>

#define NN 10000
#define EE 320000

// packed bf16 activation planes (hi/lo) for CNN intermediates
__device__ unsigned g_h1[(size_t)NN*256*32];
__device__ unsigned g_l1[(size_t)NN*256*32];
__device__ unsigned g_h0[(size_t)NN*64*32];
__device__ unsigned g_l0[(size_t)NN*64*32];
__device__ float g_cf[NN*64];
__device__ float g_nA[NN*64];
__device__ float g_nB[NN*64];
__device__ float g_agg[NN*64];
__device__ float g_edge[(size_t)EE*64];

// classic-mma weight fragments: cnn (l*4+p)*2048, w0@40960, msg@41472+, fin@74240+
__device__ __align__(16) uint2 g_wf[87552];

__device__ __forceinline__ unsigned packbf(float lo,float hi){
  unsigned r;asm("cvt.rn.bf16x2.f32 %0,%1,%2;":"=r"(r):"f"(hi),"f"(lo));return r;}
__device__ __forceinline__ float bflo(unsigned p){return __uint_as_float(p<<16);}
__device__ __forceinline__ float bfhi(unsigned p){return __uint_as_float(p&0xFFFF0000u);}
__device__ __forceinline__ void mmabf(float* c,unsigned a0,unsigned a1,unsigned a2,unsigned a3,unsigned b0,unsigned b1){
  asm("mma.sync.aligned.m16n8k16.row.col.f32.bf16.bf16.f32 {%0,%1,%2,%3},{%4,%5,%6,%7},{%8,%9},{%0,%1,%2,%3};"
      :"+f"(c[0]),"+f"(c[1]),"+f"(c[2]),"+f"(c[3]):"r"(a0),"r"(a1),"r"(a2),"r"(a3),"r"(b0),"r"(b1));}
__device__ __forceinline__ void cpa16(uint32_t d,const void* s,int sz){
  asm volatile("cp.async.cg.shared.global [%0],[%1],16,%2;"::"r"(d),"l"(s),"r"(sz));}
__device__ __forceinline__ void cpacommit(){asm volatile("cp.async.commit_group;");}
template<int N> __device__ __forceinline__ void cpawait(){asm volatile("cp.async.wait_group %0;"::"n"(N));}

// fp32-A 3-term sweep (conv0 inline, msg, final): split in registers
template<int NT>
__device__ __forceinline__ void mma_sweepN(const float* A,const uint2* Wh,const uint2* Wl,
    int KT,float C[][4],int mrow,int tq,int stride){
  const int lane=threadIdx.x&31;
  for(int kt=0;kt<KT;kt++){
    const float* ap=A+mrow*stride+kt*16+2*tq;
    float2 x0=*(const float2*)ap;
    float2 x1=*(const float2*)(ap+8*stride);
    float2 x2=*(const float2*)(ap+8);
    float2 x3=*(const float2*)(ap+8*stride+8);
    unsigned a0=packbf(x0.x,x0.y),a1=packbf(x1.x,x1.y),a2=packbf(x2.x,x2.y),a3=packbf(x3.x,x3.y);
    unsigned l0=packbf(x0.x-bflo(a0),x0.y-bfhi(a0)),l1=packbf(x1.x-bflo(a1),x1.y-bfhi(a1));
    unsigned l2=packbf(x2.x-bflo(a2),x2.y-bfhi(a2)),l3=packbf(x3.x-bflo(a3),x3.y-bfhi(a3));
    #pragma unroll
    for(int nt=0;nt<NT;nt++){
      int s=(kt*NT+nt)*32+lane;
      uint2 bh=Wh[s],bl=Wl[s];
      mmabf(C[nt],a0,a1,a2,a3,bh.x,bh.y);
      mmabf(C[nt],a0,a1,a2,a3,bl.x,bl.y);
      mmabf(C[nt],l0,l1,l2,l3,bh.x,bh.y);
    }
  }
}

// packed-A 3-term sweep: A pre-split bf16 hi/lo (stride 36 uints), zero conversion
__device__ __forceinline__ void sweep_pk(const unsigned* Ah,const unsigned* Al,
    const uint2* Wh,const uint2* Wl,int KT,float C[][4],int mrow,int tq){
  const int lane=threadIdx.x&31;
  for(int kt=0;kt<KT;kt++){
    int i0=mrow*36+kt*8+tq;
    unsigned a0=Ah[i0],a1=Ah[i0+288],a2=Ah[i0+4],a3=Ah[i0+292];
    unsigned l0=Al[i0],l1=Al[i0+288],l2=Al[i0+4],l3=Al[i0+292];
    #pragma unroll
    for(int nt=0;nt<8;nt++){
      int s=(kt*8+nt)*32+lane;
      uint2 bh=Wh[s],bl=Wl[s];
      mmabf(C[nt],a0,a1,a2,a3,bh.x,bh.y);
      mmabf(C[nt],a0,a1,a2,a3,bl.x,bl.y);
      mmabf(C[nt],l0,l1,l2,l3,bh.x,bh.y);
    }
  }
}

#define PREP_BODY(NSLOT,NT,BASE,GET) \
  for(int s=threadIdx.x;s<(NSLOT);s+=256){ \
    int lane=s&31,wd=s>>5,nt=wd%(NT),kt=wd/(NT); \
    int nn=nt*8+(lane>>2),k0=kt*16+(lane&3)*2; \
    float w00=GET(k0,nn),w01=GET((k0+1),nn),w10=GET((k0+8),nn),w11=GET((k0+9),nn); \
    unsigned h0=packbf(w00,w01),h1=packbf(w10,w11); \
    g_wf[(BASE)+s]=make_uint2(h0,h1); \
    g_wf[(BASE)+(NSLOT)+s]=make_uint2(packbf(w00-bflo(h0),w01-bfhi(h0)),packbf(w10-bflo(h1),w11-bfhi(h1))); \
  }

__global__ void k_prep_cnn(const float* __restrict__ cw){
  int l=blockIdx.x>>2,p=blockIdx.x&3;
  const float* w=cw+l*16384;
  #define G(kk,nn) (w[(nn)*256+(kk)*4+p])
  PREP_BODY(1024,8,(l*4+p)*2048,G)
  #undef G
}
__global__ void k_prep_w0(const float* __restrict__ w0){
  #define G(kk,nn) (((kk)<12)?w0[(nn)*12+(kk)]:0.f)
  PREP_BODY(256,8,40960,G)
  #undef G
}
__global__ void k_prep_msg(const float* __restrict__ w1,const float* __restrict__ w2){
  int l=blockIdx.x>>2,u=blockIdx.x&3;
  const float* wp=(u<3)?(w1+l*12288+u*4096):(w2+l*4096);
  #define G(kk,nn) (wp[(kk)*64+(nn)])
  PREP_BODY(1024,8,41472+(l*4+u)*2048,G)
  #undef G
}
__global__ void k_prep_fin(const float* __restrict__ w1,const float* __restrict__ w2){
  int b=blockIdx.x;
  if(b<2){
    #define G(kk,nn) (w1[((b)*64+(kk))*128+(nn)])
    PREP_BODY(2048,16,74240+b*4096,G)
    #undef G
  } else if(b==2){
    #define G(kk,nn) (((kk)<6)?w1[(128+(kk))*128+(nn)]:0.f)
    PREP_BODY(512,16,82432,G)
    #undef G
  } else {
    #define G(kk,nn) (w2[(kk)*64+(nn)])
    PREP_BODY(2048,8,83456,G)
    #undef G
  }
}

__device__ __forceinline__ void issueWF(uint2* buf,int gbase,int n){
  uint32_t db=(uint32_t)__cvta_generic_to_shared(buf);
  const uint2* src=g_wf+gbase;
  for(int j=threadIdx.x*2;j<n;j+=512) cpa16(db+j*8,src+j,16);
}

// ===== unified CNN layer, packed bf16 activations; L0 fuses conv0 ===========
__global__ void __launch_bounds__(256,2) k_cnn(const float* __restrict__ crop,
    const unsigned* __restrict__ inh,const unsigned* __restrict__ inl,
    unsigned* __restrict__ oh,unsigned* __restrict__ ol,float* __restrict__ outf,
    const float* __restrict__ b0c,const float* __restrict__ b,
    int so_bits,int M,int L0,int outPk,int lidx){
  extern __shared__ float sm[];
  uint2* Wb0=(uint2*)sm;                 // 2048 uint2
  uint2* Wb1=Wb0+2048;                   // 2048
  float* b0s=(float*)(Wb1+2048);         // 64
  float* bs=b0s+64;                      // 64
  unsigned* A0h=(unsigned*)(bs+64);      // 4608
  unsigned* A0l=A0h+4608;                // 4608
  unsigned* A1h=A0l+4608;                // 4608 (L0: cropw+Ap+W0f live here)
  unsigned* A1l=A1h+4608;                // 4608
  float* cropw=(float*)A1h;              // L0: 6144 floats
  float* Ap=cropw+6144;                  // L0: 2560 floats
  uint2* W0f=(uint2*)(Ap+2560);          // L0: 512 uint2
  const int t=threadIdx.x,lane=t&31,wid=t>>5;
  const int Rbase=blockIdx.x*128;
  const int S_out=1<<so_bits,S_in=S_out<<1,so2=so_bits*2;
  const int half=(Rbase>>7)&1;
  const int g=lane>>2,tq=lane&3,mrow=wid*16+g;
  const int wfb=lidx*4;
  if(t<64){bs[t]=b[t];if(L0)b0s[t]=b0c[t];}
  auto issueA=[&](int pp,unsigned* bh,unsigned* bl){
    int ky_=pp>>1,kx_=pp&1;
    uint32_t dbh=(uint32_t)__cvta_generic_to_shared(bh);
    uint32_t dbl=(uint32_t)__cvta_generic_to_shared(bl);
    #pragma unroll
    for(int k_=0;k_<8;k_++){
      int idx=t+k_*256;               // 0..2047
      int pl=idx>>10,id2=idx&1023;
      int row=id2>>3,j=(id2&7)*4;
      int R=Rbase+row;
      const unsigned* sp_=inh; int sz_=0;
      if(R<M){
        int n_=R>>so2,s2=R&(S_out*S_out-1),oy_=s2>>so_bits,ox_=s2&(S_out-1);
        size_t go=((size_t)((n_*S_in+2*oy_+ky_)*S_in)+2*ox_+kx_)*32+j;
        sp_=(pl?inl:inh)+go; sz_=16;
      }
      cpa16((pl?dbl:dbh)+(row*36+j)*4,sp_,sz_);
    }
  };
  // group 0
  if(L0){
    issueWF(W0f,40960,512);
    int n=Rbase>>8;
    uint32_t db=(uint32_t)__cvta_generic_to_shared(cropw);
    for(int i=t*4;i<6144;i+=1024){
      int c=i>>11,r=i&2047,y=r>>6,xx=r&63;
      cpa16(db+i*4,&crop[(((size_t)n*3+c)*64+half*32+y)*64+xx],16);
    }
  } else issueA(0,A0h,A0l);
  issueWF(Wb0,(wfb+0)*2048,2048);
  cpacommit();
  float C[8][4];
  #pragma unroll
  for(int i=0;i<8;i++){C[i][0]=0;C[i][1]=0;C[i][2]=0;C[i][3]=0;}
  for(int p=0;p<4;p++){
    if(p<3){
      if(!L0)issueA(p+1,(p&1)?A0h:A1h,(p&1)?A0l:A1l);
      issueWF((p&1)?Wb0:Wb1,(wfb+p+1)*2048,2048);
      cpacommit();
    }
    if(p<3)cpawait<1>();else cpawait<0>();
    __syncthreads();
    if(L0){
      const int ky=p>>1,kx=p&1;
      for(int i=t;i<2048;i+=256){
        int row=i>>4,col=i&15; float v=0.f;
        if(col<12){
          int sp=(Rbase+row)&255,oy=sp>>4,ox=sp&15;
          int oyl=oy-half*8;
          int c=col>>2,q=col&3;
          v=cropw[c*2048+(4*oyl+2*ky+(q>>1))*64+4*ox+2*kx+(q&1)];
        }
        Ap[row*20+col]=v;
      }
      __syncthreads();
      float C0[8][4];
      #pragma unroll
      for(int i=0;i<8;i++){C0[i][0]=0;C0[i][1]=0;C0[i][2]=0;C0[i][3]=0;}
      mma_sweepN<8>(Ap,W0f,W0f+256,1,C0,mrow,tq,20);
      #pragma unroll
      for(int nt=0;nt<8;nt++){
        int col=nt*8+tq*2,kp=nt*4+tq;
        float v00=fmaxf(C0[nt][0]+b0s[col],0.f),v01=fmaxf(C0[nt][1]+b0s[col+1],0.f);
        float v10=fmaxf(C0[nt][2]+b0s[col],0.f),v11=fmaxf(C0[nt][3]+b0s[col+1],0.f);
        unsigned h0=packbf(v00,v01);
        A0h[mrow*36+kp]=h0; A0l[mrow*36+kp]=packbf(v00-bflo(h0),v01-bfhi(h0));
        unsigned h1=packbf(v10,v11);
        A0h[(mrow+8)*36+kp]=h1; A0l[(mrow+8)*36+kp]=packbf(v10-bflo(h1),v11-bfhi(h1));
      }
      __syncthreads();
    }
    if(L0)sweep_pk(A0h,A0l,(p&1)?Wb1:Wb0,((p&1)?Wb1:Wb0)+1024,4,C,mrow,tq);
    else  sweep_pk((p&1)?A1h:A0h,(p&1)?A1l:A0l,(p&1)?Wb1:Wb0,((p&1)?Wb1:Wb0)+1024,4,C,mrow,tq);
    __syncthreads();
  }
  #pragma unroll
  for(int nt=0;nt<8;nt++){
    int col=nt*8+tq*2,kp=nt*4+tq,r0=Rbase+mrow,r1=r0+8;
    float v00=fmaxf(C[nt][0]+bs[col],0.f),v01=fmaxf(C[nt][1]+bs[col+1],0.f);
    float v10=fmaxf(C[nt][2]+bs[col],0.f),v11=fmaxf(C[nt][3]+bs[col+1],0.f);
    if(outPk){
      if(r0<M){unsigned h=packbf(v00,v01);
        oh[(size_t)r0*32+kp]=h; ol[(size_t)r0*32+kp]=packbf(v00-bflo(h),v01-bfhi(h));}
      if(r1<M){unsigned h=packbf(v10,v11);
        oh[(size_t)r1*32+kp]=h; ol[(size_t)r1*32+kp]=packbf(v10-bflo(h),v11-bfhi(h));}
    } else {
      if(r0<M){float2 v;v.x=v00;v.y=v01;*(float2*)&outf[(size_t)r0*64+col]=v;}
      if(r1<M){float2 v;v.x=v10;v.y=v11;*(float2*)&outf[(size_t)r1*64+col]=v;}
    }
  }
}

// ====== msg MLP (192->64->64) + scatter-add, classic bf16 mma ===============
__global__ void __launch_bounds__(256,2) k_msg(const float* __restrict__ node,
    const float* __restrict__ edge,const int* __restrict__ ei,
    const float* __restrict__ b1,const float* __restrict__ b2,
    int mbase,float* __restrict__ agg){
  extern __shared__ float sm[];
  uint2* Wb0=(uint2*)sm; uint2* Wb1=Wb0+2048;
  float* b1s=(float*)(Wb1+2048); float* b2s=b1s+64;
  float* A0=b2s+64; float* A1=A0+8704;
  int* srcs=(int*)(A1+8704); int* dsts=srcs+128;
  const int t=threadIdx.x,lane=t&31,wid=t>>5;
  const int ebase=blockIdx.x*128;
  if(t<64){b1s[t]=b1[t];b2s[t]=b2[t];}
  if(t<128){srcs[t]=ei[ebase+t];dsts[t]=ei[EE+ebase+t];}
  const int g=lane>>2,tq=lane&3,mrow=wid*16+g;
  __syncthreads();
  auto issueM=[&](int ch,float* buf){
    uint32_t db=(uint32_t)__cvta_generic_to_shared(buf);
    #pragma unroll
    for(int k_=0;k_<8;k_++){
      int idx=t+k_*256,row=idx>>4,c4=(idx&15)*4;
      const float* s_=(ch==0)?&node[(size_t)dsts[row]*64+c4]:(ch==1)?&node[(size_t)srcs[row]*64+c4]
                     :&edge[(size_t)(ebase+row)*64+c4];
      cpa16(db+(row*68+c4)*4,s_,16);
    }
  };
  float C1[8][4];
  #pragma unroll
  for(int i=0;i<8;i++){C1[i][0]=0;C1[i][1]=0;C1[i][2]=0;C1[i][3]=0;}
  issueM(0,A0);issueWF(Wb0,mbase,2048);cpacommit();
  for(int ch=0;ch<3;ch++){
    if(ch<2){
      issueM(ch+1,(ch&1)?A0:A1);
      issueWF((ch&1)?Wb0:Wb1,mbase+(ch+1)*2048,2048);
      cpacommit();
    } else {
      issueWF(Wb1,mbase+3*2048,2048);
      cpacommit();
    }
    cpawait<1>();
    __syncthreads();
    mma_sweepN<8>((ch&1)?A1:A0,(ch&1)?Wb1:Wb0,((ch&1)?Wb1:Wb0)+1024,4,C1,mrow,tq,68);
    __syncthreads();
  }
  #pragma unroll
  for(int nt=0;nt<8;nt++){
    int col=nt*8+tq*2;
    A0[mrow*68+col]=fmaxf(C1[nt][0]+b1s[col],0.f);
    A0[mrow*68+col+1]=fmaxf(C1[nt][1]+b1s[col+1],0.f);
    A0[(mrow+8)*68+col]=fmaxf(C1[nt][2]+b1s[col],0.f);
    A0[(mrow+8)*68+col+1]=fmaxf(C1[nt][3]+b1s[col+1],0.f);
  }
  cpawait<0>();
  __syncthreads();
  float C2[8][4];
  #pragma unroll
  for(int i=0;i<8;i++){C2[i][0]=0;C2[i][1]=0;C2[i][2]=0;C2[i][3]=0;}
  mma_sweepN<8>(A0,Wb1,Wb1+1024,4,C2,mrow,tq,68);
  const int d0=dsts[mrow],d1=dsts[mrow+8];
  #pragma unroll
  for(int nt=0;nt<8;nt++){
    int col=nt*8+tq*2;
    atomicAdd(&agg[(size_t)d0*64+col],C2[nt][0]+b2s[col]);
    atomicAdd(&agg[(size_t)d0*64+col+1],C2[nt][1]+b2s[col+1]);
    atomicAdd(&agg[(size_t)d1*64+col],C2[nt][2]+b2s[col]);
    atomicAdd(&agg[(size_t)d1*64+col+1],C2[nt][3]+b2s[col+1]);
  }
}

// --------------------------------------------- node_update: [x|cf]@W + LN
__global__ void __launch_bounds__(256) k_nodeup(const float* __restrict__ x,
    const float* __restrict__ cf, const float* __restrict__ w, const float* __restrict__ b,
    const float* __restrict__ g, const float* __restrict__ be, float* __restrict__ out) {
    extern __shared__ float sm[];
    float* Ws = sm;
    float* Bs = Ws + 6144; float* Gs = Bs + 64; float* BEs = Gs + 64;
    float* mu = BEs + 64; float* rs = mu + 64;
    float* As = rs + 64; float* Hs = As + 6400;
    int t = threadIdx.x;
    int Rbase = blockIdx.x * 64;
    for (int i = t; i < 6144; i += 256) Ws[i] = w[i];
    if (t < 64) { Bs[t]=b[t]; Gs[t]=g[t]; BEs[t]=be[t]; }
    for (int e = t; e < 2048; e += 256) {
        int row = e >> 5, c = e & 31, nd = Rbase + row;
        As[row * 100 + c] = (nd < NN) ? x[nd * 32 + c] : 0.f;
    }
    for (int e = t; e < 4096; e += 256) {
        int row = e >> 6, c = e & 63, nd = Rbase + row;
        As[row * 100 + 32 + c] = (nd < NN) ? cf[nd * 64 + c] : 0.f;
    }
    __syncthreads();
    int tr = t >> 4, tc = t & 15;
    float acc[4][4];
    float4 b4 = *(const float4*)&Bs[tc * 4];
    #pragma unroll
    for (int i = 0; i < 4; i++) { acc[i][0]=b4.x; acc[i][1]=b4.y; acc[i][2]=b4.z; acc[i][3]=b4.w; }
    for (int k = 0; k < 96; k++) {
        float4 w4 = *(const float4*)&Ws[k * 64 + tc * 4];
        #pragma unroll
        for (int i = 0; i < 4; i++) {
            float a = As[(tr * 4 + i) * 100 + k];
            acc[i][0] += a*w4.x; acc[i][1] += a*w4.y; acc[i][2] += a*w4.z; acc[i][3] += a*w4.w;
        }
    }
    #pragma unroll
    for (int i = 0; i < 4; i++) {
        float4 r; r.x=fmaxf(acc[i][0],0.f); r.y=fmaxf(acc[i][1],0.f);
        r.z=fmaxf(acc[i][2],0.f); r.w=fmaxf(acc[i][3],0.f);
        *(float4*)&Hs[(tr * 4 + i) * 68 + tc * 4] = r;
    }
    __syncthreads();
    if (t < 64) {
        float s = 0.f, sq = 0.f;
        for (int c = 0; c < 64; c++) { float v = Hs[t * 68 + c]; s += v; sq += v * v; }
        float m = s * (1.f / 64.f);
        mu[t] = m; rs[t] = rsqrtf(sq * (1.f / 64.f) - m * m + 1e-5f);
    }
    __syncthreads();
    for (int i = t; i < 4096; i += 256) {
        int r = i >> 6, c = i & 63, nd = Rbase + r;
        if (nd < NN) out[nd * 64 + c] = (Hs[r * 68 + c] - mu[r]) * rs[r] * Gs[c] + BEs[c];
    }
}

// --------------------------------------------- edge_update: ea@W + LN
__global__ void __launch_bounds__(256) k_edgeup(const float* __restrict__ ea,
    const float* __restrict__ w, const float* __restrict__ b,
    const float* __restrict__ g, const float* __restrict__ be, float* __restrict__ out) {
    __shared__ float Ws[384], Bs[64], Gs[64], BEs[64], Aa[64][8], Hs[64][68], mu[64], rs[64];
    int t = threadIdx.x;
    int ebase = blockIdx.x * 64;
    for (int i = t; i < 384; i += 256) Ws[i] = w[i];
    if (t < 64) { Bs[t]=b[t]; Gs[t]=g[t]; BEs[t]=be[t]; }
    for (int e = t; e < 384; e += 256) {
        int row = e / 6, k = e - row * 6;
        Aa[row][k] = ea[(size_t)(ebase + row) * 6 + k];
    }
    __syncthreads();
    int r = t >> 2, cg = (t & 3) * 16;
    float a0=Aa[r][0],a1=Aa[r][1],a2=Aa[r][2],a3=Aa[r][3],a4=Aa[r][4],a5=Aa[r][5];
    #pragma unroll
    for (int j = 0; j < 16; j++) {
        int c = cg + j;
        float h = Bs[c] + a0*Ws[c] + a1*Ws[64+c] + a2*Ws[128+c] + a3*Ws[192+c] + a4*Ws[256+c] + a5*Ws[320+c];
        Hs[r][c] = fmaxf(h, 0.f);
    }
    __syncthreads();
    if (t < 64) {
        float s = 0.f, sq = 0.f;
        for (int c = 0; c < 64; c++) { float v = Hs[t][c]; s += v; sq += v * v; }
        float m = s * (1.f / 64.f);
        mu[t] = m; rs[t] = rsqrtf(sq * (1.f / 64.f) - m * m + 1e-5f);
    }
    __syncthreads();
    for (int i = t; i < 4096; i += 256) {
        int rr = i >> 6, c = i & 63;
        out[(size_t)ebase * 64 + i] = (Hs[rr][c] - mu[rr]) * rs[rr] * Gs[c] + BEs[c];
    }
}

// ========= node MLP: [node|agg] 2-layer, 128 nodes/block =====================
__global__ void __launch_bounds__(256, 2) k_nodemlp(const float* __restrict__ node,
    const float* __restrict__ agg, const float* __restrict__ w1, const float* __restrict__ b1,
    const float* __restrict__ w2, const float* __restrict__ b2, float* __restrict__ out) {
    extern __shared__ float sm[];
    float* W1s = sm;
    float* W2s = W1s + 8192;
    float* B1s = W2s + 4096; float* B2s = B1s + 64;
    float* As = B2s + 64;
    const int t = threadIdx.x;
    const int Rbase = blockIdx.x * 128;
    for (int i = t; i < 8192; i += 256) W1s[i] = w1[i];
    for (int i = t; i < 4096; i += 256) W2s[i] = w2[i];
    if (t < 64) { B1s[t]=b1[t]; B2s[t]=b2[t]; }
    const int tr = t >> 3, tc = t & 7;
    const float* ar[4];
    #pragma unroll
    for (int i = 0; i < 4; i++) ar[i] = &As[(tr * 4 + i) * 65];
    float acc[4][8];
    for (int ch = 0; ch < 2; ch++) {
        __syncthreads();
        for (int e = t * 4; e < 8192; e += 1024) {
            int row = e >> 6, c4 = e & 63, nd = Rbase + row;
            float4 vv = make_float4(0.f,0.f,0.f,0.f);
            if (nd < NN) {
                const float* base = (ch == 0) ? &node[(size_t)nd * 64] : &agg[(size_t)nd * 64];
                vv = *(const float4*)&base[c4];
            }
            float* d = &As[row * 65 + c4];
            d[0]=vv.x; d[1]=vv.y; d[2]=vv.z; d[3]=vv.w;
        }
        __syncthreads();
        if (ch == 0) {
            float4 ba = *(const float4*)&B1s[tc * 8];
            float4 bb = *(const float4*)&B1s[tc * 8 + 4];
            #pragma unroll
            for (int i = 0; i < 4; i++) {
                acc[i][0]=ba.x;acc[i][1]=ba.y;acc[i][2]=ba.z;acc[i][3]=ba.w;
                acc[i][4]=bb.x;acc[i][5]=bb.y;acc[i][6]=bb.z;acc[i][7]=bb.w;
            }
        }
        const float* wp = &W1s[ch * 4096 + tc * 8];
        #pragma unroll 8
        for (int k = 0; k < 64; k++) {
            float4 wa = *(const float4*)&wp[k * 64];
            float4 wb = *(const float4*)&wp[k * 64 + 4];
            #pragma unroll
            for (int i = 0; i < 4; i++) {
                float a = ar[i][k];
                acc[i][0]+=a*wa.x; acc[i][1]+=a*wa.y; acc[i][2]+=a*wa.z; acc[i][3]+=a*wa.w;
                acc[i][4]+=a*wb.x; acc[i][5]+=a*wb.y; acc[i][6]+=a*wb.z; acc[i][7]+=a*wb.w;
            }
        }
    }
    __syncthreads();
    #pragma unroll
    for (int i = 0; i < 4; i++)
        #pragma unroll
        for (int j = 0; j < 8; j++)
            As[(tr * 4 + i) * 65 + tc * 8 + j] = fmaxf(acc[i][j], 0.f);
    __syncthreads();
    float a2[4][8];
    {
        float4 ba = *(const float4*)&B2s[tc * 8];
        float4 bb = *(const float4*)&B2s[tc * 8 + 4];
        #pragma unroll
        for (int i = 0; i < 4; i++) {
            a2[i][0]=ba.x;a2[i][1]=ba.y;a2[i][2]=ba.z;a2[i][3]=ba.w;
            a2[i][4]=bb.x;a2[i][5]=bb.y;a2[i][6]=bb.z;a2[i][7]=bb.w;
        }
    }
    const float* wp2 = &W2s[tc * 8];
    #pragma unroll 8
    for (int k = 0; k < 64; k++) {
        float4 wa = *(const float4*)&wp2[k * 64];
        float4 wb = *(const float4*)&wp2[k * 64 + 4];
        #pragma unroll
        for (int i = 0; i < 4; i++) {
            float a = ar[i][k];
            a2[i][0]+=a*wa.x; a2[i][1]+=a*wa.y; a2[i][2]+=a*wa.z; a2[i][3]+=a*wa.w;
            a2[i][4]+=a*wb.x; a2[i][5]+=a*wb.y; a2[i][6]+=a*wb.z; a2[i][7]+=a*wb.w;
        }
    }
    #pragma unroll
    for (int i = 0; i < 4; i++) {
        int nd = Rbase + tr * 4 + i;
        if (nd < NN) {
            float4 v;
            v.x=a2[i][0]; v.y=a2[i][1]; v.z=a2[i][2]; v.w=a2[i][3];
            *(float4*)&out[(size_t)nd * 64 + tc * 8] = v;
            v.x=a2[i][4]; v.y=a2[i][5]; v.z=a2[i][6]; v.w=a2[i][7];
            *(float4*)&out[(size_t)nd * 64 + tc * 8 + 4] = v;
        }
    }
}

// ===== final edge MLP (classic bf16 mma): 134->128->64->1 ===================
__global__ void __launch_bounds__(256,2) k_final(const float* __restrict__ node,
    const float* __restrict__ ea,const int* __restrict__ ei,
    const float* __restrict__ b1,const float* __restrict__ b2,
    const float* __restrict__ w3,const float* __restrict__ b3,float* __restrict__ out){
  extern __shared__ float sm[];
  uint2* Wb=(uint2*)sm;
  float* B1s=(float*)(Wb+4096);
  float* B2s=B1s+128; float* w3s=B2s+64; float* b3s=w3s+64;
  float* HA=b3s+4;
  int* srcs=(int*)(HA+16896); int* dsts=srcs+128;
  const int t=threadIdx.x,lane=t&31,wid=t>>5;
  const int ebase=blockIdx.x*128;
  if(t<128){B1s[t]=b1[t];srcs[t]=ei[ebase+t];dsts[t]=ei[EE+ebase+t];}
  if(t<64){B2s[t]=b2[t];w3s[t]=w3[t];}
  if(t==0)b3s[0]=b3[0];
  const int g=lane>>2,tq=lane&3,mrow=wid*16+g;
  __syncthreads();
  float C1[16][4];
  #pragma unroll
  for(int i=0;i<16;i++){C1[i][0]=0;C1[i][1]=0;C1[i][2]=0;C1[i][3]=0;}
  for(int ch=0;ch<2;ch++){
    uint32_t db=(uint32_t)__cvta_generic_to_shared(HA);
    #pragma unroll
    for(int k_=0;k_<8;k_++){
      int idx=t+k_*256,row=idx>>4,c4=(idx&15)*4;
      const int nd=(ch==0)?srcs[row]:dsts[row];
      cpa16(db+(row*68+c4)*4,&node[(size_t)nd*64+c4],16);
    }
    issueWF(Wb,74240+ch*4096,4096);
    cpacommit();
    cpawait<0>();
    __syncthreads();
    mma_sweepN<16>(HA,Wb,Wb+2048,4,C1,mrow,tq,68);
    __syncthreads();
  }
  for(int i=t;i<2560;i+=256)HA[i]=0.f;
  issueWF(Wb,82432,1024);
  cpacommit();
  __syncthreads();
  for(int i=t;i<768;i+=256){int row=i/6,k=i-row*6;HA[row*20+k]=ea[(size_t)(ebase+row)*6+k];}
  cpawait<0>();
  __syncthreads();
  mma_sweepN<16>(HA,Wb,Wb+512,1,C1,mrow,tq,20);
  __syncthreads();
  issueWF(Wb,83456,4096);
  cpacommit();
  #pragma unroll
  for(int nt=0;nt<16;nt++){
    int col=nt*8+tq*2;
    HA[mrow*132+col]      =fmaxf(C1[nt][0]+B1s[col],0.f);
    HA[mrow*132+col+1]    =fmaxf(C1[nt][1]+B1s[col+1],0.f);
    HA[(mrow+8)*132+col]  =fmaxf(C1[nt][2]+B1s[col],0.f);
    HA[(mrow+8)*132+col+1]=fmaxf(C1[nt][3]+B1s[col+1],0.f);
  }
  cpawait<0>();
  __syncthreads();
  float C2[8][4];
  #pragma unroll
  for(int i=0;i<8;i++){C2[i][0]=0;C2[i][1]=0;C2[i][2]=0;C2[i][3]=0;}
  mma_sweepN<8>(HA,Wb,Wb+2048,8,C2,mrow,tq,132);
  __syncthreads();
  #pragma unroll
  for(int nt=0;nt<8;nt++){
    int col=nt*8+tq*2;
    HA[mrow*68+col]      =fmaxf(C2[nt][0]+B2s[col],0.f);
    HA[mrow*68+col+1]    =fmaxf(C2[nt][1]+B2s[col+1],0.f);
    HA[(mrow+8)*68+col]  =fmaxf(C2[nt][2]+B2s[col],0.f);
    HA[(mrow+8)*68+col+1]=fmaxf(C2[nt][3]+B2s[col+1],0.f);
  }
  __syncthreads();
  if(t<128){
    float s=b3s[0];
    #pragma unroll 8
    for(int c=0;c<64;c++)s+=HA[t*68+c]*w3s[c];
    out[ebase+t]=s;
  }
}

// ============================================================================
extern "C" void kernel_launch(void* const* d_in, const int* in_sizes, int n_in,
                              void* d_out, int out_size) {
    const float *x=0,*ea=0,*crop=0,*cw0=0,*cb0=0,*cw=0,*cb=0,*nu_w=0,*nu_b=0,*nu_g=0,*nu_be=0,
        *eu_w=0,*eu_b=0,*eu_g=0,*eu_be=0,*ie_w1=0,*ie_b1=0,*ie_w2=0,*ie_b2=0,
        *in_w1=0,*in_b1=0,*in_w2=0,*in_b2=0,*em_w1=0,*em_b1=0,*em_w2=0,*em_b2=0,*em_w3=0,*em_b3=0;
    const int* ei = 0;
    int c64 = 0, c256 = 0, c16k = 0;
    for (int i = 0; i < n_in; i++) {
        const float* p = (const float*)d_in[i];
        switch (in_sizes[i]) {
            case 320000: x = p; break;
            case 640000: ei = (const int*)p; break;
            case 1920000: ea = p; break;
            case 122880000: crop = p; break;
            case 768: cw0 = p; break;
            case 81920: cw = p; break;
            case 320: cb = p; break;
            case 6144: nu_w = p; break;
            case 384: eu_w = p; break;
            case 49152: ie_w1 = p; break;
            case 32768: in_w1 = p; break;
            case 17152: em_w1 = p; break;
            case 128: em_b1 = p; break;
            case 8192: em_w2 = p; break;
            case 1: em_b3 = p; break;
            case 16384: if (c16k++ == 0) ie_w2 = p; else in_w2 = p; break;
            case 256:
                if (c256 == 0) ie_b1 = p; else if (c256 == 1) ie_b2 = p;
                else if (c256 == 2) in_b1 = p; else in_b2 = p;
                c256++; break;
            case 64: {
                const float** slots[9] = {&cb0,&nu_b,&nu_g,&nu_be,&eu_b,&eu_g,&eu_be,&em_b2,&em_w3};
                if (c64 < 9) *slots[c64] = p;
                c64++; break;
            }
            default: break;
        }
    }
    unsigned *h1,*l1,*h0,*l0;
    float *cf,*nA,*nB,*agg,*edg;
    cudaGetSymbolAddress((void**)&h1, g_h1);
    cudaGetSymbolAddress((void**)&l1, g_l1);
    cudaGetSymbolAddress((void**)&h0, g_h0);
    cudaGetSymbolAddress((void**)&l0, g_l0);
    cudaGetSymbolAddress((void**)&cf, g_cf);
    cudaGetSymbolAddress((void**)&nA, g_nA);
    cudaGetSymbolAddress((void**)&nB, g_nB);
    cudaGetSymbolAddress((void**)&agg, g_agg);
    cudaGetSymbolAddress((void**)&edg, g_edge);

    const int SM_CNN = 27264 * 4;
    const int SM_MSG = (4096 * 2 + 64 + 64 + 8704 + 8704 + 256) * 4;
    const int SM_NU  = (6144 + 64 * 5 + 6400 + 4352 + 64) * 4;
    const int SM_NM  = (8192 + 4096 + 128 + 8320) * 4;
    const int SM_FIN = (4096 * 2 + 128 + 64 + 64 + 4 + 16896 + 256) * 4;
    cudaFuncSetAttribute(k_cnn,     cudaFuncAttributeMaxDynamicSharedMemorySize, SM_CNN);
    cudaFuncSetAttribute(k_msg,     cudaFuncAttributeMaxDynamicSharedMemorySize, SM_MSG);
    cudaFuncSetAttribute(k_nodeup,  cudaFuncAttributeMaxDynamicSharedMemorySize, SM_NU);
    cudaFuncSetAttribute(k_nodemlp, cudaFuncAttributeMaxDynamicSharedMemorySize, SM_NM);
    cudaFuncSetAttribute(k_final,   cudaFuncAttributeMaxDynamicSharedMemorySize, SM_FIN);

    // weight fragment prep
    k_prep_cnn<<<20, 256>>>(cw);
    k_prep_w0<<<1, 256>>>(cw0);
    k_prep_msg<<<16, 256>>>(ie_w1, ie_w2);
    k_prep_fin<<<4, 256>>>(em_w1, em_w2);

    // CNN stack (packed bf16 activations between layers)
    k_cnn<<<20000, 256, SM_CNN>>>(crop, 0, 0,  h1, l1, 0,  cb0, cb,       4, NN*256, 1, 1, 0);
    k_cnn<<<5000,  256, SM_CNN>>>(crop, h1, l1, h0, l0, 0, cb0, cb + 64,  3, NN*64,  0, 1, 1);
    k_cnn<<<1250,  256, SM_CNN>>>(crop, h0, l0, h1, l1, 0, cb0, cb + 128, 2, NN*16,  0, 1, 2);
    k_cnn<<<313,   256, SM_CNN>>>(crop, h1, l1, h0, l0, 0, cb0, cb + 192, 1, NN*4,   0, 1, 3);
    k_cnn<<<79,    256, SM_CNN>>>(crop, h0, l0, 0, 0,  cf, cb0, cb + 256, 0, NN,     0, 0, 4);
    // encoders
    k_nodeup<<<157, 256, SM_NU>>>(x, cf, nu_w, nu_b, nu_g, nu_be, nA);
    k_edgeup<<<5000, 256>>>(ea, eu_w, eu_b, eu_g, eu_be, edg);
    // 4 interaction layers
    float* cur = nA; float* nxt = nB;
    for (int l = 0; l < 4; l++) {
        cudaMemsetAsync(agg, 0, (size_t)NN * 64 * sizeof(float), 0);
        k_msg<<<2500, 256, SM_MSG>>>(cur, edg, ei, ie_b1 + l * 64, ie_b2 + l * 64,
                                     41472 + l * 8192, agg);
        k_nodemlp<<<79, 256, SM_NM>>>(cur, agg, in_w1 + l * 8192, in_b1 + l * 64,
                                      in_w2 + l * 4096, in_b2 + l * 64, nxt);
        float* tmp = cur; cur = nxt; nxt = tmp;
    }
    // final edge MLP
    k_final<<<2500, 256, SM_FIN>>>(cur, ea, ei, em_b1, em_b2, em_w3, em_b3, (float*)d_out);
}